// round 8
// baseline (speedup 1.0000x reference)
#include <cuda_runtime.h>
#include <cuda_fp16.h>
#include <cstdint>

#define DI __device__ __forceinline__

// ------------------------- problem sizes -------------------------
#define N_NODES_C 16384
#define N_EDGES_C 131072
#define N_GRAPHS_C 16
#define U_SZ_C 4096
#define U_RED_C 256
#define EDGE_H_C 1024
#define EDGE_OUT_C 512
#define NODE_H_C 512

// padded concat widths (multiples of 32 for BK=32)
// e_in : [u_r 0-255][x_row 256-264][x_col 265-273][ea 274][pad->287]
// n_in : [e 0-511][x_col 512-520][pad->543]
// o_in : [agg 0-511][u_r 512-767][x 768-776][pad->799]
#define K_EIN 288
#define K_NIN 544
#define K_OIN 800

// ------------------------- device scratch -------------------------
__device__ __half g_ein [(size_t)N_EDGES_C * K_EIN];
__device__ __half g_bufA[(size_t)N_EDGES_C * EDGE_H_C];
__device__ __half g_bufB[(size_t)N_EDGES_C * EDGE_H_C];
__device__ __half g_nin [(size_t)N_EDGES_C * K_NIN];
__device__ __half g_oin [(size_t)N_NODES_C * K_OIN];
__device__ __half g_h2  [(size_t)N_NODES_C * NODE_H_C];
__device__ float  g_ur  [N_GRAPHS_C * U_RED_C];

// weights packed [Kp, N] row-major fp16 (with concat-permuted K rows)
__device__ __half g_w0h  [K_EIN    * EDGE_H_C];
__device__ __half g_w1h  [EDGE_H_C * EDGE_H_C];
__device__ __half g_w2h  [EDGE_H_C * EDGE_H_C];
__device__ __half g_w3h  [EDGE_H_C * EDGE_H_C];
__device__ __half g_wfh  [EDGE_H_C * EDGE_OUT_C];
__device__ __half g_n1w0h[K_NIN    * NODE_H_C];
__device__ __half g_n1w1h[NODE_H_C * NODE_H_C];
__device__ __half g_n2w0h[K_OIN    * NODE_H_C];

__device__ int g_cnt[N_NODES_C];
__device__ int g_off[N_NODES_C + 1];
__device__ int g_cur[N_NODES_C];
__device__ int g_elist[N_EDGES_C];

// ------------------------- small helpers -------------------------
DI uint32_t smem_u32(const void* p) {
    return (uint32_t)__cvta_generic_to_shared(p);
}
DI void cp16(uint32_t dst, const void* src) {
    asm volatile("cp.async.cg.shared.global [%0], [%1], 16;\n" :: "r"(dst), "l"(src));
}
DI void cp_commit() { asm volatile("cp.async.commit_group;\n"); }
DI void cp_wait1()  { asm volatile("cp.async.wait_group 1;\n"); }

DI void ldm_x4(uint32_t addr, uint32_t& r0, uint32_t& r1, uint32_t& r2, uint32_t& r3) {
    asm volatile("ldmatrix.sync.aligned.m8n8.x4.shared.b16 {%0,%1,%2,%3}, [%4];\n"
                 : "=r"(r0), "=r"(r1), "=r"(r2), "=r"(r3) : "r"(addr));
}
DI void ldm_x4t(uint32_t addr, uint32_t& r0, uint32_t& r1, uint32_t& r2, uint32_t& r3) {
    asm volatile("ldmatrix.sync.aligned.m8n8.x4.trans.shared.b16 {%0,%1,%2,%3}, [%4];\n"
                 : "=r"(r0), "=r"(r1), "=r"(r2), "=r"(r3) : "r"(addr));
}
// fp16-accumulate MMA: D(f16x2 x2) = A*B + D  — 2x issue rate vs f32 acc
DI void mma16816_h(uint32_t* c, const uint32_t* a, const uint32_t* b) {
    asm volatile("mma.sync.aligned.m16n8k16.row.col.f16.f16.f16.f16 "
                 "{%0,%1}, {%2,%3,%4,%5}, {%6,%7}, {%0,%1};\n"
                 : "+r"(c[0]), "+r"(c[1])
                 : "r"(a[0]), "r"(a[1]), "r"(a[2]), "r"(a[3]),
                   "r"(b[0]), "r"(b[1]));
}

// --------------- weight pack: fp32 -> fp16, row permute + zero pad ---------------
struct Seg { int src0, dst0, n; };

__global__ void pack_weight(const float* __restrict__ src, __half* __restrict__ dst,
                            int N, int Kp, Seg a, Seg b, Seg c, Seg d) {
    int idx = blockIdx.x * blockDim.x + threadIdx.x;
    if (idx >= Kp * N) return;
    int r = idx / N, col = idx - r * N;
    float v = 0.f;
    if      (r >= a.dst0 && r < a.dst0 + a.n) v = src[(size_t)(a.src0 + r - a.dst0) * N + col];
    else if (r >= b.dst0 && r < b.dst0 + b.n) v = src[(size_t)(b.src0 + r - b.dst0) * N + col];
    else if (r >= c.dst0 && r < c.dst0 + c.n) v = src[(size_t)(c.src0 + r - c.dst0) * N + col];
    else if (r >= d.dst0 && r < d.dst0 + d.n) v = src[(size_t)(d.src0 + r - d.dst0) * N + col];
    dst[idx] = __float2half(v);
}

// --------------- dim reduction: u_r = u @ w_dr + b_dr (fp32, tiny) ---------------
__global__ void dimred_kernel(const float* __restrict__ u, const float* __restrict__ w,
                              const float* __restrict__ b) {
    __shared__ float red[8][32];
    int g = blockIdx.x, ct = blockIdx.y;
    int kg = threadIdx.x >> 5, cl = threadIdx.x & 31;
    int c = ct * 32 + cl;
    const float* up = u + (size_t)g * U_SZ_C + kg * 512;
    const float* wp = w + (size_t)(kg * 512) * U_RED_C + c;
    float s = 0.f;
    #pragma unroll 8
    for (int k = 0; k < 512; k++) s += up[k] * wp[(size_t)k * U_RED_C];
    red[kg][cl] = s;
    __syncthreads();
    if (kg == 0) {
        float t = b[c];
        #pragma unroll
        for (int i = 0; i < 8; i++) t += red[i][cl];
        g_ur[g * U_RED_C + c] = t;
    }
}

// --------------- build e_in (permuted layout), one warp per edge -----------------
__global__ void build_ein_kernel(const float* __restrict__ x, const float* __restrict__ ea,
                                 const int* __restrict__ ei, const int* __restrict__ batch) {
    int e = blockIdx.x * 8 + (threadIdx.x >> 5);
    int lane = threadIdx.x & 31;
    int r = ei[e], c = ei[N_EDGES_C + e];
    int g = batch[r];
    __half* dst = g_ein + (size_t)e * K_EIN;
    const float* ur = g_ur + g * U_RED_C;
    #pragma unroll
    for (int j = 0; j < 8; j++)
        dst[j * 32 + lane] = __float2half(ur[j * 32 + lane]);
    float v = 0.f;
    if (lane < 9)        v = x[(size_t)r * 9 + lane];
    else if (lane < 18)  v = x[(size_t)c * 9 + (lane - 9)];
    else if (lane == 18) v = ea[e];
    dst[256 + lane] = __float2half(v);   // covers cols 256..287 incl. zero pad
}

// x[col] into n_in cols 512..520, zeros to 543
__global__ void add_x_nin_kernel(const float* __restrict__ x, const int* __restrict__ ei) {
    int e = blockIdx.x * 8 + (threadIdx.x >> 5);
    int lane = threadIdx.x & 31;
    int c = ei[N_EDGES_C + e];
    float v = (lane < 9) ? x[(size_t)c * 9 + lane] : 0.f;
    g_nin[(size_t)e * K_NIN + 512 + lane] = __float2half(v);
}

// ------------------------- fp16 tensor-core GEMM ---------------------------------
// C[M,N](fp16) = act(A[M,K](fp16,row) @ B[K,N](fp16,row) + bias)
// BM=128, BN=256, BK=32, 8 warps (2M x 4N), warp tile 64x64, 3-stage cp.async.
// fp16 accumulate with promotion to fp32 every 2 k-tiles (K-chunk 64).
#define BM 128
#define BN 256
#define BKK 32
#define GT 256
#define STG 3
#define A_ST (BM * 40)     // halves per A stage (pad 32->40)
#define B_ST (BKK * 264)   // halves per B stage (pad 256->264)
#define GEMM_SMEM (STG * (A_ST + B_ST) * 2)

template<bool RELU>
__global__ __launch_bounds__(GT, 1)
void gemm_kernel(const __half* __restrict__ A, int lda,
                 const __half* __restrict__ B, int ldb,
                 const float* __restrict__ bias,
                 __half* __restrict__ C, int ldc, int K) {
    extern __shared__ __half sm[];
    __half* Asm = sm;                    // [STG][128][40]
    __half* Bsm = sm + STG * A_ST;       // [STG][32][264]

    const int tid  = threadIdx.x;
    const int lane = tid & 31, warp = tid >> 5;
    const int wm = warp & 1;    // 2 warps along M -> 64 rows each
    const int wn = warp >> 1;   // 4 warps along N -> 64 cols each
    const int bm = blockIdx.y, bn = blockIdx.x;

    const __half* Ag = A + (size_t)bm * BM * lda;
    const __half* Bg = B + (size_t)bn * BN;

    float acc[4][8][4];          // persistent fp32 accumulators
    uint32_t hacc[4][8][2];      // fp16x2 chunk accumulators
    #pragma unroll
    for (int i = 0; i < 4; i++)
        #pragma unroll
        for (int j = 0; j < 8; j++) {
            #pragma unroll
            for (int k = 0; k < 4; k++) acc[i][j][k] = 0.f;
            hacc[i][j][0] = 0u; hacc[i][j][1] = 0u;
        }

    const int KT = K / BKK;

    auto load = [&](int kt, int st) {
        __half* as = Asm + st * A_ST;
        __half* bs = Bsm + st * B_ST;
        #pragma unroll
        for (int i = 0; i < 2; i++) {
            int ch = tid + i * GT;               // 512 x 16B chunks for A
            int r = ch >> 2, cc = (ch & 3) << 3;
            cp16(smem_u32(as + r * 40 + cc), Ag + (size_t)r * lda + kt * BKK + cc);
        }
        #pragma unroll
        for (int i = 0; i < 4; i++) {
            int ch = tid + i * GT;               // 1024 x 16B chunks for B
            int r = ch >> 5, cc = (ch & 31) << 3;
            cp16(smem_u32(bs + r * 264 + cc), Bg + (size_t)(kt * BKK + r) * ldb + cc);
        }
        cp_commit();
    };

    load(0, 0);
    load(1, 1);

    for (int kt = 0; kt < KT; kt++) {
        cp_wait1();              // stage for kt complete (2 groups max in flight)
        __syncthreads();
        const int st = kt % 3;
        if (kt + 2 < KT) load(kt + 2, (kt + 2) % 3);
        else             cp_commit();   // keep group accounting aligned

        #pragma unroll
        for (int ks = 0; ks < 2; ks++) {
            uint32_t afr[4][4];
            {
                const __half* as = Asm + st * A_ST;
                int row = wm * 64 + (lane & 15);
                int col = ks * 16 + (lane >> 4) * 8;
                #pragma unroll
                for (int mi = 0; mi < 4; mi++)
                    ldm_x4(smem_u32(as + (row + mi * 16) * 40 + col),
                           afr[mi][0], afr[mi][1], afr[mi][2], afr[mi][3]);
            }
            uint32_t bfr[8][2];
            {
                const __half* bs = Bsm + st * B_ST;
                int row = ks * 16 + ((lane >> 3) & 1) * 8 + (lane & 7);
                #pragma unroll
                for (int p = 0; p < 4; p++) {
                    int col = wn * 64 + p * 16 + (lane >> 4) * 8;
                    uint32_t r0, r1, r2, r3;
                    ldm_x4t(smem_u32(bs + row * 264 + col), r0, r1, r2, r3);
                    bfr[2 * p][0] = r0;     bfr[2 * p][1] = r1;
                    bfr[2 * p + 1][0] = r2; bfr[2 * p + 1][1] = r3;
                }
            }
            #pragma unroll
            for (int mi = 0; mi < 4; mi++)
                #pragma unroll
                for (int nj = 0; nj < 8; nj++)
                    mma16816_h(hacc[mi][nj], afr[mi], bfr[nj]);
        }

        // promote fp16 chunk accumulators to fp32 every 2 k-tiles (and at the end)
        if ((kt & 1) == 1 || kt == KT - 1) {
            #pragma unroll
            for (int mi = 0; mi < 4; mi++)
                #pragma unroll
                for (int nj = 0; nj < 8; nj++) {
                    __half2 h0 = *reinterpret_cast<__half2*>(&hacc[mi][nj][0]);
                    __half2 h1 = *reinterpret_cast<__half2*>(&hacc[mi][nj][1]);
                    float2 f0 = __half22float2(h0);
                    float2 f1 = __half22float2(h1);
                    acc[mi][nj][0] += f0.x;
                    acc[mi][nj][1] += f0.y;
                    acc[mi][nj][2] += f1.x;
                    acc[mi][nj][3] += f1.y;
                    hacc[mi][nj][0] = 0u;
                    hacc[mi][nj][1] = 0u;
                }
        }
    }

    // epilogue: bias + (relu) + fp16 store
    int row0 = bm * BM + wm * 64;
    int col0 = bn * BN + wn * 64;
    #pragma unroll
    for (int mi = 0; mi < 4; mi++) {
        #pragma unroll
        for (int nj = 0; nj < 8; nj++) {
            int c = col0 + nj * 8 + (lane & 3) * 2;
            float b0 = bias[c], b1 = bias[c + 1];
            #pragma unroll
            for (int h = 0; h < 2; h++) {
                int r = row0 + mi * 16 + (lane >> 2) + h * 8;
                float f0 = acc[mi][nj][2 * h] + b0;
                float f1 = acc[mi][nj][2 * h + 1] + b1;
                if (RELU) { f0 = fmaxf(f0, 0.f); f1 = fmaxf(f1, 0.f); }
                *reinterpret_cast<__half2*>(C + (size_t)r * ldc + c) = __floats2half2_rn(f0, f1);
            }
        }
    }
}

// --------------- scatter-mean: CSR build + gather reduce -------------------------
__global__ void zero_cnt_kernel() {
    int i = blockIdx.x * blockDim.x + threadIdx.x;
    if (i < N_NODES_C) { g_cnt[i] = 0; g_cur[i] = 0; }
}
__global__ void count_kernel(const int* __restrict__ ei) {
    int e = blockIdx.x * blockDim.x + threadIdx.x;
    if (e < N_EDGES_C) atomicAdd(&g_cnt[ei[e]], 1);
}
__global__ void scan_kernel() {   // single block, 1024 threads x 16 elems
    __shared__ int ws[32];
    int t = threadIdx.x;
    int base = t * 16;
    int v[16]; int s = 0;
    #pragma unroll
    for (int i = 0; i < 16; i++) { v[i] = s; s += g_cnt[base + i]; }
    int lane = t & 31, w = t >> 5;
    int x = s;
    #pragma unroll
    for (int o = 1; o < 32; o <<= 1) { int y = __shfl_up_sync(~0u, x, o); if (lane >= o) x += y; }
    if (lane == 31) ws[w] = x;
    __syncthreads();
    if (w == 0) {
        int y = ws[lane];
        #pragma unroll
        for (int o = 1; o < 32; o <<= 1) { int z = __shfl_up_sync(~0u, y, o); if (lane >= o) y += z; }
        ws[lane] = y;
    }
    __syncthreads();
    int pre = (x - s) + (w > 0 ? ws[w - 1] : 0);
    #pragma unroll
    for (int i = 0; i < 16; i++) g_off[base + i] = pre + v[i];
    if (t == 1023) g_off[N_NODES_C] = pre + s;
}
__global__ void fill_kernel(const int* __restrict__ ei) {
    int e = blockIdx.x * blockDim.x + threadIdx.x;
    if (e < N_EDGES_C) {
        int r = ei[e];
        int p = g_off[r] + atomicAdd(&g_cur[r], 1);
        g_elist[p] = e;
    }
}
// block per node: mean over its edges of h_n (g_bufB [E,512] fp16); fuse o_in build
__global__ void node_reduce_kernel(const float* __restrict__ x, const int* __restrict__ batch) {
    int n = blockIdx.x;
    int t = threadIdx.x;  // 128
    int deg = g_cnt[n], start = g_off[n];
    float acc0 = 0.f, acc1 = 0.f, acc2 = 0.f, acc3 = 0.f;
    for (int i = 0; i < deg; i++) {
        int e = g_elist[start + i];
        const __half* hr = g_bufB + (size_t)e * NODE_H_C;
        acc0 += __half2float(hr[t]);
        acc1 += __half2float(hr[t + 128]);
        acc2 += __half2float(hr[t + 256]);
        acc3 += __half2float(hr[t + 384]);
    }
    float inv = 1.f / (float)(deg > 0 ? deg : 1);
    __half* dst = g_oin + (size_t)n * K_OIN;
    dst[t]       = __float2half(acc0 * inv);
    dst[t + 128] = __float2half(acc1 * inv);
    dst[t + 256] = __float2half(acc2 * inv);
    dst[t + 384] = __float2half(acc3 * inv);
    int g = batch[n];
    dst[512 + t] = __float2half(g_ur[g * U_RED_C + t]);
    dst[640 + t] = __float2half(g_ur[g * U_RED_C + 128 + t]);
    if (t < 32) dst[768 + t] = __float2half(t < 9 ? x[(size_t)n * 9 + t] : 0.f);
}

// --------------- final dot: out[n] = h2[n,:] . n2_w1 + b --------------------------
__global__ void final_kernel(const float* __restrict__ w, const float* __restrict__ b,
                             float* __restrict__ out) {
    int n = blockIdx.x * 8 + (threadIdx.x >> 5);
    int lane = threadIdx.x & 31;
    const __half* h = g_h2 + (size_t)n * NODE_H_C;
    float s = 0.f;
    #pragma unroll
    for (int j = 0; j < 16; j++) {
        int c = lane + j * 32;
        s += __half2float(h[c]) * w[c];
    }
    #pragma unroll
    for (int o = 16; o > 0; o >>= 1) s += __shfl_xor_sync(~0u, s, o);
    if (lane == 0) out[n] = s + b[0];
}

// ------------------------- host launcher -----------------------------------------
extern "C" void kernel_launch(void* const* d_in, const int* in_sizes, int n_in,
                              void* d_out, int out_size) {
    (void)in_sizes; (void)n_in; (void)out_size;
    const float* x      = (const float*)d_in[0];
    const float* ea     = (const float*)d_in[1];
    const float* u      = (const float*)d_in[2];
    const int*   ei     = (const int*)d_in[3];
    const int*   batch  = (const int*)d_in[4];
    const float* w_dr   = (const float*)d_in[5];
    const float* b_dr   = (const float*)d_in[6];
    const float* e_w0   = (const float*)d_in[7];
    const float* e_b0   = (const float*)d_in[8];
    const float* e_w1   = (const float*)d_in[9];
    const float* e_b1   = (const float*)d_in[10];
    const float* e_w2   = (const float*)d_in[11];
    const float* e_b2   = (const float*)d_in[12];
    const float* e_w3   = (const float*)d_in[13];
    const float* e_b3   = (const float*)d_in[14];
    const float* e_wf   = (const float*)d_in[15];
    const float* e_bf   = (const float*)d_in[16];
    const float* n1_w0  = (const float*)d_in[17];
    const float* n1_b0  = (const float*)d_in[18];
    const float* n1_w1  = (const float*)d_in[19];
    const float* n1_b1  = (const float*)d_in[20];
    const float* n2_w0  = (const float*)d_in[21];
    const float* n2_b0  = (const float*)d_in[22];
    const float* n2_w1  = (const float*)d_in[23];
    const float* n2_b1  = (const float*)d_in[24];
    float* out = (float*)d_out;

    __half *w0h, *w1h, *w2h, *w3h, *wfh, *n1w0h, *n1w1h, *n2w0h;
    __half *ein, *bufA, *bufB, *nin, *oin, *h2;
    cudaGetSymbolAddress((void**)&w0h,   g_w0h);
    cudaGetSymbolAddress((void**)&w1h,   g_w1h);
    cudaGetSymbolAddress((void**)&w2h,   g_w2h);
    cudaGetSymbolAddress((void**)&w3h,   g_w3h);
    cudaGetSymbolAddress((void**)&wfh,   g_wfh);
    cudaGetSymbolAddress((void**)&n1w0h, g_n1w0h);
    cudaGetSymbolAddress((void**)&n1w1h, g_n1w1h);
    cudaGetSymbolAddress((void**)&n2w0h, g_n2w0h);
    cudaGetSymbolAddress((void**)&ein,  g_ein);
    cudaGetSymbolAddress((void**)&bufA, g_bufA);
    cudaGetSymbolAddress((void**)&bufB, g_bufB);
    cudaGetSymbolAddress((void**)&nin,  g_nin);
    cudaGetSymbolAddress((void**)&oin,  g_oin);
    cudaGetSymbolAddress((void**)&h2,   g_h2);

    cudaFuncSetAttribute(gemm_kernel<true>,  cudaFuncAttributeMaxDynamicSharedMemorySize, GEMM_SMEM);
    cudaFuncSetAttribute(gemm_kernel<false>, cudaFuncAttributeMaxDynamicSharedMemorySize, GEMM_SMEM);

    const Seg Z{0, 0, 0};
    auto gsz = [](int n) { return (n + 255) / 256; };

    // pack weights fp32->fp16 with row permutation matching our concat layouts
    pack_weight<<<gsz(K_EIN * 1024), 256>>>(e_w0, w0h, 1024, K_EIN,
        Seg{19, 0, 256}, Seg{0, 256, 9}, Seg{9, 265, 9}, Seg{18, 274, 1});
    pack_weight<<<gsz(1024 * 1024), 256>>>(e_w1, w1h, 1024, 1024, Seg{0, 0, 1024}, Z, Z, Z);
    pack_weight<<<gsz(1024 * 1024), 256>>>(e_w2, w2h, 1024, 1024, Seg{0, 0, 1024}, Z, Z, Z);
    pack_weight<<<gsz(1024 * 1024), 256>>>(e_w3, w3h, 1024, 1024, Seg{0, 0, 1024}, Z, Z, Z);
    pack_weight<<<gsz(1024 * 512),  256>>>(e_wf, wfh, 512, 1024, Seg{0, 0, 1024}, Z, Z, Z);
    pack_weight<<<gsz(K_NIN * 512), 256>>>(n1_w0, n1w0h, 512, K_NIN,
        Seg{9, 0, 512}, Seg{0, 512, 9}, Z, Z);
    pack_weight<<<gsz(512 * 512),   256>>>(n1_w1, n1w1h, 512, 512, Seg{0, 0, 512}, Z, Z, Z);
    pack_weight<<<gsz(K_OIN * 512), 256>>>(n2_w0, n2w0h, 512, K_OIN,
        Seg{9, 0, 512}, Seg{521, 512, 256}, Seg{0, 768, 9}, Z);

    // u dim reduction + edge input build
    dimred_kernel<<<dim3(16, 8), 256>>>(u, w_dr, b_dr);
    build_ein_kernel<<<N_EDGES_C / 8, 256>>>(x, ea, ei, batch);

    const int MT = N_EDGES_C / BM;      // 1024
    const int MTN = N_NODES_C / BM;     // 128

    // edge MLP
    gemm_kernel<true ><<<dim3(4, MT), GT, GEMM_SMEM>>>(ein,  K_EIN, w0h, 1024, e_b0, bufA, 1024, K_EIN);
    gemm_kernel<true ><<<dim3(4, MT), GT, GEMM_SMEM>>>(bufA, 1024,  w1h, 1024, e_b1, bufB, 1024, 1024);
    gemm_kernel<true ><<<dim3(4, MT), GT, GEMM_SMEM>>>(bufB, 1024,  w2h, 1024, e_b2, bufA, 1024, 1024);
    gemm_kernel<true ><<<dim3(4, MT), GT, GEMM_SMEM>>>(bufA, 1024,  w3h, 1024, e_b3, bufB, 1024, 1024);
    gemm_kernel<false><<<dim3(2, MT), GT, GEMM_SMEM>>>(bufB, 1024,  wfh,  512, e_bf, nin,  K_NIN, 1024);

    // node MLP 1 (inputs: [e 0-511][x_col 512-520])
    add_x_nin_kernel<<<N_EDGES_C / 8, 256>>>(x, ei);
    gemm_kernel<true ><<<dim3(2, MT), GT, GEMM_SMEM>>>(nin,  K_NIN, n1w0h, 512, n1_b0, bufA, 512, K_NIN);
    gemm_kernel<true ><<<dim3(2, MT), GT, GEMM_SMEM>>>(bufA, 512,   n1w1h, 512, n1_b1, bufB, 512, 512);

    // scatter-mean via CSR build, fused with o_in construction
    zero_cnt_kernel<<<N_NODES_C / 256, 256>>>();
    count_kernel<<<N_EDGES_C / 256, 256>>>(ei);
    scan_kernel<<<1, 1024>>>();
    fill_kernel<<<N_EDGES_C / 256, 256>>>(ei);
    node_reduce_kernel<<<N_NODES_C, 128>>>(x, batch);

    // node MLP 2 + final dot
    gemm_kernel<true ><<<dim3(2, MTN), GT, GEMM_SMEM>>>(oin, K_OIN, n2w0h, 512, n2_b0, h2, 512, K_OIN);
    final_kernel<<<N_NODES_C / 8, 256>>>(n2_w1, n2_b1, out);
}

// round 9
// speedup vs baseline: 1.1395x; 1.1395x over previous
#include <cuda_runtime.h>
#include <cuda_fp16.h>
#include <cstdint>

#define DI __device__ __forceinline__

// ------------------------- problem sizes -------------------------
#define N_NODES_C 16384
#define N_EDGES_C 131072
#define N_GRAPHS_C 16
#define U_SZ_C 4096
#define U_RED_C 256
#define EDGE_H_C 1024
#define EDGE_OUT_C 512
#define NODE_H_C 512

// n_in : [e 0-511][x_col 512-520][pad->543]
#define K_NIN 544

// ------------------------- device scratch -------------------------
__device__ __half g_bufA[(size_t)N_EDGES_C * EDGE_H_C];
__device__ __half g_bufB[(size_t)N_EDGES_C * EDGE_H_C];
__device__ __half g_nin [(size_t)N_EDGES_C * K_NIN];
__device__ __half g_oin [(size_t)N_NODES_C * NODE_H_C];
__device__ __half g_h2  [(size_t)N_NODES_C * NODE_H_C];
__device__ float  g_ur  [N_GRAPHS_C * U_RED_C];

// layer-0 factorization tables
__device__ __half g_pr  [(size_t)N_NODES_C * EDGE_H_C];   // x @ W_xr
__device__ __half g_pc  [(size_t)N_NODES_C * EDGE_H_C];   // x @ W_xc
__device__ float  g_ue  [N_GRAPHS_C * EDGE_H_C];          // u_r @ W_u + b0
__device__ float  g_un  [N_GRAPHS_C * NODE_H_C];          // u_r @ W_u2 + b2
__device__ float  g_addn[(size_t)N_NODES_C * NODE_H_C];   // row bias for n2 GEMM

// weights packed [Kp, N] row-major fp16 (with concat-permuted K rows)
__device__ __half g_w1h  [EDGE_H_C * EDGE_H_C];
__device__ __half g_w2h  [EDGE_H_C * EDGE_H_C];
__device__ __half g_w3h  [EDGE_H_C * EDGE_H_C];
__device__ __half g_wfh  [EDGE_H_C * EDGE_OUT_C];
__device__ __half g_n1w0h[K_NIN    * NODE_H_C];
__device__ __half g_n1w1h[NODE_H_C * NODE_H_C];
__device__ __half g_n2w0h[NODE_H_C * NODE_H_C];   // agg block rows 9..520

__device__ int g_cnt[N_NODES_C];
__device__ int g_off[N_NODES_C + 1];
__device__ int g_cur[N_NODES_C];
__device__ int g_elist[N_EDGES_C];

// ------------------------- small helpers -------------------------
DI uint32_t smem_u32(const void* p) {
    return (uint32_t)__cvta_generic_to_shared(p);
}
DI void cp16(uint32_t dst, const void* src) {
    asm volatile("cp.async.cg.shared.global [%0], [%1], 16;\n" :: "r"(dst), "l"(src));
}
DI void cp_commit() { asm volatile("cp.async.commit_group;\n"); }
DI void cp_wait1()  { asm volatile("cp.async.wait_group 1;\n"); }

DI void ldm_x4(uint32_t addr, uint32_t& r0, uint32_t& r1, uint32_t& r2, uint32_t& r3) {
    asm volatile("ldmatrix.sync.aligned.m8n8.x4.shared.b16 {%0,%1,%2,%3}, [%4];\n"
                 : "=r"(r0), "=r"(r1), "=r"(r2), "=r"(r3) : "r"(addr));
}
DI void ldm_x4t(uint32_t addr, uint32_t& r0, uint32_t& r1, uint32_t& r2, uint32_t& r3) {
    asm volatile("ldmatrix.sync.aligned.m8n8.x4.trans.shared.b16 {%0,%1,%2,%3}, [%4];\n"
                 : "=r"(r0), "=r"(r1), "=r"(r2), "=r"(r3) : "r"(addr));
}
DI void mma16816(float* d, const uint32_t* a, const uint32_t* b) {
    asm volatile("mma.sync.aligned.m16n8k16.row.col.f32.f16.f16.f32 "
                 "{%0,%1,%2,%3}, {%4,%5,%6,%7}, {%8,%9}, {%0,%1,%2,%3};\n"
                 : "+f"(d[0]), "+f"(d[1]), "+f"(d[2]), "+f"(d[3])
                 : "r"(a[0]), "r"(a[1]), "r"(a[2]), "r"(a[3]),
                   "r"(b[0]), "r"(b[1]));
}

// --------------- weight pack: fp32 -> fp16, row permute + zero pad ---------------
struct Seg { int src0, dst0, n; };

__global__ void pack_weight(const float* __restrict__ src, __half* __restrict__ dst,
                            int N, int Kp, Seg a, Seg b, Seg c, Seg d) {
    int idx = blockIdx.x * blockDim.x + threadIdx.x;
    if (idx >= Kp * N) return;
    int r = idx / N, col = idx - r * N;
    float v = 0.f;
    if      (r >= a.dst0 && r < a.dst0 + a.n) v = src[(size_t)(a.src0 + r - a.dst0) * N + col];
    else if (r >= b.dst0 && r < b.dst0 + b.n) v = src[(size_t)(b.src0 + r - b.dst0) * N + col];
    else if (r >= c.dst0 && r < c.dst0 + c.n) v = src[(size_t)(c.src0 + r - c.dst0) * N + col];
    else if (r >= d.dst0 && r < d.dst0 + d.n) v = src[(size_t)(d.src0 + r - d.dst0) * N + col];
    dst[idx] = __float2half(v);
}

// --------------- dim reduction: u_r = u @ w_dr + b_dr (fp32, tiny) ---------------
__global__ void dimred_kernel(const float* __restrict__ u, const float* __restrict__ w,
                              const float* __restrict__ b) {
    __shared__ float red[8][32];
    int g = blockIdx.x, ct = blockIdx.y;
    int kg = threadIdx.x >> 5, cl = threadIdx.x & 31;
    int c = ct * 32 + cl;
    const float* up = u + (size_t)g * U_SZ_C + kg * 512;
    const float* wp = w + (size_t)(kg * 512) * U_RED_C + c;
    float s = 0.f;
    #pragma unroll 8
    for (int k = 0; k < 512; k++) s += up[k] * wp[(size_t)k * U_RED_C];
    red[kg][cl] = s;
    __syncthreads();
    if (kg == 0) {
        float t = b[c];
        #pragma unroll
        for (int i = 0; i < 8; i++) t += red[i][cl];
        g_ur[g * U_RED_C + c] = t;
    }
}

// --------------- layer-0 factorization precomputes -------------------------------
// PR/PC[n,c]: x[n,:9] @ e_w0 rows 0-8 (src) / 9-17 (dest). e_w0 raw fp32 [275,1024].
__global__ void prexw_kernel(const float* __restrict__ x, const float* __restrict__ e_w0) {
    int c = blockIdx.x * 256 + threadIdx.x;
    int n = blockIdx.y;
    float xr[9];
    #pragma unroll
    for (int j = 0; j < 9; j++) xr[j] = x[(size_t)n * 9 + j];
    float pr = 0.f, pc = 0.f;
    #pragma unroll
    for (int j = 0; j < 9; j++) {
        pr += xr[j] * e_w0[(size_t)j * EDGE_H_C + c];
        pc += xr[j] * e_w0[(size_t)(9 + j) * EDGE_H_C + c];
    }
    g_pr[(size_t)n * EDGE_H_C + c] = __float2half(pr);
    g_pc[(size_t)n * EDGE_H_C + c] = __float2half(pc);
}

// Ue[g,c] = sum_j ur[g,j] * e_w0[19+j, c] + e_b0[c]
__global__ void ue_kernel(const float* __restrict__ e_w0, const float* __restrict__ e_b0) {
    int c = blockIdx.y * 256 + threadIdx.x;
    int g = blockIdx.x;
    float s = e_b0[c];
    #pragma unroll 4
    for (int j = 0; j < U_RED_C; j++)
        s += g_ur[g * U_RED_C + j] * e_w0[(size_t)(19 + j) * EDGE_H_C + c];
    g_ue[g * EDGE_H_C + c] = s;
}

// Un[g,c] = sum_j ur[g,j] * n2_w0[521+j, c] + n2_b0[c]
__global__ void un_kernel(const float* __restrict__ n2_w0, const float* __restrict__ n2_b0) {
    int c = blockIdx.y * 256 + threadIdx.x;
    int g = blockIdx.x;
    float s = n2_b0[c];
    #pragma unroll 4
    for (int j = 0; j < U_RED_C; j++)
        s += g_ur[g * U_RED_C + j] * n2_w0[(size_t)(521 + j) * NODE_H_C + c];
    g_un[g * NODE_H_C + c] = s;
}

// ADDN[n,c] = Un[batch[n],c] + x[n,:9] @ n2_w0 rows 0-8
__global__ void addn_kernel(const float* __restrict__ x, const int* __restrict__ batch,
                            const float* __restrict__ n2_w0) {
    int c = blockIdx.x * 256 + threadIdx.x;
    int n = blockIdx.y;
    int g = batch[n];
    float s = g_un[g * NODE_H_C + c];
    #pragma unroll
    for (int j = 0; j < 9; j++)
        s += x[(size_t)n * 9 + j] * n2_w0[(size_t)j * NODE_H_C + c];
    g_addn[(size_t)n * NODE_H_C + c] = s;
}

// --------------- edge layer 0 via gather-add: h0 -> bufA --------------------------
// h0[e,c] = relu(PR[row,c] + PC[col,c] + ea[e]*w_ea[c] + Ue[batch[row],c])
__global__ void edge_l0_kernel(const float* __restrict__ ea, const int* __restrict__ ei,
                               const int* __restrict__ batch, const float* __restrict__ e_w0) {
    int e = blockIdx.x * 2 + (threadIdx.x >> 7);
    int t = threadIdx.x & 127;          // 128 threads x 8 cols = 1024
    int row = ei[e], col = ei[N_EDGES_C + e];
    int g = batch[row];
    float eav = ea[e];
    int c0 = t * 8;

    uint4 prv = *reinterpret_cast<const uint4*>(g_pr + (size_t)row * EDGE_H_C + c0);
    uint4 pcv = *reinterpret_cast<const uint4*>(g_pc + (size_t)col * EDGE_H_C + c0);
    const __half2* pr2 = reinterpret_cast<const __half2*>(&prv);
    const __half2* pc2 = reinterpret_cast<const __half2*>(&pcv);
    const float* wea = e_w0 + (size_t)18 * EDGE_H_C + c0;
    const float* ue  = g_ue + g * EDGE_H_C + c0;

    uint4 outv;
    __half2* o2 = reinterpret_cast<__half2*>(&outv);
    #pragma unroll
    for (int i = 0; i < 4; i++) {
        float2 fp = __half22float2(pr2[i]);
        float2 fc = __half22float2(pc2[i]);
        float f0 = fp.x + fc.x + eav * wea[2 * i]     + ue[2 * i];
        float f1 = fp.y + fc.y + eav * wea[2 * i + 1] + ue[2 * i + 1];
        f0 = fmaxf(f0, 0.f); f1 = fmaxf(f1, 0.f);
        o2[i] = __floats2half2_rn(f0, f1);
    }
    *reinterpret_cast<uint4*>(g_bufA + (size_t)e * EDGE_H_C + c0) = outv;
}

// x[col] into n_in cols 512..520, zeros to 543
__global__ void add_x_nin_kernel(const float* __restrict__ x, const int* __restrict__ ei) {
    int e = blockIdx.x * 8 + (threadIdx.x >> 5);
    int lane = threadIdx.x & 31;
    int c = ei[N_EDGES_C + e];
    float v = (lane < 9) ? x[(size_t)c * 9 + lane] : 0.f;
    g_nin[(size_t)e * K_NIN + 512 + lane] = __float2half(v);
}

// ------------------------- fp16 tensor-core GEMM ---------------------------------
// C[M,N](fp16) = act(A[M,K](fp16,row) @ B[K,N](fp16,row) + bias)
// BM=128, BN=256, BK=32, 8 warps (2M x 4N), 3-stage cp.async, fp32 accumulate.
// ROWBIAS: bias is a per-row fp32 table [Mtot, ldc] added elementwise.
#define BM 128
#define BN 256
#define BKK 32
#define GT 256
#define STG 3
#define A_ST (BM * 40)     // halves per A stage (pad 32->40)
#define B_ST (BKK * 264)   // halves per B stage (pad 256->264)
#define GEMM_SMEM (STG * (A_ST + B_ST) * 2)

template<bool RELU, bool ROWBIAS>
__global__ __launch_bounds__(GT, 1)
void gemm_kernel(const __half* __restrict__ A, int lda,
                 const __half* __restrict__ B, int ldb,
                 const float* __restrict__ bias,
                 __half* __restrict__ C, int ldc, int K) {
    extern __shared__ __half sm[];
    __half* Asm = sm;                    // [STG][128][40]
    __half* Bsm = sm + STG * A_ST;       // [STG][32][264]

    const int tid  = threadIdx.x;
    const int lane = tid & 31, warp = tid >> 5;
    const int wm = warp & 1;    // 2 warps along M -> 64 rows each
    const int wn = warp >> 1;   // 4 warps along N -> 64 cols each
    const int bm = blockIdx.y, bn = blockIdx.x;

    const __half* Ag = A + (size_t)bm * BM * lda;
    const __half* Bg = B + (size_t)bn * BN;

    float acc[4][8][4];
    #pragma unroll
    for (int i = 0; i < 4; i++)
        #pragma unroll
        for (int j = 0; j < 8; j++)
            #pragma unroll
            for (int k = 0; k < 4; k++) acc[i][j][k] = 0.f;

    const int KT = K / BKK;

    auto load = [&](int kt, int st) {
        __half* as = Asm + st * A_ST;
        __half* bs = Bsm + st * B_ST;
        #pragma unroll
        for (int i = 0; i < 2; i++) {
            int ch = tid + i * GT;               // 512 x 16B chunks for A
            int r = ch >> 2, cc = (ch & 3) << 3;
            cp16(smem_u32(as + r * 40 + cc), Ag + (size_t)r * lda + kt * BKK + cc);
        }
        #pragma unroll
        for (int i = 0; i < 4; i++) {
            int ch = tid + i * GT;               // 1024 x 16B chunks for B
            int r = ch >> 5, cc = (ch & 31) << 3;
            cp16(smem_u32(bs + r * 264 + cc), Bg + (size_t)(kt * BKK + r) * ldb + cc);
        }
        cp_commit();
    };

    load(0, 0);
    load(1, 1);

    for (int kt = 0; kt < KT; kt++) {
        cp_wait1();
        __syncthreads();
        const int st = kt % 3;
        if (kt + 2 < KT) load(kt + 2, (kt + 2) % 3);
        else             cp_commit();

        #pragma unroll
        for (int ks = 0; ks < 2; ks++) {
            uint32_t afr[4][4];
            {
                const __half* as = Asm + st * A_ST;
                int row = wm * 64 + (lane & 15);
                int col = ks * 16 + (lane >> 4) * 8;
                #pragma unroll
                for (int mi = 0; mi < 4; mi++)
                    ldm_x4(smem_u32(as + (row + mi * 16) * 40 + col),
                           afr[mi][0], afr[mi][1], afr[mi][2], afr[mi][3]);
            }
            uint32_t bfr[8][2];
            {
                const __half* bs = Bsm + st * B_ST;
                int row = ks * 16 + ((lane >> 3) & 1) * 8 + (lane & 7);
                #pragma unroll
                for (int p = 0; p < 4; p++) {
                    int col = wn * 64 + p * 16 + (lane >> 4) * 8;
                    uint32_t r0, r1, r2, r3;
                    ldm_x4t(smem_u32(bs + row * 264 + col), r0, r1, r2, r3);
                    bfr[2 * p][0] = r0;     bfr[2 * p][1] = r1;
                    bfr[2 * p + 1][0] = r2; bfr[2 * p + 1][1] = r3;
                }
            }
            #pragma unroll
            for (int mi = 0; mi < 4; mi++)
                #pragma unroll
                for (int nj = 0; nj < 8; nj++)
                    mma16816(acc[mi][nj], afr[mi], bfr[nj]);
        }
    }

    // epilogue
    int row0 = bm * BM + wm * 64;
    int col0 = bn * BN + wn * 64;
    #pragma unroll
    for (int mi = 0; mi < 4; mi++) {
        #pragma unroll
        for (int nj = 0; nj < 8; nj++) {
            int c = col0 + nj * 8 + (lane & 3) * 2;
            float b0 = 0.f, b1 = 0.f;
            if (!ROWBIAS) { b0 = bias[c]; b1 = bias[c + 1]; }
            #pragma unroll
            for (int h = 0; h < 2; h++) {
                int r = row0 + mi * 16 + (lane >> 2) + h * 8;
                if (ROWBIAS) {
                    const float* ab = bias + (size_t)r * ldc + c;
                    b0 = ab[0]; b1 = ab[1];
                }
                float f0 = acc[mi][nj][2 * h] + b0;
                float f1 = acc[mi][nj][2 * h + 1] + b1;
                if (RELU) { f0 = fmaxf(f0, 0.f); f1 = fmaxf(f1, 0.f); }
                *reinterpret_cast<__half2*>(C + (size_t)r * ldc + c) = __floats2half2_rn(f0, f1);
            }
        }
    }
}

// --------------- scatter-mean: CSR build + gather reduce -------------------------
__global__ void zero_cnt_kernel() {
    int i = blockIdx.x * blockDim.x + threadIdx.x;
    if (i < N_NODES_C) { g_cnt[i] = 0; g_cur[i] = 0; }
}
__global__ void count_kernel(const int* __restrict__ ei) {
    int e = blockIdx.x * blockDim.x + threadIdx.x;
    if (e < N_EDGES_C) atomicAdd(&g_cnt[ei[e]], 1);
}
__global__ void scan_kernel() {   // single block, 1024 threads x 16 elems
    __shared__ int ws[32];
    int t = threadIdx.x;
    int base = t * 16;
    int v[16]; int s = 0;
    #pragma unroll
    for (int i = 0; i < 16; i++) { v[i] = s; s += g_cnt[base + i]; }
    int lane = t & 31, w = t >> 5;
    int x = s;
    #pragma unroll
    for (int o = 1; o < 32; o <<= 1) { int y = __shfl_up_sync(~0u, x, o); if (lane >= o) x += y; }
    if (lane == 31) ws[w] = x;
    __syncthreads();
    if (w == 0) {
        int y = ws[lane];
        #pragma unroll
        for (int o = 1; o < 32; o <<= 1) { int z = __shfl_up_sync(~0u, y, o); if (lane >= o) y += z; }
        ws[lane] = y;
    }
    __syncthreads();
    int pre = (x - s) + (w > 0 ? ws[w - 1] : 0);
    #pragma unroll
    for (int i = 0; i < 16; i++) g_off[base + i] = pre + v[i];
    if (t == 1023) g_off[N_NODES_C] = pre + s;
}
__global__ void fill_kernel(const int* __restrict__ ei) {
    int e = blockIdx.x * blockDim.x + threadIdx.x;
    if (e < N_EDGES_C) {
        int r = ei[e];
        int p = g_off[r] + atomicAdd(&g_cur[r], 1);
        g_elist[p] = e;
    }
}
// block per node: mean over its edges of h_n (g_bufB [E,512] fp16) -> oin (agg only)
__global__ void node_reduce_kernel() {
    int n = blockIdx.x;
    int t = threadIdx.x;  // 128
    int deg = g_cnt[n], start = g_off[n];
    float acc0 = 0.f, acc1 = 0.f, acc2 = 0.f, acc3 = 0.f;
    for (int i = 0; i < deg; i++) {
        int e = g_elist[start + i];
        const __half* hr = g_bufB + (size_t)e * NODE_H_C;
        acc0 += __half2float(hr[t]);
        acc1 += __half2float(hr[t + 128]);
        acc2 += __half2float(hr[t + 256]);
        acc3 += __half2float(hr[t + 384]);
    }
    float inv = 1.f / (float)(deg > 0 ? deg : 1);
    __half* dst = g_oin + (size_t)n * NODE_H_C;
    dst[t]       = __float2half(acc0 * inv);
    dst[t + 128] = __float2half(acc1 * inv);
    dst[t + 256] = __float2half(acc2 * inv);
    dst[t + 384] = __float2half(acc3 * inv);
}

// --------------- final dot: out[n] = h2[n,:] . n2_w1 + b --------------------------
__global__ void final_kernel(const float* __restrict__ w, const float* __restrict__ b,
                             float* __restrict__ out) {
    int n = blockIdx.x * 8 + (threadIdx.x >> 5);
    int lane = threadIdx.x & 31;
    const __half* h = g_h2 + (size_t)n * NODE_H_C;
    float s = 0.f;
    #pragma unroll
    for (int j = 0; j < 16; j++) {
        int c = lane + j * 32;
        s += __half2float(h[c]) * w[c];
    }
    #pragma unroll
    for (int o = 16; o > 0; o >>= 1) s += __shfl_xor_sync(~0u, s, o);
    if (lane == 0) out[n] = s + b[0];
}

// ------------------------- host launcher -----------------------------------------
extern "C" void kernel_launch(void* const* d_in, const int* in_sizes, int n_in,
                              void* d_out, int out_size) {
    (void)in_sizes; (void)n_in; (void)out_size;
    const float* x      = (const float*)d_in[0];
    const float* ea     = (const float*)d_in[1];
    const float* u      = (const float*)d_in[2];
    const int*   ei     = (const int*)d_in[3];
    const int*   batch  = (const int*)d_in[4];
    const float* w_dr   = (const float*)d_in[5];
    const float* b_dr   = (const float*)d_in[6];
    const float* e_w0   = (const float*)d_in[7];
    const float* e_b0   = (const float*)d_in[8];
    const float* e_w1   = (const float*)d_in[9];
    const float* e_b1   = (const float*)d_in[10];
    const float* e_w2   = (const float*)d_in[11];
    const float* e_b2   = (const float*)d_in[12];
    const float* e_w3   = (const float*)d_in[13];
    const float* e_b3   = (const float*)d_in[14];
    const float* e_wf   = (const float*)d_in[15];
    const float* e_bf   = (const float*)d_in[16];
    const float* n1_w0  = (const float*)d_in[17];
    const float* n1_b0  = (const float*)d_in[18];
    const float* n1_w1  = (const float*)d_in[19];
    const float* n1_b1  = (const float*)d_in[20];
    const float* n2_w0  = (const float*)d_in[21];
    const float* n2_b0  = (const float*)d_in[22];
    const float* n2_w1  = (const float*)d_in[23];
    const float* n2_b1  = (const float*)d_in[24];
    float* out = (float*)d_out;

    __half *w1h, *w2h, *w3h, *wfh, *n1w0h, *n1w1h, *n2w0h;
    __half *bufA, *bufB, *nin, *oin, *h2;
    float  *addn;
    cudaGetSymbolAddress((void**)&w1h,   g_w1h);
    cudaGetSymbolAddress((void**)&w2h,   g_w2h);
    cudaGetSymbolAddress((void**)&w3h,   g_w3h);
    cudaGetSymbolAddress((void**)&wfh,   g_wfh);
    cudaGetSymbolAddress((void**)&n1w0h, g_n1w0h);
    cudaGetSymbolAddress((void**)&n1w1h, g_n1w1h);
    cudaGetSymbolAddress((void**)&n2w0h, g_n2w0h);
    cudaGetSymbolAddress((void**)&bufA, g_bufA);
    cudaGetSymbolAddress((void**)&bufB, g_bufB);
    cudaGetSymbolAddress((void**)&nin,  g_nin);
    cudaGetSymbolAddress((void**)&oin,  g_oin);
    cudaGetSymbolAddress((void**)&h2,   g_h2);
    cudaGetSymbolAddress((void**)&addn, g_addn);

    cudaFuncSetAttribute((const void*)gemm_kernel<true,  false>, cudaFuncAttributeMaxDynamicSharedMemorySize, GEMM_SMEM);
    cudaFuncSetAttribute((const void*)gemm_kernel<false, false>, cudaFuncAttributeMaxDynamicSharedMemorySize, GEMM_SMEM);
    cudaFuncSetAttribute((const void*)gemm_kernel<true,  true >, cudaFuncAttributeMaxDynamicSharedMemorySize, GEMM_SMEM);

    const Seg Z{0, 0, 0};
    auto gsz = [](int n) { return (n + 255) / 256; };

    // pack weights fp32->fp16 (w0 / n2-x / n2-u blocks handled by factorization)
    pack_weight<<<gsz(1024 * 1024), 256>>>(e_w1, w1h, 1024, 1024, Seg{0, 0, 1024}, Z, Z, Z);
    pack_weight<<<gsz(1024 * 1024), 256>>>(e_w2, w2h, 1024, 1024, Seg{0, 0, 1024}, Z, Z, Z);
    pack_weight<<<gsz(1024 * 1024), 256>>>(e_w3, w3h, 1024, 1024, Seg{0, 0, 1024}, Z, Z, Z);
    pack_weight<<<gsz(1024 * 512),  256>>>(e_wf, wfh, 512, 1024, Seg{0, 0, 1024}, Z, Z, Z);
    pack_weight<<<gsz(K_NIN * 512), 256>>>(n1_w0, n1w0h, 512, K_NIN,
        Seg{9, 0, 512}, Seg{0, 512, 9}, Z, Z);
    pack_weight<<<gsz(512 * 512),   256>>>(n1_w1, n1w1h, 512, 512, Seg{0, 0, 512}, Z, Z, Z);
    pack_weight<<<gsz(512 * 512),   256>>>(n2_w0, n2w0h, 512, 512, Seg{9, 0, 512}, Z, Z, Z);

    // u dim reduction + factorization tables
    dimred_kernel<<<dim3(16, 8), 256>>>(u, w_dr, b_dr);
    prexw_kernel<<<dim3(4, N_NODES_C), 256>>>(x, e_w0);
    ue_kernel<<<dim3(16, 4), 256>>>(e_w0, e_b0);
    un_kernel<<<dim3(16, 2), 256>>>(n2_w0, n2_b0);
    addn_kernel<<<dim3(2, N_NODES_C), 256>>>(x, batch, n2_w0);

    // edge layer 0 via gather-add -> bufA
    edge_l0_kernel<<<N_EDGES_C / 2, 256>>>(ea, ei, batch, e_w0);

    const int MT = N_EDGES_C / BM;      // 1024
    const int MTN = N_NODES_C / BM;     // 128

    // edge MLP interior + final
    gemm_kernel<true , false><<<dim3(4, MT), GT, GEMM_SMEM>>>(bufA, 1024, w1h, 1024, e_b1, bufB, 1024, 1024);
    gemm_kernel<true , false><<<dim3(4, MT), GT, GEMM_SMEM>>>(bufB, 1024, w2h, 1024, e_b2, bufA, 1024, 1024);
    gemm_kernel<true , false><<<dim3(4, MT), GT, GEMM_SMEM>>>(bufA, 1024, w3h, 1024, e_b3, bufB, 1024, 1024);
    gemm_kernel<false, false><<<dim3(2, MT), GT, GEMM_SMEM>>>(bufB, 1024, wfh,  512, e_bf, nin,  K_NIN, 1024);

    // node MLP 1 (inputs: [e 0-511][x_col 512-520])
    add_x_nin_kernel<<<N_EDGES_C / 8, 256>>>(x, ei);
    gemm_kernel<true , false><<<dim3(2, MT), GT, GEMM_SMEM>>>(nin,  K_NIN, n1w0h, 512, n1_b0, bufA, 512, K_NIN);
    gemm_kernel<true , false><<<dim3(2, MT), GT, GEMM_SMEM>>>(bufA, 512,   n1w1h, 512, n1_b1, bufB, 512, 512);

    // scatter-mean via CSR build
    zero_cnt_kernel<<<N_NODES_C / 256, 256>>>();
    count_kernel<<<N_EDGES_C / 256, 256>>>(ei);
    scan_kernel<<<1, 1024>>>();
    fill_kernel<<<N_EDGES_C / 256, 256>>>(ei);
    node_reduce_kernel<<<N_NODES_C, 128>>>();

    // node MLP 2 (K=512, row-bias table carries x/u_r/bias contributions) + final dot
    gemm_kernel<true , true ><<<dim3(2, MTN), GT, GEMM_SMEM>>>(oin, 512, n2w0h, 512, addn, h2, 512, 512);
    final_kernel<<<N_NODES_C / 8, 256>>>(n2_w1, n2_b1, out);
}

// round 10
// speedup vs baseline: 1.1600x; 1.0180x over previous
#include <cuda_runtime.h>
#include <cuda_fp16.h>
#include <cstdint>

#define DI __device__ __forceinline__

// ------------------------- problem sizes -------------------------
#define N_NODES_C 16384
#define N_EDGES_C 131072
#define N_GRAPHS_C 16
#define U_SZ_C 4096
#define U_RED_C 256
#define EDGE_H_C 1024
#define EDGE_OUT_C 512
#define NODE_H_C 512

// ------------------------- device scratch -------------------------
__device__ __half g_bufA[(size_t)N_EDGES_C * EDGE_H_C];
__device__ __half g_bufB[(size_t)N_EDGES_C * EDGE_H_C];
__device__ __half g_oin [(size_t)N_NODES_C * NODE_H_C];
__device__ __half g_h2  [(size_t)N_NODES_C * NODE_H_C];
__device__ float  g_ur  [N_GRAPHS_C * U_RED_C];

// layer-0 factorization tables
__device__ __half g_pr  [(size_t)N_NODES_C * EDGE_H_C];   // x @ W_xr
__device__ __half g_pc  [(size_t)N_NODES_C * EDGE_H_C];   // x @ W_xc
__device__ float  g_ue  [N_GRAPHS_C * EDGE_H_C];          // u_r @ W_u + e_b0
__device__ float  g_un  [N_GRAPHS_C * NODE_H_C];          // u_r @ W_u2 + n2_b0
__device__ float  g_addn[(size_t)N_NODES_C * NODE_H_C];   // row bias for n2 GEMM

// e_wf -> n1_w0 fusion tables
__device__ __half g_cw  [EDGE_H_C * NODE_H_C];            // e_wf @ n1_w0[9:521]
__device__ float  g_bb  [NODE_H_C];                        // n1_b0 + e_bf @ W_e
__device__ float  g_pn1 [(size_t)N_NODES_C * NODE_H_C];   // bb + x[n] @ W_x (per node)
__device__ float  g_zero[NODE_H_C];                        // stays 0 (module zero-init)

// weights packed [Kp, N] row-major fp16
__device__ __half g_w1h  [EDGE_H_C * EDGE_H_C];
__device__ __half g_w2h  [EDGE_H_C * EDGE_H_C];
__device__ __half g_w3h  [EDGE_H_C * EDGE_H_C];
__device__ __half g_wfh  [EDGE_H_C * EDGE_OUT_C];
__device__ __half g_n1w0h[NODE_H_C * NODE_H_C];   // n1_w0 rows 9..520 (e-part)
__device__ __half g_n1w1h[NODE_H_C * NODE_H_C];
__device__ __half g_n2w0h[NODE_H_C * NODE_H_C];   // n2_w0 rows 9..520 (agg-part)

__device__ int g_cnt[N_NODES_C];
__device__ int g_off[N_NODES_C + 1];
__device__ int g_cur[N_NODES_C];
__device__ int g_elist[N_EDGES_C];

// ------------------------- small helpers -------------------------
DI uint32_t smem_u32(const void* p) {
    return (uint32_t)__cvta_generic_to_shared(p);
}
DI void cp16(uint32_t dst, const void* src) {
    asm volatile("cp.async.cg.shared.global [%0], [%1], 16;\n" :: "r"(dst), "l"(src));
}
DI void cp_commit() { asm volatile("cp.async.commit_group;\n"); }
DI void cp_wait1()  { asm volatile("cp.async.wait_group 1;\n"); }

DI void ldm_x4(uint32_t addr, uint32_t& r0, uint32_t& r1, uint32_t& r2, uint32_t& r3) {
    asm volatile("ldmatrix.sync.aligned.m8n8.x4.shared.b16 {%0,%1,%2,%3}, [%4];\n"
                 : "=r"(r0), "=r"(r1), "=r"(r2), "=r"(r3) : "r"(addr));
}
DI void ldm_x4t(uint32_t addr, uint32_t& r0, uint32_t& r1, uint32_t& r2, uint32_t& r3) {
    asm volatile("ldmatrix.sync.aligned.m8n8.x4.trans.shared.b16 {%0,%1,%2,%3}, [%4];\n"
                 : "=r"(r0), "=r"(r1), "=r"(r2), "=r"(r3) : "r"(addr));
}
DI void mma16816(float* d, const uint32_t* a, const uint32_t* b) {
    asm volatile("mma.sync.aligned.m16n8k16.row.col.f32.f16.f16.f32 "
                 "{%0,%1,%2,%3}, {%4,%5,%6,%7}, {%8,%9}, {%0,%1,%2,%3};\n"
                 : "+f"(d[0]), "+f"(d[1]), "+f"(d[2]), "+f"(d[3])
                 : "r"(a[0]), "r"(a[1]), "r"(a[2]), "r"(a[3]),
                   "r"(b[0]), "r"(b[1]));
}

// --------------- weight pack: fp32 -> fp16, row permute + zero pad ---------------
struct Seg { int src0, dst0, n; };

__global__ void pack_weight(const float* __restrict__ src, __half* __restrict__ dst,
                            int N, int Kp, Seg a, Seg b, Seg c, Seg d) {
    int idx = blockIdx.x * blockDim.x + threadIdx.x;
    if (idx >= Kp * N) return;
    int r = idx / N, col = idx - r * N;
    float v = 0.f;
    if      (r >= a.dst0 && r < a.dst0 + a.n) v = src[(size_t)(a.src0 + r - a.dst0) * N + col];
    else if (r >= b.dst0 && r < b.dst0 + b.n) v = src[(size_t)(b.src0 + r - b.dst0) * N + col];
    else if (r >= c.dst0 && r < c.dst0 + c.n) v = src[(size_t)(c.src0 + r - c.dst0) * N + col];
    else if (r >= d.dst0 && r < d.dst0 + d.n) v = src[(size_t)(d.src0 + r - d.dst0) * N + col];
    dst[idx] = __float2half(v);
}

// --------------- dim reduction: u_r = u @ w_dr + b_dr (fp32, tiny) ---------------
__global__ void dimred_kernel(const float* __restrict__ u, const float* __restrict__ w,
                              const float* __restrict__ b) {
    __shared__ float red[8][32];
    int g = blockIdx.x, ct = blockIdx.y;
    int kg = threadIdx.x >> 5, cl = threadIdx.x & 31;
    int c = ct * 32 + cl;
    const float* up = u + (size_t)g * U_SZ_C + kg * 512;
    const float* wp = w + (size_t)(kg * 512) * U_RED_C + c;
    float s = 0.f;
    #pragma unroll 8
    for (int k = 0; k < 512; k++) s += up[k] * wp[(size_t)k * U_RED_C];
    red[kg][cl] = s;
    __syncthreads();
    if (kg == 0) {
        float t = b[c];
        #pragma unroll
        for (int i = 0; i < 8; i++) t += red[i][cl];
        g_ur[g * U_RED_C + c] = t;
    }
}

// --------------- layer-0 factorization precomputes -------------------------------
__global__ void prexw_kernel(const float* __restrict__ x, const float* __restrict__ e_w0) {
    int c = blockIdx.x * 256 + threadIdx.x;
    int n = blockIdx.y;
    float xr[9];
    #pragma unroll
    for (int j = 0; j < 9; j++) xr[j] = x[(size_t)n * 9 + j];
    float pr = 0.f, pc = 0.f;
    #pragma unroll
    for (int j = 0; j < 9; j++) {
        pr += xr[j] * e_w0[(size_t)j * EDGE_H_C + c];
        pc += xr[j] * e_w0[(size_t)(9 + j) * EDGE_H_C + c];
    }
    g_pr[(size_t)n * EDGE_H_C + c] = __float2half(pr);
    g_pc[(size_t)n * EDGE_H_C + c] = __float2half(pc);
}

__global__ void ue_kernel(const float* __restrict__ e_w0, const float* __restrict__ e_b0) {
    int c = blockIdx.y * 256 + threadIdx.x;
    int g = blockIdx.x;
    float s = e_b0[c];
    #pragma unroll 4
    for (int j = 0; j < U_RED_C; j++)
        s += g_ur[g * U_RED_C + j] * e_w0[(size_t)(19 + j) * EDGE_H_C + c];
    g_ue[g * EDGE_H_C + c] = s;
}

__global__ void un_kernel(const float* __restrict__ n2_w0, const float* __restrict__ n2_b0) {
    int c = blockIdx.y * 256 + threadIdx.x;
    int g = blockIdx.x;
    float s = n2_b0[c];
    #pragma unroll 4
    for (int j = 0; j < U_RED_C; j++)
        s += g_ur[g * U_RED_C + j] * n2_w0[(size_t)(521 + j) * NODE_H_C + c];
    g_un[g * NODE_H_C + c] = s;
}

__global__ void addn_kernel(const float* __restrict__ x, const int* __restrict__ batch,
                            const float* __restrict__ n2_w0) {
    int c = blockIdx.x * 256 + threadIdx.x;
    int n = blockIdx.y;
    int g = batch[n];
    float s = g_un[g * NODE_H_C + c];
    #pragma unroll
    for (int j = 0; j < 9; j++)
        s += x[(size_t)n * 9 + j] * n2_w0[(size_t)j * NODE_H_C + c];
    g_addn[(size_t)n * NODE_H_C + c] = s;
}

// --------------- e_wf->n1 fusion precomputes --------------------------------------
// bb[c] = n1_b0[c] + sum_j e_bf[j] * n1_w0[9+j, c]
__global__ void bb_kernel(const float* __restrict__ e_bf, const float* __restrict__ n1_w0,
                          const float* __restrict__ n1_b0) {
    int c = blockIdx.x * 256 + threadIdx.x;
    float s = n1_b0[c];
    #pragma unroll 4
    for (int j = 0; j < EDGE_OUT_C; j++)
        s += e_bf[j] * n1_w0[(size_t)(9 + j) * NODE_H_C + c];
    g_bb[c] = s;
}
// PN1[n,c] = bb[c] + x[n,:9] @ n1_w0 rows 0-8
__global__ void pn1_kernel(const float* __restrict__ x, const float* __restrict__ n1_w0) {
    int c = blockIdx.x * 256 + threadIdx.x;
    int n = blockIdx.y;
    float s = g_bb[c];
    #pragma unroll
    for (int j = 0; j < 9; j++)
        s += x[(size_t)n * 9 + j] * n1_w0[(size_t)j * NODE_H_C + c];
    g_pn1[(size_t)n * NODE_H_C + c] = s;
}

// --------------- edge layer 0 via gather-add: h0 -> bufA --------------------------
__global__ void edge_l0_kernel(const float* __restrict__ ea, const int* __restrict__ ei,
                               const int* __restrict__ batch, const float* __restrict__ e_w0) {
    int e = blockIdx.x * 2 + (threadIdx.x >> 7);
    int t = threadIdx.x & 127;          // 128 threads x 8 cols = 1024
    int row = ei[e], col = ei[N_EDGES_C + e];
    int g = batch[row];
    float eav = ea[e];
    int c0 = t * 8;

    uint4 prv = *reinterpret_cast<const uint4*>(g_pr + (size_t)row * EDGE_H_C + c0);
    uint4 pcv = *reinterpret_cast<const uint4*>(g_pc + (size_t)col * EDGE_H_C + c0);
    const __half2* pr2 = reinterpret_cast<const __half2*>(&prv);
    const __half2* pc2 = reinterpret_cast<const __half2*>(&pcv);
    const float* wea = e_w0 + (size_t)18 * EDGE_H_C + c0;
    const float* ue  = g_ue + g * EDGE_H_C + c0;

    uint4 outv;
    __half2* o2 = reinterpret_cast<__half2*>(&outv);
    #pragma unroll
    for (int i = 0; i < 4; i++) {
        float2 fp = __half22float2(pr2[i]);
        float2 fc = __half22float2(pc2[i]);
        float f0 = fp.x + fc.x + eav * wea[2 * i]     + ue[2 * i];
        float f1 = fp.y + fc.y + eav * wea[2 * i + 1] + ue[2 * i + 1];
        f0 = fmaxf(f0, 0.f); f1 = fmaxf(f1, 0.f);
        o2[i] = __floats2half2_rn(f0, f1);
    }
    *reinterpret_cast<uint4*>(g_bufA + (size_t)e * EDGE_H_C + c0) = outv;
}

// ------------------------- fp16 tensor-core GEMM ---------------------------------
// C[M,N](fp16) = act(A[M,K](fp16,row) @ B[K,N](fp16,row) + bias)
// BMODE: 0 = column bias vector bias[c]
//        1 = per-row fp32 table bias[r*ldc + c]
//        2 = indexed table bias[bidx[r]*ldc + c]
#define BM 128
#define BN 256
#define BKK 32
#define GT 256
#define STG 3
#define A_ST (BM * 40)     // halves per A stage (pad 32->40)
#define B_ST (BKK * 264)   // halves per B stage (pad 256->264)
#define GEMM_SMEM (STG * (A_ST + B_ST) * 2)

template<bool RELU, int BMODE>
__global__ __launch_bounds__(GT, 1)
void gemm_kernel(const __half* __restrict__ A, int lda,
                 const __half* __restrict__ B, int ldb,
                 const float* __restrict__ bias,
                 const int* __restrict__ bidx,
                 __half* __restrict__ C, int ldc, int K) {
    extern __shared__ __half sm[];
    __half* Asm = sm;                    // [STG][128][40]
    __half* Bsm = sm + STG * A_ST;       // [STG][32][264]

    const int tid  = threadIdx.x;
    const int lane = tid & 31, warp = tid >> 5;
    const int wm = warp & 1;    // 2 warps along M -> 64 rows each
    const int wn = warp >> 1;   // 4 warps along N -> 64 cols each
    const int bm = blockIdx.y, bn = blockIdx.x;

    const __half* Ag = A + (size_t)bm * BM * lda;
    const __half* Bg = B + (size_t)bn * BN;

    float acc[4][8][4];
    #pragma unroll
    for (int i = 0; i < 4; i++)
        #pragma unroll
        for (int j = 0; j < 8; j++)
            #pragma unroll
            for (int k = 0; k < 4; k++) acc[i][j][k] = 0.f;

    const int KT = K / BKK;

    auto load = [&](int kt, int st) {
        __half* as = Asm + st * A_ST;
        __half* bs = Bsm + st * B_ST;
        #pragma unroll
        for (int i = 0; i < 2; i++) {
            int ch = tid + i * GT;               // 512 x 16B chunks for A
            int r = ch >> 2, cc = (ch & 3) << 3;
            cp16(smem_u32(as + r * 40 + cc), Ag + (size_t)r * lda + kt * BKK + cc);
        }
        #pragma unroll
        for (int i = 0; i < 4; i++) {
            int ch = tid + i * GT;               // 1024 x 16B chunks for B
            int r = ch >> 5, cc = (ch & 31) << 3;
            cp16(smem_u32(bs + r * 264 + cc), Bg + (size_t)(kt * BKK + r) * ldb + cc);
        }
        cp_commit();
    };

    load(0, 0);
    load(1, 1);

    for (int kt = 0; kt < KT; kt++) {
        cp_wait1();
        __syncthreads();
        const int st = kt % 3;
        if (kt + 2 < KT) load(kt + 2, (kt + 2) % 3);
        else             cp_commit();

        #pragma unroll
        for (int ks = 0; ks < 2; ks++) {
            uint32_t afr[4][4];
            {
                const __half* as = Asm + st * A_ST;
                int row = wm * 64 + (lane & 15);
                int col = ks * 16 + (lane >> 4) * 8;
                #pragma unroll
                for (int mi = 0; mi < 4; mi++)
                    ldm_x4(smem_u32(as + (row + mi * 16) * 40 + col),
                           afr[mi][0], afr[mi][1], afr[mi][2], afr[mi][3]);
            }
            uint32_t bfr[8][2];
            {
                const __half* bs = Bsm + st * B_ST;
                int row = ks * 16 + ((lane >> 3) & 1) * 8 + (lane & 7);
                #pragma unroll
                for (int p = 0; p < 4; p++) {
                    int col = wn * 64 + p * 16 + (lane >> 4) * 8;
                    uint32_t r0, r1, r2, r3;
                    ldm_x4t(smem_u32(bs + row * 264 + col), r0, r1, r2, r3);
                    bfr[2 * p][0] = r0;     bfr[2 * p][1] = r1;
                    bfr[2 * p + 1][0] = r2; bfr[2 * p + 1][1] = r3;
                }
            }
            #pragma unroll
            for (int mi = 0; mi < 4; mi++)
                #pragma unroll
                for (int nj = 0; nj < 8; nj++)
                    mma16816(acc[mi][nj], afr[mi], bfr[nj]);
        }
    }

    // epilogue
    int row0 = bm * BM + wm * 64;
    int col0 = bn * BN + wn * 64;
    #pragma unroll
    for (int mi = 0; mi < 4; mi++) {
        #pragma unroll
        for (int h = 0; h < 2; h++) {
            int r = row0 + mi * 16 + (lane >> 2) + h * 8;
            const float* tb = bias;
            if (BMODE == 1) tb = bias + (size_t)r * ldc;
            if (BMODE == 2) tb = bias + (size_t)bidx[r] * ldc;
            #pragma unroll
            for (int nj = 0; nj < 8; nj++) {
                int c = col0 + nj * 8 + (lane & 3) * 2;
                float b0 = tb[c], b1 = tb[c + 1];
                float f0 = acc[mi][nj][2 * h] + b0;
                float f1 = acc[mi][nj][2 * h + 1] + b1;
                if (RELU) { f0 = fmaxf(f0, 0.f); f1 = fmaxf(f1, 0.f); }
                *reinterpret_cast<__half2*>(C + (size_t)r * ldc + c) = __floats2half2_rn(f0, f1);
            }
        }
    }
}

// --------------- scatter-mean: CSR build + gather reduce -------------------------
__global__ void zero_cnt_kernel() {
    int i = blockIdx.x * blockDim.x + threadIdx.x;
    if (i < N_NODES_C) { g_cnt[i] = 0; g_cur[i] = 0; }
}
__global__ void count_kernel(const int* __restrict__ ei) {
    int e = blockIdx.x * blockDim.x + threadIdx.x;
    if (e < N_EDGES_C) atomicAdd(&g_cnt[ei[e]], 1);
}
__global__ void scan_kernel() {   // single block, 1024 threads x 16 elems
    __shared__ int ws[32];
    int t = threadIdx.x;
    int base = t * 16;
    int v[16]; int s = 0;
    #pragma unroll
    for (int i = 0; i < 16; i++) { v[i] = s; s += g_cnt[base + i]; }
    int lane = t & 31, w = t >> 5;
    int x = s;
    #pragma unroll
    for (int o = 1; o < 32; o <<= 1) { int y = __shfl_up_sync(~0u, x, o); if (lane >= o) x += y; }
    if (lane == 31) ws[w] = x;
    __syncthreads();
    if (w == 0) {
        int y = ws[lane];
        #pragma unroll
        for (int o = 1; o < 32; o <<= 1) { int z = __shfl_up_sync(~0u, y, o); if (lane >= o) y += z; }
        ws[lane] = y;
    }
    __syncthreads();
    int pre = (x - s) + (w > 0 ? ws[w - 1] : 0);
    #pragma unroll
    for (int i = 0; i < 16; i++) g_off[base + i] = pre + v[i];
    if (t == 1023) g_off[N_NODES_C] = pre + s;
}
__global__ void fill_kernel(const int* __restrict__ ei) {
    int e = blockIdx.x * blockDim.x + threadIdx.x;
    if (e < N_EDGES_C) {
        int r = ei[e];
        int p = g_off[r] + atomicAdd(&g_cur[r], 1);
        g_elist[p] = e;
    }
}
// block per node: mean over its edges of h_n (g_bufB [E,512] fp16) -> oin
__global__ void node_reduce_kernel() {
    int n = blockIdx.x;
    int t = threadIdx.x;  // 128
    int deg = g_cnt[n], start = g_off[n];
    float acc0 = 0.f, acc1 = 0.f, acc2 = 0.f, acc3 = 0.f;
    for (int i = 0; i < deg; i++) {
        int e = g_elist[start + i];
        const __half* hr = g_bufB + (size_t)e * NODE_H_C;
        acc0 += __half2float(hr[t]);
        acc1 += __half2float(hr[t + 128]);
        acc2 += __half2float(hr[t + 256]);
        acc3 += __half2float(hr[t + 384]);
    }
    float inv = 1.f / (float)(deg > 0 ? deg : 1);
    __half* dst = g_oin + (size_t)n * NODE_H_C;
    dst[t]       = __float2half(acc0 * inv);
    dst[t + 128] = __float2half(acc1 * inv);
    dst[t + 256] = __float2half(acc2 * inv);
    dst[t + 384] = __float2half(acc3 * inv);
}

// --------------- final dot: out[n] = h2[n,:] . n2_w1 + b --------------------------
__global__ void final_kernel(const float* __restrict__ w, const float* __restrict__ b,
                             float* __restrict__ out) {
    int n = blockIdx.x * 8 + (threadIdx.x >> 5);
    int lane = threadIdx.x & 31;
    const __half* h = g_h2 + (size_t)n * NODE_H_C;
    float s = 0.f;
    #pragma unroll
    for (int j = 0; j < 16; j++) {
        int c = lane + j * 32;
        s += __half2float(h[c]) * w[c];
    }
    #pragma unroll
    for (int o = 16; o > 0; o >>= 1) s += __shfl_xor_sync(~0u, s, o);
    if (lane == 0) out[n] = s + b[0];
}

// ------------------------- host launcher -----------------------------------------
extern "C" void kernel_launch(void* const* d_in, const int* in_sizes, int n_in,
                              void* d_out, int out_size) {
    (void)in_sizes; (void)n_in; (void)out_size;
    const float* x      = (const float*)d_in[0];
    const float* ea     = (const float*)d_in[1];
    const float* u      = (const float*)d_in[2];
    const int*   ei     = (const int*)d_in[3];
    const int*   batch  = (const int*)d_in[4];
    const float* w_dr   = (const float*)d_in[5];
    const float* b_dr   = (const float*)d_in[6];
    const float* e_w0   = (const float*)d_in[7];
    const float* e_b0   = (const float*)d_in[8];
    const float* e_w1   = (const float*)d_in[9];
    const float* e_b1   = (const float*)d_in[10];
    const float* e_w2   = (const float*)d_in[11];
    const float* e_b2   = (const float*)d_in[12];
    const float* e_w3   = (const float*)d_in[13];
    const float* e_b3   = (const float*)d_in[14];
    const float* e_wf   = (const float*)d_in[15];
    const float* e_bf   = (const float*)d_in[16];
    const float* n1_w0  = (const float*)d_in[17];
    const float* n1_b0  = (const float*)d_in[18];
    const float* n1_w1  = (const float*)d_in[19];
    const float* n1_b1  = (const float*)d_in[20];
    const float* n2_w0  = (const float*)d_in[21];
    const float* n2_b0  = (const float*)d_in[22];
    const float* n2_w1  = (const float*)d_in[23];
    const float* n2_b1  = (const float*)d_in[24];
    float* out = (float*)d_out;

    __half *w1h, *w2h, *w3h, *wfh, *n1w0h, *n1w1h, *n2w0h, *cw;
    __half *bufA, *bufB, *oin, *h2;
    float  *addn, *pn1, *zerov;
    cudaGetSymbolAddress((void**)&w1h,   g_w1h);
    cudaGetSymbolAddress((void**)&w2h,   g_w2h);
    cudaGetSymbolAddress((void**)&w3h,   g_w3h);
    cudaGetSymbolAddress((void**)&wfh,   g_wfh);
    cudaGetSymbolAddress((void**)&n1w0h, g_n1w0h);
    cudaGetSymbolAddress((void**)&n1w1h, g_n1w1h);
    cudaGetSymbolAddress((void**)&n2w0h, g_n2w0h);
    cudaGetSymbolAddress((void**)&cw,    g_cw);
    cudaGetSymbolAddress((void**)&bufA, g_bufA);
    cudaGetSymbolAddress((void**)&bufB, g_bufB);
    cudaGetSymbolAddress((void**)&oin,  g_oin);
    cudaGetSymbolAddress((void**)&h2,   g_h2);
    cudaGetSymbolAddress((void**)&addn, g_addn);
    cudaGetSymbolAddress((void**)&pn1,  g_pn1);
    cudaGetSymbolAddress((void**)&zerov, g_zero);

    cudaFuncSetAttribute((const void*)gemm_kernel<true,  0>, cudaFuncAttributeMaxDynamicSharedMemorySize, GEMM_SMEM);
    cudaFuncSetAttribute((const void*)gemm_kernel<false, 0>, cudaFuncAttributeMaxDynamicSharedMemorySize, GEMM_SMEM);
    cudaFuncSetAttribute((const void*)gemm_kernel<true,  1>, cudaFuncAttributeMaxDynamicSharedMemorySize, GEMM_SMEM);
    cudaFuncSetAttribute((const void*)gemm_kernel<true,  2>, cudaFuncAttributeMaxDynamicSharedMemorySize, GEMM_SMEM);

    const Seg Z{0, 0, 0};
    auto gsz = [](int n) { return (n + 255) / 256; };

    // pack weights fp32->fp16
    pack_weight<<<gsz(1024 * 1024), 256>>>(e_w1, w1h, 1024, 1024, Seg{0, 0, 1024}, Z, Z, Z);
    pack_weight<<<gsz(1024 * 1024), 256>>>(e_w2, w2h, 1024, 1024, Seg{0, 0, 1024}, Z, Z, Z);
    pack_weight<<<gsz(1024 * 1024), 256>>>(e_w3, w3h, 1024, 1024, Seg{0, 0, 1024}, Z, Z, Z);
    pack_weight<<<gsz(1024 * 512),  256>>>(e_wf, wfh, 512, 1024, Seg{0, 0, 1024}, Z, Z, Z);
    pack_weight<<<gsz(512 * 512),   256>>>(n1_w0, n1w0h, 512, 512, Seg{9, 0, 512}, Z, Z, Z);
    pack_weight<<<gsz(512 * 512),   256>>>(n1_w1, n1w1h, 512, 512, Seg{0, 0, 512}, Z, Z, Z);
    pack_weight<<<gsz(512 * 512),   256>>>(n2_w0, n2w0h, 512, 512, Seg{9, 0, 512}, Z, Z, Z);

    // u dim reduction + factorization tables
    dimred_kernel<<<dim3(16, 8), 256>>>(u, w_dr, b_dr);
    prexw_kernel<<<dim3(4, N_NODES_C), 256>>>(x, e_w0);
    ue_kernel<<<dim3(16, 4), 256>>>(e_w0, e_b0);
    un_kernel<<<dim3(16, 2), 256>>>(n2_w0, n2_b0);
    addn_kernel<<<dim3(2, N_NODES_C), 256>>>(x, batch, n2_w0);
    bb_kernel<<<2, 256>>>(e_bf, n1_w0, n1_b0);
    pn1_kernel<<<dim3(2, N_NODES_C), 256>>>(x, n1_w0);

    // composite weight CW = e_wf @ n1_w0[9:521]  (exact linear fusion, no relu between)
    gemm_kernel<false, 0><<<dim3(2, 8), GT, GEMM_SMEM>>>(wfh, 512, n1w0h, 512, zerov, nullptr, cw, 512, 512);

    // edge layer 0 via gather-add -> bufA
    edge_l0_kernel<<<N_EDGES_C / 2, 256>>>(ea, ei, batch, e_w0);

    const int MT = N_EDGES_C / BM;      // 1024
    const int MTN = N_NODES_C / BM;     // 128

    // edge MLP interior
    gemm_kernel<true, 0><<<dim3(4, MT), GT, GEMM_SMEM>>>(bufA, 1024, w1h, 1024, e_b1, nullptr, bufB, 1024, 1024);
    gemm_kernel<true, 0><<<dim3(4, MT), GT, GEMM_SMEM>>>(bufB, 1024, w2h, 1024, e_b2, nullptr, bufA, 1024, 1024);
    gemm_kernel<true, 0><<<dim3(4, MT), GT, GEMM_SMEM>>>(bufA, 1024, w3h, 1024, e_b3, nullptr, bufB, 1024, 1024);

    // fused (e_wf -> n1 layer0): h = relu(h3 @ CW + PN1[col[e]])
    gemm_kernel<true, 2><<<dim3(2, MT), GT, GEMM_SMEM>>>(bufB, 1024, cw, 512, pn1, ei + N_EDGES_C, bufA, 512, 1024);

    // n1 layer 1
    gemm_kernel<true, 0><<<dim3(2, MT), GT, GEMM_SMEM>>>(bufA, 512, n1w1h, 512, n1_b1, nullptr, bufB, 512, 512);

    // scatter-mean via CSR build
    zero_cnt_kernel<<<N_NODES_C / 256, 256>>>();
    count_kernel<<<N_EDGES_C / 256, 256>>>(ei);
    scan_kernel<<<1, 1024>>>();
    fill_kernel<<<N_EDGES_C / 256, 256>>>(ei);
    node_reduce_kernel<<<N_NODES_C, 128>>>();

    // node MLP 2 (K=512, row-bias table carries x/u_r/bias contributions) + final dot
    gemm_kernel<true, 1><<<dim3(2, MTN), GT, GEMM_SMEM>>>(oin, 512, n2w0h, 512, addn, nullptr, h2, 512, 512);
    final_kernel<<<N_NODES_C / 8, 256>>>(n2_w1, n2_b1, out);
}

// round 11
// speedup vs baseline: 1.1962x; 1.0312x over previous
#include <cuda_runtime.h>
#include <cuda_fp16.h>
#include <cstdint>

#define DI __device__ __forceinline__

// ------------------------- problem sizes -------------------------
#define N_NODES_C 16384
#define N_EDGES_C 131072
#define N_GRAPHS_C 16
#define U_SZ_C 4096
#define U_RED_C 256
#define EDGE_H_C 1024
#define EDGE_OUT_C 512
#define NODE_H_C 512

// ------------------------- device scratch -------------------------
__device__ __half g_bufA[(size_t)N_EDGES_C * EDGE_H_C];
__device__ __half g_bufB[(size_t)N_EDGES_C * EDGE_H_C];
__device__ __half g_oin [(size_t)N_NODES_C * NODE_H_C];
__device__ __half g_h2  [(size_t)N_NODES_C * NODE_H_C];
__device__ float  g_ur  [N_GRAPHS_C * U_RED_C];

// layer-0 small-K input: [x_row(9), x_col(9), ea(1), pad->32] + per-edge graph id
__device__ __half g_e19 [(size_t)(N_EDGES_C + 256) * 32];
__device__ int    g_gedge[N_EDGES_C];

// factorization tables
__device__ float  g_ue  [N_GRAPHS_C * EDGE_H_C];          // u_r @ W_u + e_b0   (edge l0 bias)
__device__ float  g_un  [N_GRAPHS_C * NODE_H_C];          // u_r @ W_u2 + n2_b0
__device__ float  g_addn[(size_t)N_NODES_C * NODE_H_C];   // row bias for n2 GEMM

// e_wf -> n1_w0 fusion tables
__device__ __half g_cw  [EDGE_H_C * NODE_H_C];            // e_wf @ n1_w0[9:521]
__device__ float  g_bb  [NODE_H_C];                        // n1_b0 + e_bf @ W_e
__device__ float  g_pn1 [(size_t)N_NODES_C * NODE_H_C];   // bb + x[n] @ W_x (per node)
__device__ float  g_zero[NODE_H_C];                        // stays 0 (module zero-init)

// weights packed [Kp, N] row-major fp16
__device__ __half g_w19h [32       * EDGE_H_C];   // e_w0 rows 0..18 (x_row,x_col,ea), zero pad
__device__ __half g_w1h  [EDGE_H_C * EDGE_H_C];
__device__ __half g_w2h  [EDGE_H_C * EDGE_H_C];
__device__ __half g_w3h  [EDGE_H_C * EDGE_H_C];
__device__ __half g_wfh  [EDGE_H_C * EDGE_OUT_C];
__device__ __half g_n1w0h[NODE_H_C * NODE_H_C];   // n1_w0 rows 9..520 (e-part)
__device__ __half g_n1w1h[NODE_H_C * NODE_H_C];
__device__ __half g_n2w0h[NODE_H_C * NODE_H_C];   // n2_w0 rows 9..520 (agg-part)

__device__ int g_cnt[N_NODES_C];
__device__ int g_off[N_NODES_C + 1];
__device__ int g_cur[N_NODES_C];
__device__ int g_elist[N_EDGES_C];

// ------------------------- small helpers -------------------------
DI uint32_t smem_u32(const void* p) {
    return (uint32_t)__cvta_generic_to_shared(p);
}
DI void cp16(uint32_t dst, const void* src) {
    asm volatile("cp.async.cg.shared.global [%0], [%1], 16;\n" :: "r"(dst), "l"(src));
}
DI void cp_commit() { asm volatile("cp.async.commit_group;\n"); }
DI void cp_wait1()  { asm volatile("cp.async.wait_group 1;\n"); }

DI void ldm_x4(uint32_t addr, uint32_t& r0, uint32_t& r1, uint32_t& r2, uint32_t& r3) {
    asm volatile("ldmatrix.sync.aligned.m8n8.x4.shared.b16 {%0,%1,%2,%3}, [%4];\n"
                 : "=r"(r0), "=r"(r1), "=r"(r2), "=r"(r3) : "r"(addr));
}
DI void ldm_x4t(uint32_t addr, uint32_t& r0, uint32_t& r1, uint32_t& r2, uint32_t& r3) {
    asm volatile("ldmatrix.sync.aligned.m8n8.x4.trans.shared.b16 {%0,%1,%2,%3}, [%4];\n"
                 : "=r"(r0), "=r"(r1), "=r"(r2), "=r"(r3) : "r"(addr));
}
DI void mma16816(float* d, const uint32_t* a, const uint32_t* b) {
    asm volatile("mma.sync.aligned.m16n8k16.row.col.f32.f16.f16.f32 "
                 "{%0,%1,%2,%3}, {%4,%5,%6,%7}, {%8,%9}, {%0,%1,%2,%3};\n"
                 : "+f"(d[0]), "+f"(d[1]), "+f"(d[2]), "+f"(d[3])
                 : "r"(a[0]), "r"(a[1]), "r"(a[2]), "r"(a[3]),
                   "r"(b[0]), "r"(b[1]));
}

// --------------- weight pack: fp32 -> fp16, row permute + zero pad ---------------
struct Seg { int src0, dst0, n; };

__global__ void pack_weight(const float* __restrict__ src, __half* __restrict__ dst,
                            int N, int Kp, Seg a, Seg b, Seg c, Seg d) {
    int idx = blockIdx.x * blockDim.x + threadIdx.x;
    if (idx >= Kp * N) return;
    int r = idx / N, col = idx - r * N;
    float v = 0.f;
    if      (r >= a.dst0 && r < a.dst0 + a.n) v = src[(size_t)(a.src0 + r - a.dst0) * N + col];
    else if (r >= b.dst0 && r < b.dst0 + b.n) v = src[(size_t)(b.src0 + r - b.dst0) * N + col];
    else if (r >= c.dst0 && r < c.dst0 + c.n) v = src[(size_t)(c.src0 + r - c.dst0) * N + col];
    else if (r >= d.dst0 && r < d.dst0 + d.n) v = src[(size_t)(d.src0 + r - d.dst0) * N + col];
    dst[idx] = __float2half(v);
}

// --------------- dim reduction: u_r = u @ w_dr + b_dr (fp32, tiny) ---------------
__global__ void dimred_kernel(const float* __restrict__ u, const float* __restrict__ w,
                              const float* __restrict__ b) {
    __shared__ float red[8][32];
    int g = blockIdx.x, ct = blockIdx.y;
    int kg = threadIdx.x >> 5, cl = threadIdx.x & 31;
    int c = ct * 32 + cl;
    const float* up = u + (size_t)g * U_SZ_C + kg * 512;
    const float* wp = w + (size_t)(kg * 512) * U_RED_C + c;
    float s = 0.f;
    #pragma unroll 8
    for (int k = 0; k < 512; k++) s += up[k] * wp[(size_t)k * U_RED_C];
    red[kg][cl] = s;
    __syncthreads();
    if (kg == 0) {
        float t = b[c];
        #pragma unroll
        for (int i = 0; i < 8; i++) t += red[i][cl];
        g_ur[g * U_RED_C + c] = t;
    }
}

// --------------- bias-table precomputes -------------------------------------------
// Ue[g,c] = sum_j ur[g,j] * e_w0[19+j, c] + e_b0[c]
__global__ void ue_kernel(const float* __restrict__ e_w0, const float* __restrict__ e_b0) {
    int c = blockIdx.y * 256 + threadIdx.x;
    int g = blockIdx.x;
    float s = e_b0[c];
    #pragma unroll 4
    for (int j = 0; j < U_RED_C; j++)
        s += g_ur[g * U_RED_C + j] * e_w0[(size_t)(19 + j) * EDGE_H_C + c];
    g_ue[g * EDGE_H_C + c] = s;
}

__global__ void un_kernel(const float* __restrict__ n2_w0, const float* __restrict__ n2_b0) {
    int c = blockIdx.y * 256 + threadIdx.x;
    int g = blockIdx.x;
    float s = n2_b0[c];
    #pragma unroll 4
    for (int j = 0; j < U_RED_C; j++)
        s += g_ur[g * U_RED_C + j] * n2_w0[(size_t)(521 + j) * NODE_H_C + c];
    g_un[g * NODE_H_C + c] = s;
}

__global__ void addn_kernel(const float* __restrict__ x, const int* __restrict__ batch,
                            const float* __restrict__ n2_w0) {
    int c = blockIdx.x * 256 + threadIdx.x;
    int n = blockIdx.y;
    int g = batch[n];
    float s = g_un[g * NODE_H_C + c];
    #pragma unroll
    for (int j = 0; j < 9; j++)
        s += x[(size_t)n * 9 + j] * n2_w0[(size_t)j * NODE_H_C + c];
    g_addn[(size_t)n * NODE_H_C + c] = s;
}

// bb[c] = n1_b0[c] + sum_j e_bf[j] * n1_w0[9+j, c]
__global__ void bb_kernel(const float* __restrict__ e_bf, const float* __restrict__ n1_w0,
                          const float* __restrict__ n1_b0) {
    int c = blockIdx.x * 256 + threadIdx.x;
    float s = n1_b0[c];
    #pragma unroll 4
    for (int j = 0; j < EDGE_OUT_C; j++)
        s += e_bf[j] * n1_w0[(size_t)(9 + j) * NODE_H_C + c];
    g_bb[c] = s;
}
// PN1[n,c] = bb[c] + x[n,:9] @ n1_w0 rows 0-8
__global__ void pn1_kernel(const float* __restrict__ x, const float* __restrict__ n1_w0) {
    int c = blockIdx.x * 256 + threadIdx.x;
    int n = blockIdx.y;
    float s = g_bb[c];
    #pragma unroll
    for (int j = 0; j < 9; j++)
        s += x[(size_t)n * 9 + j] * n1_w0[(size_t)j * NODE_H_C + c];
    g_pn1[(size_t)n * NODE_H_C + c] = s;
}

// --------------- build e19: [x_row, x_col, ea, pad] fp16 + per-edge graph id ------
__global__ void build_e19_kernel(const float* __restrict__ x, const float* __restrict__ ea,
                                 const int* __restrict__ ei, const int* __restrict__ batch) {
    int e = blockIdx.x * 8 + (threadIdx.x >> 5);
    int lane = threadIdx.x & 31;
    int r = ei[e], c = ei[N_EDGES_C + e];
    float v = 0.f;
    if (lane < 9)        v = x[(size_t)r * 9 + lane];
    else if (lane < 18)  v = x[(size_t)c * 9 + (lane - 9)];
    else if (lane == 18) v = ea[e];
    g_e19[(size_t)e * 32 + lane] = __float2half(v);
    if (lane == 0) g_gedge[e] = batch[r];
}

// ------------------------- fp16 tensor-core GEMM ---------------------------------
// C[M,N](fp16) = act(A[M,K](fp16,row) @ B[K,N](fp16,row) + bias)
// BMODE: 0 = column bias vector bias[c]
//        1 = per-row fp32 table bias[r*ldc + c]
//        2 = indexed table bias[bidx[r]*ldc + c]
#define BM 128
#define BN 256
#define BKK 32
#define GT 256
#define STG 3
#define A_ST (BM * 40)     // halves per A stage (pad 32->40)
#define B_ST (BKK * 264)   // halves per B stage (pad 256->264)
#define GEMM_SMEM (STG * (A_ST + B_ST) * 2)

template<bool RELU, int BMODE>
__global__ __launch_bounds__(GT, 1)
void gemm_kernel(const __half* __restrict__ A, int lda,
                 const __half* __restrict__ B, int ldb,
                 const float* __restrict__ bias,
                 const int* __restrict__ bidx,
                 __half* __restrict__ C, int ldc, int K) {
    extern __shared__ __half sm[];
    __half* Asm = sm;                    // [STG][128][40]
    __half* Bsm = sm + STG * A_ST;       // [STG][32][264]

    const int tid  = threadIdx.x;
    const int lane = tid & 31, warp = tid >> 5;
    const int wm = warp & 1;    // 2 warps along M -> 64 rows each
    const int wn = warp >> 1;   // 4 warps along N -> 64 cols each
    const int bm = blockIdx.y, bn = blockIdx.x;

    const __half* Ag = A + (size_t)bm * BM * lda;
    const __half* Bg = B + (size_t)bn * BN;

    float acc[4][8][4];
    #pragma unroll
    for (int i = 0; i < 4; i++)
        #pragma unroll
        for (int j = 0; j < 8; j++)
            #pragma unroll
            for (int k = 0; k < 4; k++) acc[i][j][k] = 0.f;

    const int KT = K / BKK;

    auto load = [&](int kt, int st) {
        __half* as = Asm + st * A_ST;
        __half* bs = Bsm + st * B_ST;
        #pragma unroll
        for (int i = 0; i < 2; i++) {
            int ch = tid + i * GT;               // 512 x 16B chunks for A
            int r = ch >> 2, cc = (ch & 3) << 3;
            cp16(smem_u32(as + r * 40 + cc), Ag + (size_t)r * lda + kt * BKK + cc);
        }
        #pragma unroll
        for (int i = 0; i < 4; i++) {
            int ch = tid + i * GT;               // 1024 x 16B chunks for B
            int r = ch >> 5, cc = (ch & 31) << 3;
            cp16(smem_u32(bs + r * 264 + cc), Bg + (size_t)(kt * BKK + r) * ldb + cc);
        }
        cp_commit();
    };

    load(0, 0);
    load(KT > 1 ? 1 : 0, 1);   // clamp: KT==1 re-loads kt=0 into unused stage

    for (int kt = 0; kt < KT; kt++) {
        cp_wait1();
        __syncthreads();
        const int st = kt % 3;
        if (kt + 2 < KT) load(kt + 2, (kt + 2) % 3);
        else             cp_commit();

        #pragma unroll
        for (int ks = 0; ks < 2; ks++) {
            uint32_t afr[4][4];
            {
                const __half* as = Asm + st * A_ST;
                int row = wm * 64 + (lane & 15);
                int col = ks * 16 + (lane >> 4) * 8;
                #pragma unroll
                for (int mi = 0; mi < 4; mi++)
                    ldm_x4(smem_u32(as + (row + mi * 16) * 40 + col),
                           afr[mi][0], afr[mi][1], afr[mi][2], afr[mi][3]);
            }
            uint32_t bfr[8][2];
            {
                const __half* bs = Bsm + st * B_ST;
                int row = ks * 16 + ((lane >> 3) & 1) * 8 + (lane & 7);
                #pragma unroll
                for (int p = 0; p < 4; p++) {
                    int col = wn * 64 + p * 16 + (lane >> 4) * 8;
                    uint32_t r0, r1, r2, r3;
                    ldm_x4t(smem_u32(bs + row * 264 + col), r0, r1, r2, r3);
                    bfr[2 * p][0] = r0;     bfr[2 * p][1] = r1;
                    bfr[2 * p + 1][0] = r2; bfr[2 * p + 1][1] = r3;
                }
            }
            #pragma unroll
            for (int mi = 0; mi < 4; mi++)
                #pragma unroll
                for (int nj = 0; nj < 8; nj++)
                    mma16816(acc[mi][nj], afr[mi], bfr[nj]);
        }
    }

    // epilogue
    int row0 = bm * BM + wm * 64;
    int col0 = bn * BN + wn * 64;
    #pragma unroll
    for (int mi = 0; mi < 4; mi++) {
        #pragma unroll
        for (int h = 0; h < 2; h++) {
            int r = row0 + mi * 16 + (lane >> 2) + h * 8;
            const float* tb = bias;
            if (BMODE == 1) tb = bias + (size_t)r * ldc;
            if (BMODE == 2) tb = bias + (size_t)bidx[r] * ldc;
            #pragma unroll
            for (int nj = 0; nj < 8; nj++) {
                int c = col0 + nj * 8 + (lane & 3) * 2;
                float b0 = tb[c], b1 = tb[c + 1];
                float f0 = acc[mi][nj][2 * h] + b0;
                float f1 = acc[mi][nj][2 * h + 1] + b1;
                if (RELU) { f0 = fmaxf(f0, 0.f); f1 = fmaxf(f1, 0.f); }
                *reinterpret_cast<__half2*>(C + (size_t)r * ldc + c) = __floats2half2_rn(f0, f1);
            }
        }
    }
}

// --------------- scatter-mean: CSR build + gather reduce -------------------------
__global__ void zero_cnt_kernel() {
    int i = blockIdx.x * blockDim.x + threadIdx.x;
    if (i < N_NODES_C) { g_cnt[i] = 0; g_cur[i] = 0; }
}
__global__ void count_kernel(const int* __restrict__ ei) {
    int e = blockIdx.x * blockDim.x + threadIdx.x;
    if (e < N_EDGES_C) atomicAdd(&g_cnt[ei[e]], 1);
}
__global__ void scan_kernel() {   // single block, 1024 threads x 16 elems
    __shared__ int ws[32];
    int t = threadIdx.x;
    int base = t * 16;
    int v[16]; int s = 0;
    #pragma unroll
    for (int i = 0; i < 16; i++) { v[i] = s; s += g_cnt[base + i]; }
    int lane = t & 31, w = t >> 5;
    int x = s;
    #pragma unroll
    for (int o = 1; o < 32; o <<= 1) { int y = __shfl_up_sync(~0u, x, o); if (lane >= o) x += y; }
    if (lane == 31) ws[w] = x;
    __syncthreads();
    if (w == 0) {
        int y = ws[lane];
        #pragma unroll
        for (int o = 1; o < 32; o <<= 1) { int z = __shfl_up_sync(~0u, y, o); if (lane >= o) y += z; }
        ws[lane] = y;
    }
    __syncthreads();
    int pre = (x - s) + (w > 0 ? ws[w - 1] : 0);
    #pragma unroll
    for (int i = 0; i < 16; i++) g_off[base + i] = pre + v[i];
    if (t == 1023) g_off[N_NODES_C] = pre + s;
}
__global__ void fill_kernel(const int* __restrict__ ei) {
    int e = blockIdx.x * blockDim.x + threadIdx.x;
    if (e < N_EDGES_C) {
        int r = ei[e];
        int p = g_off[r] + atomicAdd(&g_cur[r], 1);
        g_elist[p] = e;
    }
}
// block per node: mean over its edges of h_n (g_bufB [E,512] fp16) -> oin
__global__ void node_reduce_kernel() {
    int n = blockIdx.x;
    int t = threadIdx.x;  // 128
    int deg = g_cnt[n], start = g_off[n];
    float acc0 = 0.f, acc1 = 0.f, acc2 = 0.f, acc3 = 0.f;
    for (int i = 0; i < deg; i++) {
        int e = g_elist[start + i];
        const __half* hr = g_bufB + (size_t)e * NODE_H_C;
        acc0 += __half2float(hr[t]);
        acc1 += __half2float(hr[t + 128]);
        acc2 += __half2float(hr[t + 256]);
        acc3 += __half2float(hr[t + 384]);
    }
    float inv = 1.f / (float)(deg > 0 ? deg : 1);
    __half* dst = g_oin + (size_t)n * NODE_H_C;
    dst[t]       = __float2half(acc0 * inv);
    dst[t + 128] = __float2half(acc1 * inv);
    dst[t + 256] = __float2half(acc2 * inv);
    dst[t + 384] = __float2half(acc3 * inv);
}

// --------------- final dot: out[n] = h2[n,:] . n2_w1 + b --------------------------
__global__ void final_kernel(const float* __restrict__ w, const float* __restrict__ b,
                             float* __restrict__ out) {
    int n = blockIdx.x * 8 + (threadIdx.x >> 5);
    int lane = threadIdx.x & 31;
    const __half* h = g_h2 + (size_t)n * NODE_H_C;
    float s = 0.f;
    #pragma unroll
    for (int j = 0; j < 16; j++) {
        int c = lane + j * 32;
        s += __half2float(h[c]) * w[c];
    }
    #pragma unroll
    for (int o = 16; o > 0; o >>= 1) s += __shfl_xor_sync(~0u, s, o);
    if (lane == 0) out[n] = s + b[0];
}

// ------------------------- host launcher -----------------------------------------
extern "C" void kernel_launch(void* const* d_in, const int* in_sizes, int n_in,
                              void* d_out, int out_size) {
    (void)in_sizes; (void)n_in; (void)out_size;
    const float* x      = (const float*)d_in[0];
    const float* ea     = (const float*)d_in[1];
    const float* u      = (const float*)d_in[2];
    const int*   ei     = (const int*)d_in[3];
    const int*   batch  = (const int*)d_in[4];
    const float* w_dr   = (const float*)d_in[5];
    const float* b_dr   = (const float*)d_in[6];
    const float* e_w0   = (const float*)d_in[7];
    const float* e_b0   = (const float*)d_in[8];
    const float* e_w1   = (const float*)d_in[9];
    const float* e_b1   = (const float*)d_in[10];
    const float* e_w2   = (const float*)d_in[11];
    const float* e_b2   = (const float*)d_in[12];
    const float* e_w3   = (const float*)d_in[13];
    const float* e_b3   = (const float*)d_in[14];
    const float* e_wf   = (const float*)d_in[15];
    const float* e_bf   = (const float*)d_in[16];
    const float* n1_w0  = (const float*)d_in[17];
    const float* n1_b0  = (const float*)d_in[18];
    const float* n1_w1  = (const float*)d_in[19];
    const float* n1_b1  = (const float*)d_in[20];
    const float* n2_w0  = (const float*)d_in[21];
    const float* n2_b0  = (const float*)d_in[22];
    const float* n2_w1  = (const float*)d_in[23];
    const float* n2_b1  = (const float*)d_in[24];
    float* out = (float*)d_out;

    __half *w19h, *w1h, *w2h, *w3h, *wfh, *n1w0h, *n1w1h, *n2w0h, *cw;
    __half *bufA, *bufB, *oin, *h2, *e19;
    float  *addn, *pn1, *zerov, *uef;
    int    *gedge;
    cudaGetSymbolAddress((void**)&w19h,  g_w19h);
    cudaGetSymbolAddress((void**)&w1h,   g_w1h);
    cudaGetSymbolAddress((void**)&w2h,   g_w2h);
    cudaGetSymbolAddress((void**)&w3h,   g_w3h);
    cudaGetSymbolAddress((void**)&wfh,   g_wfh);
    cudaGetSymbolAddress((void**)&n1w0h, g_n1w0h);
    cudaGetSymbolAddress((void**)&n1w1h, g_n1w1h);
    cudaGetSymbolAddress((void**)&n2w0h, g_n2w0h);
    cudaGetSymbolAddress((void**)&cw,    g_cw);
    cudaGetSymbolAddress((void**)&bufA, g_bufA);
    cudaGetSymbolAddress((void**)&bufB, g_bufB);
    cudaGetSymbolAddress((void**)&oin,  g_oin);
    cudaGetSymbolAddress((void**)&h2,   g_h2);
    cudaGetSymbolAddress((void**)&e19,  g_e19);
    cudaGetSymbolAddress((void**)&addn, g_addn);
    cudaGetSymbolAddress((void**)&pn1,  g_pn1);
    cudaGetSymbolAddress((void**)&zerov, g_zero);
    cudaGetSymbolAddress((void**)&uef,  g_ue);
    cudaGetSymbolAddress((void**)&gedge, g_gedge);

    cudaFuncSetAttribute((const void*)gemm_kernel<true,  0>, cudaFuncAttributeMaxDynamicSharedMemorySize, GEMM_SMEM);
    cudaFuncSetAttribute((const void*)gemm_kernel<false, 0>, cudaFuncAttributeMaxDynamicSharedMemorySize, GEMM_SMEM);
    cudaFuncSetAttribute((const void*)gemm_kernel<true,  1>, cudaFuncAttributeMaxDynamicSharedMemorySize, GEMM_SMEM);
    cudaFuncSetAttribute((const void*)gemm_kernel<true,  2>, cudaFuncAttributeMaxDynamicSharedMemorySize, GEMM_SMEM);

    const Seg Z{0, 0, 0};
    auto gsz = [](int n) { return (n + 255) / 256; };

    // pack weights fp32->fp16
    pack_weight<<<gsz(32 * 1024),   256>>>(e_w0, w19h, 1024, 32, Seg{0, 0, 19}, Z, Z, Z);
    pack_weight<<<gsz(1024 * 1024), 256>>>(e_w1, w1h, 1024, 1024, Seg{0, 0, 1024}, Z, Z, Z);
    pack_weight<<<gsz(1024 * 1024), 256>>>(e_w2, w2h, 1024, 1024, Seg{0, 0, 1024}, Z, Z, Z);
    pack_weight<<<gsz(1024 * 1024), 256>>>(e_w3, w3h, 1024, 1024, Seg{0, 0, 1024}, Z, Z, Z);
    pack_weight<<<gsz(1024 * 512),  256>>>(e_wf, wfh, 512, 1024, Seg{0, 0, 1024}, Z, Z, Z);
    pack_weight<<<gsz(512 * 512),   256>>>(n1_w0, n1w0h, 512, 512, Seg{9, 0, 512}, Z, Z, Z);
    pack_weight<<<gsz(512 * 512),   256>>>(n1_w1, n1w1h, 512, 512, Seg{0, 0, 512}, Z, Z, Z);
    pack_weight<<<gsz(512 * 512),   256>>>(n2_w0, n2w0h, 512, 512, Seg{9, 0, 512}, Z, Z, Z);

    // u dim reduction + bias tables
    dimred_kernel<<<dim3(16, 8), 256>>>(u, w_dr, b_dr);
    ue_kernel<<<dim3(16, 4), 256>>>(e_w0, e_b0);
    un_kernel<<<dim3(16, 2), 256>>>(n2_w0, n2_b0);
    addn_kernel<<<dim3(2, N_NODES_C), 256>>>(x, batch, n2_w0);
    bb_kernel<<<2, 256>>>(e_bf, n1_w0, n1_b0);
    pn1_kernel<<<dim3(2, N_NODES_C), 256>>>(x, n1_w0);

    // composite weight CW = e_wf @ n1_w0[9:521]  (exact linear fusion, no relu between)
    gemm_kernel<false, 0><<<dim3(2, 8), GT, GEMM_SMEM>>>(wfh, 512, n1w0h, 512, zerov, nullptr, cw, 512, 512);

    // layer-0 small-K input build
    build_e19_kernel<<<N_EDGES_C / 8, 256>>>(x, ea, ei, batch);

    const int MT = N_EDGES_C / BM;      // 1024
    const int MTN = N_NODES_C / BM;     // 128

    // edge MLP: layer 0 as K=32 GEMM with indexed Ue bias, then interior layers
    gemm_kernel<true, 2><<<dim3(4, MT), GT, GEMM_SMEM>>>(e19, 32, w19h, 1024, uef, gedge, bufA, 1024, 32);
    gemm_kernel<true, 0><<<dim3(4, MT), GT, GEMM_SMEM>>>(bufA, 1024, w1h, 1024, e_b1, nullptr, bufB, 1024, 1024);
    gemm_kernel<true, 0><<<dim3(4, MT), GT, GEMM_SMEM>>>(bufB, 1024, w2h, 1024, e_b2, nullptr, bufA, 1024, 1024);
    gemm_kernel<true, 0><<<dim3(4, MT), GT, GEMM_SMEM>>>(bufA, 1024, w3h, 1024, e_b3, nullptr, bufB, 1024, 1024);

    // fused (e_wf -> n1 layer0): h = relu(h3 @ CW + PN1[col[e]])
    gemm_kernel<true, 2><<<dim3(2, MT), GT, GEMM_SMEM>>>(bufB, 1024, cw, 512, pn1, ei + N_EDGES_C, bufA, 512, 1024);

    // n1 layer 1
    gemm_kernel<true, 0><<<dim3(2, MT), GT, GEMM_SMEM>>>(bufA, 512, n1w1h, 512, n1_b1, nullptr, bufB, 512, 512);

    // scatter-mean via CSR build
    zero_cnt_kernel<<<N_NODES_C / 256, 256>>>();
    count_kernel<<<N_EDGES_C / 256, 256>>>(ei);
    scan_kernel<<<1, 1024>>>();
    fill_kernel<<<N_EDGES_C / 256, 256>>>(ei);
    node_reduce_kernel<<<N_NODES_C, 128>>>();

    // node MLP 2 (K=512, row-bias table carries x/u_r/bias contributions) + final dot
    gemm_kernel<true, 1><<<dim3(2, MTN), GT, GEMM_SMEM>>>(oin, 512, n2w0h, 512, addn, nullptr, h2, 512, 512);
    final_kernel<<<N_NODES_C / 8, 256>>>(n2_w1, n2_b1, out);
}

// round 12
// speedup vs baseline: 1.1997x; 1.0029x over previous
#include <cuda_runtime.h>
#include <cuda_fp16.h>
#include <cstdint>

#define DI __device__ __forceinline__

// ------------------------- problem sizes -------------------------
#define N_NODES_C 16384
#define N_EDGES_C 131072
#define N_GRAPHS_C 16
#define U_SZ_C 4096
#define U_RED_C 256
#define EDGE_H_C 1024
#define EDGE_OUT_C 512
#define NODE_H_C 512

// ------------------------- device scratch -------------------------
__device__ __half g_bufA[(size_t)N_EDGES_C * EDGE_H_C];
__device__ __half g_bufB[(size_t)N_EDGES_C * EDGE_H_C];
__device__ __half g_oin [(size_t)N_NODES_C * NODE_H_C];
__device__ __half g_h2  [(size_t)N_NODES_C * NODE_H_C];
__device__ float  g_ur  [N_GRAPHS_C * U_RED_C];

// layer-0 small-K input: [x_row(9), x_col(9), ea(1), pad->32] + per-edge graph id
__device__ __half g_e19 [(size_t)(N_EDGES_C + 256) * 32];
__device__ int    g_gedge[N_EDGES_C];

// factorization tables
__device__ float  g_ue  [N_GRAPHS_C * EDGE_H_C];          // u_r @ W_u + e_b0   (edge l0 bias)
__device__ float  g_un  [N_GRAPHS_C * NODE_H_C];          // u_r @ W_u2 + n2_b0
__device__ float  g_addn[(size_t)N_NODES_C * NODE_H_C];   // row bias for n2 GEMM

// e_wf -> n1_w0 fusion tables
__device__ __half g_cw  [EDGE_H_C * NODE_H_C];            // e_wf @ n1_w0[9:521]
__device__ float  g_bb  [NODE_H_C];                        // n1_b0 + e_bf @ W_e
__device__ float  g_pn1 [(size_t)N_NODES_C * NODE_H_C];   // bb + x[n] @ W_x (per node)
__device__ float  g_zero[NODE_H_C];                        // stays 0 (module zero-init)

// weights packed [Kp, N] row-major fp16
__device__ __half g_w19h [32       * EDGE_H_C];   // e_w0 rows 0..18 (x_row,x_col,ea), zero pad
__device__ __half g_w1h  [EDGE_H_C * EDGE_H_C];
__device__ __half g_w2h  [EDGE_H_C * EDGE_H_C];
__device__ __half g_w3h  [EDGE_H_C * EDGE_H_C];
__device__ __half g_wfh  [EDGE_H_C * EDGE_OUT_C];
__device__ __half g_n1w0h[NODE_H_C * NODE_H_C];   // n1_w0 rows 9..520 (e-part)
__device__ __half g_n1w1h[NODE_H_C * NODE_H_C];
__device__ __half g_n2w0h[NODE_H_C * NODE_H_C];   // n2_w0 rows 9..520 (agg-part)

__device__ int g_cnt[N_NODES_C];
__device__ int g_off[N_NODES_C + 1];
__device__ int g_cur[N_NODES_C];
__device__ int g_elist[N_EDGES_C];

// ------------------------- small helpers -------------------------
DI uint32_t smem_u32(const void* p) {
    return (uint32_t)__cvta_generic_to_shared(p);
}
DI void cp16(uint32_t dst, const void* src) {
    asm volatile("cp.async.cg.shared.global [%0], [%1], 16;\n" :: "r"(dst), "l"(src));
}
DI void cp_commit() { asm volatile("cp.async.commit_group;\n"); }
DI void cp_wait1()  { asm volatile("cp.async.wait_group 1;\n"); }

DI void ldm_x4(uint32_t addr, uint32_t& r0, uint32_t& r1, uint32_t& r2, uint32_t& r3) {
    asm volatile("ldmatrix.sync.aligned.m8n8.x4.shared.b16 {%0,%1,%2,%3}, [%4];\n"
                 : "=r"(r0), "=r"(r1), "=r"(r2), "=r"(r3) : "r"(addr));
}
DI void ldm_x4t(uint32_t addr, uint32_t& r0, uint32_t& r1, uint32_t& r2, uint32_t& r3) {
    asm volatile("ldmatrix.sync.aligned.m8n8.x4.trans.shared.b16 {%0,%1,%2,%3}, [%4];\n"
                 : "=r"(r0), "=r"(r1), "=r"(r2), "=r"(r3) : "r"(addr));
}
DI void mma16816(float* d, const uint32_t* a, const uint32_t* b) {
    asm volatile("mma.sync.aligned.m16n8k16.row.col.f32.f16.f16.f32 "
                 "{%0,%1,%2,%3}, {%4,%5,%6,%7}, {%8,%9}, {%0,%1,%2,%3};\n"
                 : "+f"(d[0]), "+f"(d[1]), "+f"(d[2]), "+f"(d[3])
                 : "r"(a[0]), "r"(a[1]), "r"(a[2]), "r"(a[3]),
                   "r"(b[0]), "r"(b[1]));
}

// --------------- weight pack: fp32 -> fp16, row permute + zero pad ---------------
struct Seg { int src0, dst0, n; };

__global__ void pack_weight(const float* __restrict__ src, __half* __restrict__ dst,
                            int N, int Kp, Seg a, Seg b, Seg c, Seg d) {
    int idx = blockIdx.x * blockDim.x + threadIdx.x;
    if (idx >= Kp * N) return;
    int r = idx / N, col = idx - r * N;
    float v = 0.f;
    if      (r >= a.dst0 && r < a.dst0 + a.n) v = src[(size_t)(a.src0 + r - a.dst0) * N + col];
    else if (r >= b.dst0 && r < b.dst0 + b.n) v = src[(size_t)(b.src0 + r - b.dst0) * N + col];
    else if (r >= c.dst0 && r < c.dst0 + c.n) v = src[(size_t)(c.src0 + r - c.dst0) * N + col];
    else if (r >= d.dst0 && r < d.dst0 + d.n) v = src[(size_t)(d.src0 + r - d.dst0) * N + col];
    dst[idx] = __float2half(v);
}

// --------------- dim reduction: u_r = u @ w_dr + b_dr (fp32, tiny) ---------------
__global__ void dimred_kernel(const float* __restrict__ u, const float* __restrict__ w,
                              const float* __restrict__ b) {
    __shared__ float red[8][32];
    int g = blockIdx.x, ct = blockIdx.y;
    int kg = threadIdx.x >> 5, cl = threadIdx.x & 31;
    int c = ct * 32 + cl;
    const float* up = u + (size_t)g * U_SZ_C + kg * 512;
    const float* wp = w + (size_t)(kg * 512) * U_RED_C + c;
    float s = 0.f;
    #pragma unroll 8
    for (int k = 0; k < 512; k++) s += up[k] * wp[(size_t)k * U_RED_C];
    red[kg][cl] = s;
    __syncthreads();
    if (kg == 0) {
        float t = b[c];
        #pragma unroll
        for (int i = 0; i < 8; i++) t += red[i][cl];
        g_ur[g * U_RED_C + c] = t;
    }
}

// --------------- bias-table precomputes -------------------------------------------
__global__ void ue_kernel(const float* __restrict__ e_w0, const float* __restrict__ e_b0) {
    int c = blockIdx.y * 256 + threadIdx.x;
    int g = blockIdx.x;
    float s = e_b0[c];
    #pragma unroll 4
    for (int j = 0; j < U_RED_C; j++)
        s += g_ur[g * U_RED_C + j] * e_w0[(size_t)(19 + j) * EDGE_H_C + c];
    g_ue[g * EDGE_H_C + c] = s;
}

__global__ void un_kernel(const float* __restrict__ n2_w0, const float* __restrict__ n2_b0) {
    int c = blockIdx.y * 256 + threadIdx.x;
    int g = blockIdx.x;
    float s = n2_b0[c];
    #pragma unroll 4
    for (int j = 0; j < U_RED_C; j++)
        s += g_ur[g * U_RED_C + j] * n2_w0[(size_t)(521 + j) * NODE_H_C + c];
    g_un[g * NODE_H_C + c] = s;
}

__global__ void addn_kernel(const float* __restrict__ x, const int* __restrict__ batch,
                            const float* __restrict__ n2_w0) {
    int c = blockIdx.x * 256 + threadIdx.x;
    int n = blockIdx.y;
    int g = batch[n];
    float s = g_un[g * NODE_H_C + c];
    #pragma unroll
    for (int j = 0; j < 9; j++)
        s += x[(size_t)n * 9 + j] * n2_w0[(size_t)j * NODE_H_C + c];
    g_addn[(size_t)n * NODE_H_C + c] = s;
}

__global__ void bb_kernel(const float* __restrict__ e_bf, const float* __restrict__ n1_w0,
                          const float* __restrict__ n1_b0) {
    int c = blockIdx.x * 256 + threadIdx.x;
    float s = n1_b0[c];
    #pragma unroll 4
    for (int j = 0; j < EDGE_OUT_C; j++)
        s += e_bf[j] * n1_w0[(size_t)(9 + j) * NODE_H_C + c];
    g_bb[c] = s;
}
__global__ void pn1_kernel(const float* __restrict__ x, const float* __restrict__ n1_w0) {
    int c = blockIdx.x * 256 + threadIdx.x;
    int n = blockIdx.y;
    float s = g_bb[c];
    #pragma unroll
    for (int j = 0; j < 9; j++)
        s += x[(size_t)n * 9 + j] * n1_w0[(size_t)j * NODE_H_C + c];
    g_pn1[(size_t)n * NODE_H_C + c] = s;
}

// --------------- build e19: [x_row, x_col, ea, pad] fp16 + per-edge graph id ------
__global__ void build_e19_kernel(const float* __restrict__ x, const float* __restrict__ ea,
                                 const int* __restrict__ ei, const int* __restrict__ batch) {
    int e = blockIdx.x * 8 + (threadIdx.x >> 5);
    int lane = threadIdx.x & 31;
    int r = ei[e], c = ei[N_EDGES_C + e];
    float v = 0.f;
    if (lane < 9)        v = x[(size_t)r * 9 + lane];
    else if (lane < 18)  v = x[(size_t)c * 9 + (lane - 9)];
    else if (lane == 18) v = ea[e];
    g_e19[(size_t)e * 32 + lane] = __float2half(v);
    if (lane == 0) g_gedge[e] = batch[r];
}

// ------------------------- fp16 tensor-core GEMM ---------------------------------
// BMODE: 0 = column bias vector, 1 = per-row fp32 table, 2 = indexed table
#define BM 128
#define BN 256
#define BKK 32
#define GT 256
#define STG 3
#define A_ST (BM * 40)     // halves per A stage (pad 32->40)
#define B_ST (BKK * 264)   // halves per B stage (pad 256->264)
#define GEMM_SMEM (STG * (A_ST + B_ST) * 2)

template<bool RELU, int BMODE>
__global__ __launch_bounds__(GT, 1)
void gemm_kernel(const __half* __restrict__ A, int lda,
                 const __half* __restrict__ B, int ldb,
                 const float* __restrict__ bias,
                 const int* __restrict__ bidx,
                 __half* __restrict__ C, int ldc, int K) {
    extern __shared__ __half sm[];
    __half* Asm = sm;                    // [STG][128][40]
    __half* Bsm = sm + STG * A_ST;       // [STG][32][264]

    const int tid  = threadIdx.x;
    const int lane = tid & 31, warp = tid >> 5;
    const int wm = warp & 1;
    const int wn = warp >> 1;
    const int bm = blockIdx.y, bn = blockIdx.x;

    const __half* Ag = A + (size_t)bm * BM * lda;
    const __half* Bg = B + (size_t)bn * BN;

    float acc[4][8][4];
    #pragma unroll
    for (int i = 0; i < 4; i++)
        #pragma unroll
        for (int j = 0; j < 8; j++)
            #pragma unroll
            for (int k = 0; k < 4; k++) acc[i][j][k] = 0.f;

    const int KT = K / BKK;

    auto load = [&](int kt, int st) {
        __half* as = Asm + st * A_ST;
        __half* bs = Bsm + st * B_ST;
        #pragma unroll
        for (int i = 0; i < 2; i++) {
            int ch = tid + i * GT;
            int r = ch >> 2, cc = (ch & 3) << 3;
            cp16(smem_u32(as + r * 40 + cc), Ag + (size_t)r * lda + kt * BKK + cc);
        }
        #pragma unroll
        for (int i = 0; i < 4; i++) {
            int ch = tid + i * GT;
            int r = ch >> 5, cc = (ch & 31) << 3;
            cp16(smem_u32(bs + r * 264 + cc), Bg + (size_t)(kt * BKK + r) * ldb + cc);
        }
        cp_commit();
    };

    load(0, 0);
    load(KT > 1 ? 1 : 0, 1);

    for (int kt = 0; kt < KT; kt++) {
        cp_wait1();
        __syncthreads();
        const int st = kt % 3;
        if (kt + 2 < KT) load(kt + 2, (kt + 2) % 3);
        else             cp_commit();

        #pragma unroll
        for (int ks = 0; ks < 2; ks++) {
            uint32_t afr[4][4];
            {
                const __half* as = Asm + st * A_ST;
                int row = wm * 64 + (lane & 15);
                int col = ks * 16 + (lane >> 4) * 8;
                #pragma unroll
                for (int mi = 0; mi < 4; mi++)
                    ldm_x4(smem_u32(as + (row + mi * 16) * 40 + col),
                           afr[mi][0], afr[mi][1], afr[mi][2], afr[mi][3]);
            }
            uint32_t bfr[8][2];
            {
                const __half* bs = Bsm + st * B_ST;
                int row = ks * 16 + ((lane >> 3) & 1) * 8 + (lane & 7);
                #pragma unroll
                for (int p = 0; p < 4; p++) {
                    int col = wn * 64 + p * 16 + (lane >> 4) * 8;
                    uint32_t r0, r1, r2, r3;
                    ldm_x4t(smem_u32(bs + row * 264 + col), r0, r1, r2, r3);
                    bfr[2 * p][0] = r0;     bfr[2 * p][1] = r1;
                    bfr[2 * p + 1][0] = r2; bfr[2 * p + 1][1] = r3;
                }
            }
            #pragma unroll
            for (int mi = 0; mi < 4; mi++)
                #pragma unroll
                for (int nj = 0; nj < 8; nj++)
                    mma16816(acc[mi][nj], afr[mi], bfr[nj]);
        }
    }

    // epilogue
    int row0 = bm * BM + wm * 64;
    int col0 = bn * BN + wn * 64;
    #pragma unroll
    for (int mi = 0; mi < 4; mi++) {
        #pragma unroll
        for (int h = 0; h < 2; h++) {
            int r = row0 + mi * 16 + (lane >> 2) + h * 8;
            const float* tb = bias;
            if (BMODE == 1) tb = bias + (size_t)r * ldc;
            if (BMODE == 2) tb = bias + (size_t)bidx[r] * ldc;
            #pragma unroll
            for (int nj = 0; nj < 8; nj++) {
                int c = col0 + nj * 8 + (lane & 3) * 2;
                float b0 = tb[c], b1 = tb[c + 1];
                float f0 = acc[mi][nj][2 * h] + b0;
                float f1 = acc[mi][nj][2 * h + 1] + b1;
                if (RELU) { f0 = fmaxf(f0, 0.f); f1 = fmaxf(f1, 0.f); }
                *reinterpret_cast<__half2*>(C + (size_t)r * ldc + c) = __floats2half2_rn(f0, f1);
            }
        }
    }
}

// --------------- scatter-mean: CSR build + gather reduce -------------------------
__global__ void zero_cnt_kernel() {
    int i = blockIdx.x * blockDim.x + threadIdx.x;
    if (i < N_NODES_C) { g_cnt[i] = 0; g_cur[i] = 0; }
}
__global__ void count_kernel(const int* __restrict__ ei) {
    int e = blockIdx.x * blockDim.x + threadIdx.x;
    if (e < N_EDGES_C) atomicAdd(&g_cnt[ei[e]], 1);
}
__global__ void scan_kernel() {
    __shared__ int ws[32];
    int t = threadIdx.x;
    int base = t * 16;
    int v[16]; int s = 0;
    #pragma unroll
    for (int i = 0; i < 16; i++) { v[i] = s; s += g_cnt[base + i]; }
    int lane = t & 31, w = t >> 5;
    int x = s;
    #pragma unroll
    for (int o = 1; o < 32; o <<= 1) { int y = __shfl_up_sync(~0u, x, o); if (lane >= o) x += y; }
    if (lane == 31) ws[w] = x;
    __syncthreads();
    if (w == 0) {
        int y = ws[lane];
        #pragma unroll
        for (int o = 1; o < 32; o <<= 1) { int z = __shfl_up_sync(~0u, y, o); if (lane >= o) y += z; }
        ws[lane] = y;
    }
    __syncthreads();
    int pre = (x - s) + (w > 0 ? ws[w - 1] : 0);
    #pragma unroll
    for (int i = 0; i < 16; i++) g_off[base + i] = pre + v[i];
    if (t == 1023) g_off[N_NODES_C] = pre + s;
}
__global__ void fill_kernel(const int* __restrict__ ei) {
    int e = blockIdx.x * blockDim.x + threadIdx.x;
    if (e < N_EDGES_C) {
        int r = ei[e];
        int p = g_off[r] + atomicAdd(&g_cur[r], 1);
        g_elist[p] = e;
    }
}
// block per node: mean over its edges of h_n (g_bufB [E,512] fp16) -> oin
// thread t handles 4 contiguous halves (one uint2 load per edge row)
__global__ void node_reduce_kernel() {
    int n = blockIdx.x;
    int t = threadIdx.x;  // 128
    int deg = g_cnt[n], start = g_off[n];
    float a0 = 0.f, a1 = 0.f, a2 = 0.f, a3 = 0.f;
    for (int i = 0; i < deg; i++) {
        int e = g_elist[start + i];
        uint2 v = *reinterpret_cast<const uint2*>(g_bufB + (size_t)e * NODE_H_C + t * 4);
        __half2 h0 = *reinterpret_cast<__half2*>(&v.x);
        __half2 h1 = *reinterpret_cast<__half2*>(&v.y);
        float2 f0 = __half22float2(h0), f1 = __half22float2(h1);
        a0 += f0.x; a1 += f0.y; a2 += f1.x; a3 += f1.y;
    }
    float inv = 1.f / (float)(deg > 0 ? deg : 1);
    __half2 o0 = __floats2half2_rn(a0 * inv, a1 * inv);
    __half2 o1 = __floats2half2_rn(a2 * inv, a3 * inv);
    uint2 ov;
    ov.x = *reinterpret_cast<uint32_t*>(&o0);
    ov.y = *reinterpret_cast<uint32_t*>(&o1);
    *reinterpret_cast<uint2*>(g_oin + (size_t)n * NODE_H_C + t * 4) = ov;
}

// --------------- final dot: out[n] = h2[n,:] . n2_w1 + b --------------------------
__global__ void final_kernel(const float* __restrict__ w, const float* __restrict__ b,
                             float* __restrict__ out) {
    int n = blockIdx.x * 8 + (threadIdx.x >> 5);
    int lane = threadIdx.x & 31;
    const __half* h = g_h2 + (size_t)n * NODE_H_C;
    float s = 0.f;
    #pragma unroll
    for (int j = 0; j < 16; j++) {
        int c = lane + j * 32;
        s += __half2float(h[c]) * w[c];
    }
    #pragma unroll
    for (int o = 16; o > 0; o >>= 1) s += __shfl_xor_sync(~0u, s, o);
    if (lane == 0) out[n] = s + b[0];
}

// ------------------------- host launcher -----------------------------------------
extern "C" void kernel_launch(void* const* d_in, const int* in_sizes, int n_in,
                              void* d_out, int out_size) {
    (void)in_sizes; (void)n_in; (void)out_size;
    const float* x      = (const float*)d_in[0];
    const float* ea     = (const float*)d_in[1];
    const float* u      = (const float*)d_in[2];
    const int*   ei     = (const int*)d_in[3];
    const int*   batch  = (const int*)d_in[4];
    const float* w_dr   = (const float*)d_in[5];
    const float* b_dr   = (const float*)d_in[6];
    const float* e_w0   = (const float*)d_in[7];
    const float* e_b0   = (const float*)d_in[8];
    const float* e_w1   = (const float*)d_in[9];
    const float* e_b1   = (const float*)d_in[10];
    const float* e_w2   = (const float*)d_in[11];
    const float* e_b2   = (const float*)d_in[12];
    const float* e_w3   = (const float*)d_in[13];
    const float* e_b3   = (const float*)d_in[14];
    const float* e_wf   = (const float*)d_in[15];
    const float* e_bf   = (const float*)d_in[16];
    const float* n1_w0  = (const float*)d_in[17];
    const float* n1_b0  = (const float*)d_in[18];
    const float* n1_w1  = (const float*)d_in[19];
    const float* n1_b1  = (const float*)d_in[20];
    const float* n2_w0  = (const float*)d_in[21];
    const float* n2_b0  = (const float*)d_in[22];
    const float* n2_w1  = (const float*)d_in[23];
    const float* n2_b1  = (const float*)d_in[24];
    float* out = (float*)d_out;

    __half *w19h, *w1h, *w2h, *w3h, *wfh, *n1w0h, *n1w1h, *n2w0h, *cw;
    __half *bufA, *bufB, *oin, *h2, *e19;
    float  *addn, *pn1, *zerov, *uef;
    int    *gedge;
    cudaGetSymbolAddress((void**)&w19h,  g_w19h);
    cudaGetSymbolAddress((void**)&w1h,   g_w1h);
    cudaGetSymbolAddress((void**)&w2h,   g_w2h);
    cudaGetSymbolAddress((void**)&w3h,   g_w3h);
    cudaGetSymbolAddress((void**)&wfh,   g_wfh);
    cudaGetSymbolAddress((void**)&n1w0h, g_n1w0h);
    cudaGetSymbolAddress((void**)&n1w1h, g_n1w1h);
    cudaGetSymbolAddress((void**)&n2w0h, g_n2w0h);
    cudaGetSymbolAddress((void**)&cw,    g_cw);
    cudaGetSymbolAddress((void**)&bufA, g_bufA);
    cudaGetSymbolAddress((void**)&bufB, g_bufB);
    cudaGetSymbolAddress((void**)&oin,  g_oin);
    cudaGetSymbolAddress((void**)&h2,   g_h2);
    cudaGetSymbolAddress((void**)&e19,  g_e19);
    cudaGetSymbolAddress((void**)&addn, g_addn);
    cudaGetSymbolAddress((void**)&pn1,  g_pn1);
    cudaGetSymbolAddress((void**)&zerov, g_zero);
    cudaGetSymbolAddress((void**)&uef,  g_ue);
    cudaGetSymbolAddress((void**)&gedge, g_gedge);

    cudaFuncSetAttribute((const void*)gemm_kernel<true,  0>, cudaFuncAttributeMaxDynamicSharedMemorySize, GEMM_SMEM);
    cudaFuncSetAttribute((const void*)gemm_kernel<false, 0>, cudaFuncAttributeMaxDynamicSharedMemorySize, GEMM_SMEM);
    cudaFuncSetAttribute((const void*)gemm_kernel<true,  1>, cudaFuncAttributeMaxDynamicSharedMemorySize, GEMM_SMEM);
    cudaFuncSetAttribute((const void*)gemm_kernel<true,  2>, cudaFuncAttributeMaxDynamicSharedMemorySize, GEMM_SMEM);

    // side stream + fork/join events (created once; same captured work every call)
    static cudaStream_t s2 = nullptr;
    static cudaEvent_t evFork = nullptr, evJoin = nullptr;
    if (s2 == nullptr) {
        cudaStreamCreateWithFlags(&s2, cudaStreamNonBlocking);
        cudaEventCreateWithFlags(&evFork, cudaEventDisableTiming);
        cudaEventCreateWithFlags(&evJoin, cudaEventDisableTiming);
    }

    const Seg Z{0, 0, 0};
    auto gsz = [](int n) { return (n + 255) / 256; };

    // ---- main stream: minimal prologue for the GEMM chain ----
    pack_weight<<<gsz(32 * 1024), 256>>>(e_w0, w19h, 1024, 32, Seg{0, 0, 19}, Z, Z, Z);
    dimred_kernel<<<dim3(16, 8), 256>>>(u, w_dr, b_dr);
    ue_kernel<<<dim3(16, 4), 256>>>(e_w0, e_b0);
    build_e19_kernel<<<N_EDGES_C / 8, 256>>>(x, ea, ei, batch);

    // ---- fork side stream: packs, tables, CW GEMM, CSR build (overlap big GEMMs) ----
    cudaEventRecord(evFork, 0);
    cudaStreamWaitEvent(s2, evFork, 0);

    pack_weight<<<gsz(1024 * 1024), 256, 0, s2>>>(e_w1, w1h, 1024, 1024, Seg{0, 0, 1024}, Z, Z, Z);
    pack_weight<<<gsz(1024 * 1024), 256, 0, s2>>>(e_w2, w2h, 1024, 1024, Seg{0, 0, 1024}, Z, Z, Z);
    pack_weight<<<gsz(1024 * 1024), 256, 0, s2>>>(e_w3, w3h, 1024, 1024, Seg{0, 0, 1024}, Z, Z, Z);
    pack_weight<<<gsz(1024 * 512),  256, 0, s2>>>(e_wf, wfh, 512, 1024, Seg{0, 0, 1024}, Z, Z, Z);
    pack_weight<<<gsz(512 * 512),   256, 0, s2>>>(n1_w0, n1w0h, 512, 512, Seg{9, 0, 512}, Z, Z, Z);
    pack_weight<<<gsz(512 * 512),   256, 0, s2>>>(n1_w1, n1w1h, 512, 512, Seg{0, 0, 512}, Z, Z, Z);
    pack_weight<<<gsz(512 * 512),   256, 0, s2>>>(n2_w0, n2w0h, 512, 512, Seg{9, 0, 512}, Z, Z, Z);
    un_kernel<<<dim3(16, 2), 256, 0, s2>>>(n2_w0, n2_b0);
    addn_kernel<<<dim3(2, N_NODES_C), 256, 0, s2>>>(x, batch, n2_w0);
    bb_kernel<<<2, 256, 0, s2>>>(e_bf, n1_w0, n1_b0);
    pn1_kernel<<<dim3(2, N_NODES_C), 256, 0, s2>>>(x, n1_w0);
    // composite weight CW = e_wf @ n1_w0[9:521]  (exact linear fusion)
    gemm_kernel<false, 0><<<dim3(2, 8), GT, GEMM_SMEM, s2>>>(wfh, 512, n1w0h, 512, zerov, nullptr, cw, 512, 512);
    // CSR build for scatter-mean
    zero_cnt_kernel<<<N_NODES_C / 256, 256, 0, s2>>>();
    count_kernel<<<N_EDGES_C / 256, 256, 0, s2>>>(ei);
    scan_kernel<<<1, 1024, 0, s2>>>();
    fill_kernel<<<N_EDGES_C / 256, 256, 0, s2>>>(ei);

    cudaEventRecord(evJoin, s2);

    const int MT = N_EDGES_C / BM;      // 1024
    const int MTN = N_NODES_C / BM;     // 128

    // ---- main stream: edge MLP (needs only w19h/ue/e19 and w1..w3 packs) ----
    // layer 0 as K=32 GEMM with indexed Ue bias
    gemm_kernel<true, 2><<<dim3(4, MT), GT, GEMM_SMEM>>>(e19, 32, w19h, 1024, uef, gedge, bufA, 1024, 32);

    // interior layers need w1h/w2h/w3h from s2 — but those packs run first on s2
    // (~20 us) while l0 GEMM (~60 us) runs here; join formally before first use.
    cudaStreamWaitEvent(0, evJoin, 0);
    gemm_kernel<true, 0><<<dim3(4, MT), GT, GEMM_SMEM>>>(bufA, 1024, w1h, 1024, e_b1, nullptr, bufB, 1024, 1024);
    gemm_kernel<true, 0><<<dim3(4, MT), GT, GEMM_SMEM>>>(bufB, 1024, w2h, 1024, e_b2, nullptr, bufA, 1024, 1024);
    gemm_kernel<true, 0><<<dim3(4, MT), GT, GEMM_SMEM>>>(bufA, 1024, w3h, 1024, e_b3, nullptr, bufB, 1024, 1024);

    // fused (e_wf -> n1 layer0): h = relu(h3 @ CW + PN1[col[e]])
    gemm_kernel<true, 2><<<dim3(2, MT), GT, GEMM_SMEM>>>(bufB, 1024, cw, 512, pn1, ei + N_EDGES_C, bufA, 512, 1024);

    // n1 layer 1
    gemm_kernel<true, 0><<<dim3(2, MT), GT, GEMM_SMEM>>>(bufA, 512, n1w1h, 512, n1_b1, nullptr, bufB, 512, 512);

    // scatter-mean gather-reduce (CSR tables ready from s2)
    node_reduce_kernel<<<N_NODES_C, 128>>>();

    // node MLP 2 (K=512, row-bias table carries x/u_r/bias contributions) + final dot
    gemm_kernel<true, 1><<<dim3(2, MTN), GT, GEMM_SMEM>>>(oin, 512, n2w0h, 512, addn, nullptr, h2, 512, 512);
    final_kernel<<<N_NODES_C / 8, 256>>>(n2_w1, n2_b1, out);
}

// round 13
// speedup vs baseline: 1.2120x; 1.0103x over previous
#include <cuda_runtime.h>
#include <cuda_fp16.h>
#include <cstdint>

#define DI __device__ __forceinline__

// ------------------------- problem sizes -------------------------
#define N_NODES_C 16384
#define N_EDGES_C 131072
#define N_GRAPHS_C 16
#define U_SZ_C 4096
#define U_RED_C 256
#define EDGE_H_C 1024
#define EDGE_OUT_C 512
#define NODE_H_C 512
#define E_HALF (N_EDGES_C / 2)

// ------------------------- device scratch -------------------------
__device__ __half g_bufA[(size_t)N_EDGES_C * EDGE_H_C];
__device__ __half g_bufB[(size_t)N_EDGES_C * EDGE_H_C];
__device__ __half g_oin [(size_t)N_NODES_C * NODE_H_C];
__device__ __half g_h2  [(size_t)N_NODES_C * NODE_H_C];
__device__ float  g_ur  [N_GRAPHS_C * U_RED_C];

// layer-0 small-K input: [x_row(9), x_col(9), ea(1), pad->32] + per-edge graph id
__device__ __half g_e19 [(size_t)(N_EDGES_C + 256) * 32];
__device__ int    g_gedge[N_EDGES_C];

// factorization tables
__device__ float  g_ue  [N_GRAPHS_C * EDGE_H_C];          // u_r @ W_u + e_b0   (edge l0 bias)
__device__ float  g_un  [N_GRAPHS_C * NODE_H_C];          // u_r @ W_u2 + n2_b0
__device__ float  g_addn[(size_t)N_NODES_C * NODE_H_C];   // row bias for n2 GEMM

// e_wf -> n1_w0 fusion tables
__device__ __half g_cw  [EDGE_H_C * NODE_H_C];            // e_wf @ n1_w0[9:521]
__device__ float  g_bb  [NODE_H_C];                        // n1_b0 + e_bf @ W_e
__device__ float  g_pn1 [(size_t)N_NODES_C * NODE_H_C];   // bb + x[n] @ W_x (per node)
__device__ float  g_zero[NODE_H_C];                        // stays 0 (module zero-init)

// weights packed [Kp, N] row-major fp16
__device__ __half g_w19h [32       * EDGE_H_C];   // e_w0 rows 0..18 (x_row,x_col,ea), zero pad
__device__ __half g_w1h  [EDGE_H_C * EDGE_H_C];
__device__ __half g_w2h  [EDGE_H_C * EDGE_H_C];
__device__ __half g_w3h  [EDGE_H_C * EDGE_H_C];
__device__ __half g_wfh  [EDGE_H_C * EDGE_OUT_C];
__device__ __half g_n1w0h[NODE_H_C * NODE_H_C];   // n1_w0 rows 9..520 (e-part)
__device__ __half g_n1w1h[NODE_H_C * NODE_H_C];
__device__ __half g_n2w0h[NODE_H_C * NODE_H_C];   // n2_w0 rows 9..520 (agg-part)

__device__ int g_cnt[N_NODES_C];
__device__ int g_off[N_NODES_C + 1];
__device__ int g_cur[N_NODES_C];
__device__ int g_elist[N_EDGES_C];

// ------------------------- small helpers -------------------------
DI uint32_t smem_u32(const void* p) {
    return (uint32_t)__cvta_generic_to_shared(p);
}
DI void cp16(uint32_t dst, const void* src) {
    asm volatile("cp.async.cg.shared.global [%0], [%1], 16;\n" :: "r"(dst), "l"(src));
}
DI void cp_commit() { asm volatile("cp.async.commit_group;\n"); }
DI void cp_wait1()  { asm volatile("cp.async.wait_group 1;\n"); }

DI void ldm_x4(uint32_t addr, uint32_t& r0, uint32_t& r1, uint32_t& r2, uint32_t& r3) {
    asm volatile("ldmatrix.sync.aligned.m8n8.x4.shared.b16 {%0,%1,%2,%3}, [%4];\n"
                 : "=r"(r0), "=r"(r1), "=r"(r2), "=r"(r3) : "r"(addr));
}
DI void ldm_x4t(uint32_t addr, uint32_t& r0, uint32_t& r1, uint32_t& r2, uint32_t& r3) {
    asm volatile("ldmatrix.sync.aligned.m8n8.x4.trans.shared.b16 {%0,%1,%2,%3}, [%4];\n"
                 : "=r"(r0), "=r"(r1), "=r"(r2), "=r"(r3) : "r"(addr));
}
DI void mma16816(float* d, const uint32_t* a, const uint32_t* b) {
    asm volatile("mma.sync.aligned.m16n8k16.row.col.f32.f16.f16.f32 "
                 "{%0,%1,%2,%3}, {%4,%5,%6,%7}, {%8,%9}, {%0,%1,%2,%3};\n"
                 : "+f"(d[0]), "+f"(d[1]), "+f"(d[2]), "+f"(d[3])
                 : "r"(a[0]), "r"(a[1]), "r"(a[2]), "r"(a[3]),
                   "r"(b[0]), "r"(b[1]));
}

// --------------- weight pack: fp32 -> fp16, row permute + zero pad ---------------
struct Seg { int src0, dst0, n; };

__global__ void pack_weight(const float* __restrict__ src, __half* __restrict__ dst,
                            int N, int Kp, Seg a, Seg b, Seg c, Seg d) {
    int idx = blockIdx.x * blockDim.x + threadIdx.x;
    if (idx >= Kp * N) return;
    int r = idx / N, col = idx - r * N;
    float v = 0.f;
    if      (r >= a.dst0 && r < a.dst0 + a.n) v = src[(size_t)(a.src0 + r - a.dst0) * N + col];
    else if (r >= b.dst0 && r < b.dst0 + b.n) v = src[(size_t)(b.src0 + r - b.dst0) * N + col];
    else if (r >= c.dst0 && r < c.dst0 + c.n) v = src[(size_t)(c.src0 + r - c.dst0) * N + col];
    else if (r >= d.dst0 && r < d.dst0 + d.n) v = src[(size_t)(d.src0 + r - d.dst0) * N + col];
    dst[idx] = __float2half(v);
}

// --------------- dim reduction: u_r = u @ w_dr + b_dr (fp32, tiny) ---------------
__global__ void dimred_kernel(const float* __restrict__ u, const float* __restrict__ w,
                              const float* __restrict__ b) {
    __shared__ float red[8][32];
    int g = blockIdx.x, ct = blockIdx.y;
    int kg = threadIdx.x >> 5, cl = threadIdx.x & 31;
    int c = ct * 32 + cl;
    const float* up = u + (size_t)g * U_SZ_C + kg * 512;
    const float* wp = w + (size_t)(kg * 512) * U_RED_C + c;
    float s = 0.f;
    #pragma unroll 8
    for (int k = 0; k < 512; k++) s += up[k] * wp[(size_t)k * U_RED_C];
    red[kg][cl] = s;
    __syncthreads();
    if (kg == 0) {
        float t = b[c];
        #pragma unroll
        for (int i = 0; i < 8; i++) t += red[i][cl];
        g_ur[g * U_RED_C + c] = t;
    }
}

// --------------- bias-table precomputes -------------------------------------------
__global__ void ue_kernel(const float* __restrict__ e_w0, const float* __restrict__ e_b0) {
    int c = blockIdx.y * 256 + threadIdx.x;
    int g = blockIdx.x;
    float s = e_b0[c];
    #pragma unroll 4
    for (int j = 0; j < U_RED_C; j++)
        s += g_ur[g * U_RED_C + j] * e_w0[(size_t)(19 + j) * EDGE_H_C + c];
    g_ue[g * EDGE_H_C + c] = s;
}

__global__ void un_kernel(const float* __restrict__ n2_w0, const float* __restrict__ n2_b0) {
    int c = blockIdx.y * 256 + threadIdx.x;
    int g = blockIdx.x;
    float s = n2_b0[c];
    #pragma unroll 4
    for (int j = 0; j < U_RED_C; j++)
        s += g_ur[g * U_RED_C + j] * n2_w0[(size_t)(521 + j) * NODE_H_C + c];
    g_un[g * NODE_H_C + c] = s;
}

__global__ void addn_kernel(const float* __restrict__ x, const int* __restrict__ batch,
                            const float* __restrict__ n2_w0) {
    int c = blockIdx.x * 256 + threadIdx.x;
    int n = blockIdx.y;
    int g = batch[n];
    float s = g_un[g * NODE_H_C + c];
    #pragma unroll
    for (int j = 0; j < 9; j++)
        s += x[(size_t)n * 9 + j] * n2_w0[(size_t)j * NODE_H_C + c];
    g_addn[(size_t)n * NODE_H_C + c] = s;
}

__global__ void bb_kernel(const float* __restrict__ e_bf, const float* __restrict__ n1_w0,
                          const float* __restrict__ n1_b0) {
    int c = blockIdx.x * 256 + threadIdx.x;
    float s = n1_b0[c];
    #pragma unroll 4
    for (int j = 0; j < EDGE_OUT_C; j++)
        s += e_bf[j] * n1_w0[(size_t)(9 + j) * NODE_H_C + c];
    g_bb[c] = s;
}
__global__ void pn1_kernel(const float* __restrict__ x, const float* __restrict__ n1_w0) {
    int c = blockIdx.x * 256 + threadIdx.x;
    int n = blockIdx.y;
    float s = g_bb[c];
    #pragma unroll
    for (int j = 0; j < 9; j++)
        s += x[(size_t)n * 9 + j] * n1_w0[(size_t)j * NODE_H_C + c];
    g_pn1[(size_t)n * NODE_H_C + c] = s;
}

// --------------- build e19: [x_row, x_col, ea, pad] fp16 + per-edge graph id ------
__global__ void build_e19_kernel(const float* __restrict__ x, const float* __restrict__ ea,
                                 const int* __restrict__ ei, const int* __restrict__ batch) {
    int e = blockIdx.x * 8 + (threadIdx.x >> 5);
    int lane = threadIdx.x & 31;
    int r = ei[e], c = ei[N_EDGES_C + e];
    float v = 0.f;
    if (lane < 9)        v = x[(size_t)r * 9 + lane];
    else if (lane < 18)  v = x[(size_t)c * 9 + (lane - 9)];
    else if (lane == 18) v = ea[e];
    g_e19[(size_t)e * 32 + lane] = __float2half(v);
    if (lane == 0) g_gedge[e] = batch[r];
}

// ------------------------- fp16 tensor-core GEMM ---------------------------------
// BMODE: 0 = column bias vector, 1 = per-row fp32 table, 2 = indexed table
#define BM 128
#define BN 256
#define BKK 32
#define GT 256
#define STG 3
#define A_ST (BM * 40)     // halves per A stage (pad 32->40)
#define B_ST (BKK * 264)   // halves per B stage (pad 256->264)
#define GEMM_SMEM (STG * (A_ST + B_ST) * 2)

template<bool RELU, int BMODE>
__global__ __launch_bounds__(GT, 1)
void gemm_kernel(const __half* __restrict__ A, int lda,
                 const __half* __restrict__ B, int ldb,
                 const float* __restrict__ bias,
                 const int* __restrict__ bidx,
                 __half* __restrict__ C, int ldc, int K) {
    extern __shared__ __half sm[];
    __half* Asm = sm;                    // [STG][128][40]
    __half* Bsm = sm + STG * A_ST;       // [STG][32][264]

    const int tid  = threadIdx.x;
    const int lane = tid & 31, warp = tid >> 5;
    const int wm = warp & 1;
    const int wn = warp >> 1;
    const int bm = blockIdx.y, bn = blockIdx.x;

    const __half* Ag = A + (size_t)bm * BM * lda;
    const __half* Bg = B + (size_t)bn * BN;

    float acc[4][8][4];
    #pragma unroll
    for (int i = 0; i < 4; i++)
        #pragma unroll
        for (int j = 0; j < 8; j++)
            #pragma unroll
            for (int k = 0; k < 4; k++) acc[i][j][k] = 0.f;

    const int KT = K / BKK;

    auto load = [&](int kt, int st) {
        __half* as = Asm + st * A_ST;
        __half* bs = Bsm + st * B_ST;
        #pragma unroll
        for (int i = 0; i < 2; i++) {
            int ch = tid + i * GT;
            int r = ch >> 2, cc = (ch & 3) << 3;
            cp16(smem_u32(as + r * 40 + cc), Ag + (size_t)r * lda + kt * BKK + cc);
        }
        #pragma unroll
        for (int i = 0; i < 4; i++) {
            int ch = tid + i * GT;
            int r = ch >> 5, cc = (ch & 31) << 3;
            cp16(smem_u32(bs + r * 264 + cc), Bg + (size_t)(kt * BKK + r) * ldb + cc);
        }
        cp_commit();
    };

    load(0, 0);
    load(KT > 1 ? 1 : 0, 1);

    for (int kt = 0; kt < KT; kt++) {
        cp_wait1();
        __syncthreads();
        const int st = kt % 3;
        if (kt + 2 < KT) load(kt + 2, (kt + 2) % 3);
        else             cp_commit();

        #pragma unroll
        for (int ks = 0; ks < 2; ks++) {
            uint32_t afr[4][4];
            {
                const __half* as = Asm + st * A_ST;
                int row = wm * 64 + (lane & 15);
                int col = ks * 16 + (lane >> 4) * 8;
                #pragma unroll
                for (int mi = 0; mi < 4; mi++)
                    ldm_x4(smem_u32(as + (row + mi * 16) * 40 + col),
                           afr[mi][0], afr[mi][1], afr[mi][2], afr[mi][3]);
            }
            uint32_t bfr[8][2];
            {
                const __half* bs = Bsm + st * B_ST;
                int row = ks * 16 + ((lane >> 3) & 1) * 8 + (lane & 7);
                #pragma unroll
                for (int p = 0; p < 4; p++) {
                    int col = wn * 64 + p * 16 + (lane >> 4) * 8;
                    uint32_t r0, r1, r2, r3;
                    ldm_x4t(smem_u32(bs + row * 264 + col), r0, r1, r2, r3);
                    bfr[2 * p][0] = r0;     bfr[2 * p][1] = r1;
                    bfr[2 * p + 1][0] = r2; bfr[2 * p + 1][1] = r3;
                }
            }
            #pragma unroll
            for (int mi = 0; mi < 4; mi++)
                #pragma unroll
                for (int nj = 0; nj < 8; nj++)
                    mma16816(acc[mi][nj], afr[mi], bfr[nj]);
        }
    }

    // epilogue
    int row0 = bm * BM + wm * 64;
    int col0 = bn * BN + wn * 64;
    #pragma unroll
    for (int mi = 0; mi < 4; mi++) {
        #pragma unroll
        for (int h = 0; h < 2; h++) {
            int r = row0 + mi * 16 + (lane >> 2) + h * 8;
            const float* tb = bias;
            if (BMODE == 1) tb = bias + (size_t)r * ldc;
            if (BMODE == 2) tb = bias + (size_t)bidx[r] * ldc;
            #pragma unroll
            for (int nj = 0; nj < 8; nj++) {
                int c = col0 + nj * 8 + (lane & 3) * 2;
                float b0 = tb[c], b1 = tb[c + 1];
                float f0 = acc[mi][nj][2 * h] + b0;
                float f1 = acc[mi][nj][2 * h + 1] + b1;
                if (RELU) { f0 = fmaxf(f0, 0.f); f1 = fmaxf(f1, 0.f); }
                *reinterpret_cast<__half2*>(C + (size_t)r * ldc + c) = __floats2half2_rn(f0, f1);
            }
        }
    }
}

// --------------- scatter-mean: CSR build + gather reduce -------------------------
__global__ void zero_cnt_kernel() {
    int i = blockIdx.x * blockDim.x + threadIdx.x;
    if (i < N_NODES_C) { g_cnt[i] = 0; g_cur[i] = 0; }
}
__global__ void count_kernel(const int* __restrict__ ei) {
    int e = blockIdx.x * blockDim.x + threadIdx.x;
    if (e < N_EDGES_C) atomicAdd(&g_cnt[ei[e]], 1);
}
__global__ void scan_kernel() {
    __shared__ int ws[32];
    int t = threadIdx.x;
    int base = t * 16;
    int v[16]; int s = 0;
    #pragma unroll
    for (int i = 0; i < 16; i++) { v[i] = s; s += g_cnt[base + i]; }
    int lane = t & 31, w = t >> 5;
    int x = s;
    #pragma unroll
    for (int o = 1; o < 32; o <<= 1) { int y = __shfl_up_sync(~0u, x, o); if (lane >= o) x += y; }
    if (lane == 31) ws[w] = x;
    __syncthreads();
    if (w == 0) {
        int y = ws[lane];
        #pragma unroll
        for (int o = 1; o < 32; o <<= 1) { int z = __shfl_up_sync(~0u, y, o); if (lane >= o) y += z; }
        ws[lane] = y;
    }
    __syncthreads();
    int pre = (x - s) + (w > 0 ? ws[w - 1] : 0);
    #pragma unroll
    for (int i = 0; i < 16; i++) g_off[base + i] = pre + v[i];
    if (t == 1023) g_off[N_NODES_C] = pre + s;
}
__global__ void fill_kernel(const int* __restrict__ ei) {
    int e = blockIdx.x * blockDim.x + threadIdx.x;
    if (e < N_EDGES_C) {
        int r = ei[e];
        int p = g_off[r] + atomicAdd(&g_cur[r], 1);
        g_elist[p] = e;
    }
}
// block per node: mean over its edges of h_n (g_bufB [E,512] fp16) -> oin
__global__ void node_reduce_kernel() {
    int n = blockIdx.x;
    int t = threadIdx.x;  // 128
    int deg = g_cnt[n], start = g_off[n];
    float a0 = 0.f, a1 = 0.f, a2 = 0.f, a3 = 0.f;
    for (int i = 0; i < deg; i++) {
        int e = g_elist[start + i];
        uint2 v = *reinterpret_cast<const uint2*>(g_bufB + (size_t)e * NODE_H_C + t * 4);
        __half2 h0 = *reinterpret_cast<__half2*>(&v.x);
        __half2 h1 = *reinterpret_cast<__half2*>(&v.y);
        float2 f0 = __half22float2(h0), f1 = __half22float2(h1);
        a0 += f0.x; a1 += f0.y; a2 += f1.x; a3 += f1.y;
    }
    float inv = 1.f / (float)(deg > 0 ? deg : 1);
    __half2 o0 = __floats2half2_rn(a0 * inv, a1 * inv);
    __half2 o1 = __floats2half2_rn(a2 * inv, a3 * inv);
    uint2 ov;
    ov.x = *reinterpret_cast<uint32_t*>(&o0);
    ov.y = *reinterpret_cast<uint32_t*>(&o1);
    *reinterpret_cast<uint2*>(g_oin + (size_t)n * NODE_H_C + t * 4) = ov;
}

// --------------- final dot: out[n] = h2[n,:] . n2_w1 + b --------------------------
__global__ void final_kernel(const float* __restrict__ w, const float* __restrict__ b,
                             float* __restrict__ out) {
    int n = blockIdx.x * 8 + (threadIdx.x >> 5);
    int lane = threadIdx.x & 31;
    const __half* h = g_h2 + (size_t)n * NODE_H_C;
    float s = 0.f;
    #pragma unroll
    for (int j = 0; j < 16; j++) {
        int c = lane + j * 32;
        s += __half2float(h[c]) * w[c];
    }
    #pragma unroll
    for (int o = 16; o > 0; o >>= 1) s += __shfl_xor_sync(~0u, s, o);
    if (lane == 0) out[n] = s + b[0];
}

// ------------------------- host launcher -----------------------------------------
extern "C" void kernel_launch(void* const* d_in, const int* in_sizes, int n_in,
                              void* d_out, int out_size) {
    (void)in_sizes; (void)n_in; (void)out_size;
    const float* x      = (const float*)d_in[0];
    const float* ea     = (const float*)d_in[1];
    const float* u      = (const float*)d_in[2];
    const int*   ei     = (const int*)d_in[3];
    const int*   batch  = (const int*)d_in[4];
    const float* w_dr   = (const float*)d_in[5];
    const float* b_dr   = (const float*)d_in[6];
    const float* e_w0   = (const float*)d_in[7];
    const float* e_b0   = (const float*)d_in[8];
    const float* e_w1   = (const float*)d_in[9];
    const float* e_b1   = (const float*)d_in[10];
    const float* e_w2   = (const float*)d_in[11];
    const float* e_b2   = (const float*)d_in[12];
    const float* e_w3   = (const float*)d_in[13];
    const float* e_b3   = (const float*)d_in[14];
    const float* e_wf   = (const float*)d_in[15];
    const float* e_bf   = (const float*)d_in[16];
    const float* n1_w0  = (const float*)d_in[17];
    const float* n1_b0  = (const float*)d_in[18];
    const float* n1_w1  = (const float*)d_in[19];
    const float* n1_b1  = (const float*)d_in[20];
    const float* n2_w0  = (const float*)d_in[21];
    const float* n2_b0  = (const float*)d_in[22];
    const float* n2_w1  = (const float*)d_in[23];
    const float* n2_b1  = (const float*)d_in[24];
    float* out = (float*)d_out;

    __half *w19h, *w1h, *w2h, *w3h, *wfh, *n1w0h, *n1w1h, *n2w0h, *cw;
    __half *bufA, *bufB, *oin, *h2, *e19;
    float  *addn, *pn1, *zerov, *uef;
    int    *gedge;
    cudaGetSymbolAddress((void**)&w19h,  g_w19h);
    cudaGetSymbolAddress((void**)&w1h,   g_w1h);
    cudaGetSymbolAddress((void**)&w2h,   g_w2h);
    cudaGetSymbolAddress((void**)&w3h,   g_w3h);
    cudaGetSymbolAddress((void**)&wfh,   g_wfh);
    cudaGetSymbolAddress((void**)&n1w0h, g_n1w0h);
    cudaGetSymbolAddress((void**)&n1w1h, g_n1w1h);
    cudaGetSymbolAddress((void**)&n2w0h, g_n2w0h);
    cudaGetSymbolAddress((void**)&cw,    g_cw);
    cudaGetSymbolAddress((void**)&bufA, g_bufA);
    cudaGetSymbolAddress((void**)&bufB, g_bufB);
    cudaGetSymbolAddress((void**)&oin,  g_oin);
    cudaGetSymbolAddress((void**)&h2,   g_h2);
    cudaGetSymbolAddress((void**)&e19,  g_e19);
    cudaGetSymbolAddress((void**)&addn, g_addn);
    cudaGetSymbolAddress((void**)&pn1,  g_pn1);
    cudaGetSymbolAddress((void**)&zerov, g_zero);
    cudaGetSymbolAddress((void**)&uef,  g_ue);
    cudaGetSymbolAddress((void**)&gedge, g_gedge);

    cudaFuncSetAttribute((const void*)gemm_kernel<true,  0>, cudaFuncAttributeMaxDynamicSharedMemorySize, GEMM_SMEM);
    cudaFuncSetAttribute((const void*)gemm_kernel<false, 0>, cudaFuncAttributeMaxDynamicSharedMemorySize, GEMM_SMEM);
    cudaFuncSetAttribute((const void*)gemm_kernel<true,  1>, cudaFuncAttributeMaxDynamicSharedMemorySize, GEMM_SMEM);
    cudaFuncSetAttribute((const void*)gemm_kernel<true,  2>, cudaFuncAttributeMaxDynamicSharedMemorySize, GEMM_SMEM);

    // streams + fork/join events (created once; identical captured work per call)
    static cudaStream_t s2 = nullptr, s3 = nullptr;
    static cudaEvent_t evFork = nullptr, evJoin = nullptr, evB = nullptr;
    if (s2 == nullptr) {
        cudaStreamCreateWithFlags(&s2, cudaStreamNonBlocking);
        cudaStreamCreateWithFlags(&s3, cudaStreamNonBlocking);
        cudaEventCreateWithFlags(&evFork, cudaEventDisableTiming);
        cudaEventCreateWithFlags(&evJoin, cudaEventDisableTiming);
        cudaEventCreateWithFlags(&evB,    cudaEventDisableTiming);
    }

    const Seg Z{0, 0, 0};
    auto gsz = [](int n) { return (n + 255) / 256; };

    // ---- main stream: minimal prologue for the GEMM chains ----
    pack_weight<<<gsz(32 * 1024), 256>>>(e_w0, w19h, 1024, 32, Seg{0, 0, 19}, Z, Z, Z);
    dimred_kernel<<<dim3(16, 8), 256>>>(u, w_dr, b_dr);
    ue_kernel<<<dim3(16, 4), 256>>>(e_w0, e_b0);
    build_e19_kernel<<<N_EDGES_C / 8, 256>>>(x, ea, ei, batch);

    // ---- fork ----
    cudaEventRecord(evFork, 0);
    cudaStreamWaitEvent(s2, evFork, 0);
    cudaStreamWaitEvent(s3, evFork, 0);

    // side stream s2: packs, tables, CW GEMM, CSR build
    pack_weight<<<gsz(1024 * 1024), 256, 0, s2>>>(e_w1, w1h, 1024, 1024, Seg{0, 0, 1024}, Z, Z, Z);
    pack_weight<<<gsz(1024 * 1024), 256, 0, s2>>>(e_w2, w2h, 1024, 1024, Seg{0, 0, 1024}, Z, Z, Z);
    pack_weight<<<gsz(1024 * 1024), 256, 0, s2>>>(e_w3, w3h, 1024, 1024, Seg{0, 0, 1024}, Z, Z, Z);
    pack_weight<<<gsz(1024 * 512),  256, 0, s2>>>(e_wf, wfh, 512, 1024, Seg{0, 0, 1024}, Z, Z, Z);
    pack_weight<<<gsz(512 * 512),   256, 0, s2>>>(n1_w0, n1w0h, 512, 512, Seg{9, 0, 512}, Z, Z, Z);
    pack_weight<<<gsz(512 * 512),   256, 0, s2>>>(n1_w1, n1w1h, 512, 512, Seg{0, 0, 512}, Z, Z, Z);
    pack_weight<<<gsz(512 * 512),   256, 0, s2>>>(n2_w0, n2w0h, 512, 512, Seg{9, 0, 512}, Z, Z, Z);
    un_kernel<<<dim3(16, 2), 256, 0, s2>>>(n2_w0, n2_b0);
    addn_kernel<<<dim3(2, N_NODES_C), 256, 0, s2>>>(x, batch, n2_w0);
    bb_kernel<<<2, 256, 0, s2>>>(e_bf, n1_w0, n1_b0);
    pn1_kernel<<<dim3(2, N_NODES_C), 256, 0, s2>>>(x, n1_w0);
    gemm_kernel<false, 0><<<dim3(2, 8), GT, GEMM_SMEM, s2>>>(wfh, 512, n1w0h, 512, zerov, nullptr, cw, 512, 512);
    zero_cnt_kernel<<<N_NODES_C / 256, 256, 0, s2>>>();
    count_kernel<<<N_EDGES_C / 256, 256, 0, s2>>>(ei);
    scan_kernel<<<1, 1024, 0, s2>>>();
    fill_kernel<<<N_EDGES_C / 256, 256, 0, s2>>>(ei);
    cudaEventRecord(evJoin, s2);

    const int MT2 = E_HALF / BM;        // 512 (half the edges per chain)
    const int MTN = N_NODES_C / BM;     // 128
    const size_t OF1 = (size_t)E_HALF * EDGE_H_C;   // bufA/bufB offset for chain B (1024-wide)
    const size_t OF5 = (size_t)E_HALF * NODE_H_C;   // 512-wide offset

    // ---- chain A (stream 0): first half of edges ----
    gemm_kernel<true, 2><<<dim3(4, MT2), GT, GEMM_SMEM>>>(e19, 32, w19h, 1024, uef, gedge, bufA, 1024, 32);
    cudaStreamWaitEvent(0, evJoin, 0);
    gemm_kernel<true, 0><<<dim3(4, MT2), GT, GEMM_SMEM>>>(bufA, 1024, w1h, 1024, e_b1, nullptr, bufB, 1024, 1024);
    gemm_kernel<true, 0><<<dim3(4, MT2), GT, GEMM_SMEM>>>(bufB, 1024, w2h, 1024, e_b2, nullptr, bufA, 1024, 1024);
    gemm_kernel<true, 0><<<dim3(4, MT2), GT, GEMM_SMEM>>>(bufA, 1024, w3h, 1024, e_b3, nullptr, bufB, 1024, 1024);
    gemm_kernel<true, 2><<<dim3(2, MT2), GT, GEMM_SMEM>>>(bufB, 1024, cw, 512, pn1, ei + N_EDGES_C, bufA, 512, 1024);
    gemm_kernel<true, 0><<<dim3(2, MT2), GT, GEMM_SMEM>>>(bufA, 512, n1w1h, 512, n1_b1, nullptr, bufB, 512, 512);

    // ---- chain B (stream s3): second half of edges ----
    gemm_kernel<true, 2><<<dim3(4, MT2), GT, GEMM_SMEM, s3>>>(e19 + (size_t)E_HALF * 32, 32, w19h, 1024, uef, gedge + E_HALF, bufA + OF1, 1024, 32);
    cudaStreamWaitEvent(s3, evJoin, 0);
    gemm_kernel<true, 0><<<dim3(4, MT2), GT, GEMM_SMEM, s3>>>(bufA + OF1, 1024, w1h, 1024, e_b1, nullptr, bufB + OF1, 1024, 1024);
    gemm_kernel<true, 0><<<dim3(4, MT2), GT, GEMM_SMEM, s3>>>(bufB + OF1, 1024, w2h, 1024, e_b2, nullptr, bufA + OF1, 1024, 1024);
    gemm_kernel<true, 0><<<dim3(4, MT2), GT, GEMM_SMEM, s3>>>(bufA + OF1, 1024, w3h, 1024, e_b3, nullptr, bufB + OF1, 1024, 1024);
    gemm_kernel<true, 2><<<dim3(2, MT2), GT, GEMM_SMEM, s3>>>(bufB + OF1, 1024, cw, 512, pn1, ei + N_EDGES_C + E_HALF, bufA + OF5, 512, 1024);
    gemm_kernel<true, 0><<<dim3(2, MT2), GT, GEMM_SMEM, s3>>>(bufA + OF5, 512, n1w1h, 512, n1_b1, nullptr, bufB + OF5, 512, 512);
    cudaEventRecord(evB, s3);

    // ---- join both chains -> scatter-mean -> node MLP 2 -> final ----
    cudaStreamWaitEvent(0, evB, 0);
    node_reduce_kernel<<<N_NODES_C, 128>>>();
    gemm_kernel<true, 1><<<dim3(2, MTN), GT, GEMM_SMEM>>>(oin, 512, n2w0h, 512, addn, nullptr, h2, 512, 512);
    final_kernel<<<N_NODES_C / 8, 256>>>(n2_w1, n2_b1, out);
}

// round 15
// speedup vs baseline: 1.2217x; 1.0080x over previous
#include <cuda_runtime.h>
#include <cuda_fp16.h>
#include <cstdint>

#define DI __device__ __forceinline__

// ------------------------- problem sizes -------------------------
#define N_NODES_C 16384
#define N_EDGES_C 131072
#define N_GRAPHS_C 16
#define U_SZ_C 4096
#define U_RED_C 256
#define EDGE_H_C 1024
#define EDGE_OUT_C 512
#define NODE_H_C 512
#define E_HALF (N_EDGES_C / 2)

// ------------------------- device scratch -------------------------
__device__ __half g_bufA[(size_t)N_EDGES_C * EDGE_H_C];
__device__ __half g_bufB[(size_t)N_EDGES_C * EDGE_H_C];
__device__ __half g_bufC[(size_t)N_EDGES_C * NODE_H_C];   // CW-fused outputs (512-wide)
__device__ __half g_bufD[(size_t)N_EDGES_C * NODE_H_C];   // n1w1 outputs (512-wide)
__device__ __half g_oin [(size_t)N_NODES_C * NODE_H_C];
__device__ __half g_h2  [(size_t)N_NODES_C * NODE_H_C];
__device__ float  g_ur  [N_GRAPHS_C * U_RED_C];

// layer-0 small-K input: [x_row(9), x_col(9), ea(1), pad->32] + per-edge graph id
__device__ __half g_e19 [(size_t)(N_EDGES_C + 256) * 32];
__device__ int    g_gedge[N_EDGES_C];

// factorization tables
__device__ float  g_ue  [N_GRAPHS_C * EDGE_H_C];          // u_r @ W_u + e_b0
__device__ float  g_un  [N_GRAPHS_C * NODE_H_C];          // u_r @ W_u2 + n2_b0
__device__ float  g_addn[(size_t)N_NODES_C * NODE_H_C];   // row bias for n2 GEMM

// e_wf -> n1_w0 fusion tables
__device__ __half g_cw  [EDGE_H_C * NODE_H_C];            // e_wf @ n1_w0[9:521]
__device__ float  g_bb  [NODE_H_C];
__device__ float  g_pn1 [(size_t)N_NODES_C * NODE_H_C];   // bb + x[n] @ W_x (per node)
__device__ float  g_zero[NODE_H_C];

// weights packed [Kp, N] row-major fp16
__device__ __half g_w19h [32       * EDGE_H_C];
__device__ __half g_w1h  [EDGE_H_C * EDGE_H_C];
__device__ __half g_w2h  [EDGE_H_C * EDGE_H_C];
__device__ __half g_w3h  [EDGE_H_C * EDGE_H_C];
__device__ __half g_wfh  [EDGE_H_C * EDGE_OUT_C];
__device__ __half g_n1w0h[NODE_H_C * NODE_H_C];
__device__ __half g_n1w1h[NODE_H_C * NODE_H_C];
__device__ __half g_n2w0h[NODE_H_C * NODE_H_C];

__device__ int g_cnt[N_NODES_C];
__device__ int g_off[N_NODES_C + 1];
__device__ int g_cur[N_NODES_C];
__device__ int g_elist[N_EDGES_C];

// ------------------------- small helpers -------------------------
DI uint32_t smem_u32(const void* p) {
    return (uint32_t)__cvta_generic_to_shared(p);
}
DI void cp16(uint32_t dst, const void* src) {
    asm volatile("cp.async.cg.shared.global [%0], [%1], 16;\n" :: "r"(dst), "l"(src));
}
DI void cp_commit() { asm volatile("cp.async.commit_group;\n"); }
DI void cp_wait1()  { asm volatile("cp.async.wait_group 1;\n"); }

DI void ldm_x4(uint32_t addr, uint32_t& r0, uint32_t& r1, uint32_t& r2, uint32_t& r3) {
    asm volatile("ldmatrix.sync.aligned.m8n8.x4.shared.b16 {%0,%1,%2,%3}, [%4];\n"
                 : "=r"(r0), "=r"(r1), "=r"(r2), "=r"(r3) : "r"(addr));
}
DI void ldm_x4t(uint32_t addr, uint32_t& r0, uint32_t& r1, uint32_t& r2, uint32_t& r3) {
    asm volatile("ldmatrix.sync.aligned.m8n8.x4.trans.shared.b16 {%0,%1,%2,%3}, [%4];\n"
                 : "=r"(r0), "=r"(r1), "=r"(r2), "=r"(r3) : "r"(addr));
}
DI void mma16816(float* d, const uint32_t* a, const uint32_t* b) {
    asm volatile("mma.sync.aligned.m16n8k16.row.col.f32.f16.f16.f32 "
                 "{%0,%1,%2,%3}, {%4,%5,%6,%7}, {%8,%9}, {%0,%1,%2,%3};\n"
                 : "+f"(d[0]), "+f"(d[1]), "+f"(d[2]), "+f"(d[3])
                 : "r"(a[0]), "r"(a[1]), "r"(a[2]), "r"(a[3]),
                   "r"(b[0]), "r"(b[1]));
}

// --------------- weight pack: fp32 -> fp16, row permute + zero pad ---------------
struct Seg { int src0, dst0, n; };

__global__ void pack_weight(const float* __restrict__ src, __half* __restrict__ dst,
                            int N, int Kp, Seg a, Seg b, Seg c, Seg d) {
    int idx = blockIdx.x * blockDim.x + threadIdx.x;
    if (idx >= Kp * N) return;
    int r = idx / N, col = idx - r * N;
    float v = 0.f;
    if      (r >= a.dst0 && r < a.dst0 + a.n) v = src[(size_t)(a.src0 + r - a.dst0) * N + col];
    else if (r >= b.dst0 && r < b.dst0 + b.n) v = src[(size_t)(b.src0 + r - b.dst0) * N + col];
    else if (r >= c.dst0 && r < c.dst0 + c.n) v = src[(size_t)(c.src0 + r - c.dst0) * N + col];
    else if (r >= d.dst0 && r < d.dst0 + d.n) v = src[(size_t)(d.src0 + r - d.dst0) * N + col];
    dst[idx] = __float2half(v);
}

// --------------- dim reduction: u_r = u @ w_dr + b_dr (fp32, tiny) ---------------
__global__ void dimred_kernel(const float* __restrict__ u, const float* __restrict__ w,
                              const float* __restrict__ b) {
    __shared__ float red[8][32];
    int g = blockIdx.x, ct = blockIdx.y;
    int kg = threadIdx.x >> 5, cl = threadIdx.x & 31;
    int c = ct * 32 + cl;
    const float* up = u + (size_t)g * U_SZ_C + kg * 512;
    const float* wp = w + (size_t)(kg * 512) * U_RED_C + c;
    float s = 0.f;
    #pragma unroll 8
    for (int k = 0; k < 512; k++) s += up[k] * wp[(size_t)k * U_RED_C];
    red[kg][cl] = s;
    __syncthreads();
    if (kg == 0) {
        float t = b[c];
        #pragma unroll
        for (int i = 0; i < 8; i++) t += red[i][cl];
        g_ur[g * U_RED_C + c] = t;
    }
}

// --------------- bias-table precomputes -------------------------------------------
__global__ void ue_kernel(const float* __restrict__ e_w0, const float* __restrict__ e_b0) {
    int c = blockIdx.y * 256 + threadIdx.x;
    int g = blockIdx.x;
    float s = e_b0[c];
    #pragma unroll 4
    for (int j = 0; j < U_RED_C; j++)
        s += g_ur[g * U_RED_C + j] * e_w0[(size_t)(19 + j) * EDGE_H_C + c];
    g_ue[g * EDGE_H_C + c] = s;
}

__global__ void un_kernel(const float* __restrict__ n2_w0, const float* __restrict__ n2_b0) {
    int c = blockIdx.y * 256 + threadIdx.x;
    int g = blockIdx.x;
    float s = n2_b0[c];
    #pragma unroll 4
    for (int j = 0; j < U_RED_C; j++)
        s += g_ur[g * U_RED_C + j] * n2_w0[(size_t)(521 + j) * NODE_H_C + c];
    g_un[g * NODE_H_C + c] = s;
}

__global__ void addn_kernel(const float* __restrict__ x, const int* __restrict__ batch,
                            const float* __restrict__ n2_w0) {
    int c = blockIdx.x * 256 + threadIdx.x;
    int n = blockIdx.y;
    int g = batch[n];
    float s = g_un[g * NODE_H_C + c];
    #pragma unroll
    for (int j = 0; j < 9; j++)
        s += x[(size_t)n * 9 + j] * n2_w0[(size_t)j * NODE_H_C + c];
    g_addn[(size_t)n * NODE_H_C + c] = s;
}

__global__ void bb_kernel(const float* __restrict__ e_bf, const float* __restrict__ n1_w0,
                          const float* __restrict__ n1_b0) {
    int c = blockIdx.x * 256 + threadIdx.x;
    float s = n1_b0[c];
    #pragma unroll 4
    for (int j = 0; j < EDGE_OUT_C; j++)
        s += e_bf[j] * n1_w0[(size_t)(9 + j) * NODE_H_C + c];
    g_bb[c] = s;
}
__global__ void pn1_kernel(const float* __restrict__ x, const float* __restrict__ n1_w0) {
    int c = blockIdx.x * 256 + threadIdx.x;
    int n = blockIdx.y;
    float s = g_bb[c];
    #pragma unroll
    for (int j = 0; j < 9; j++)
        s += x[(size_t)n * 9 + j] * n1_w0[(size_t)j * NODE_H_C + c];
    g_pn1[(size_t)n * NODE_H_C + c] = s;
}

// --------------- build e19: [x_row, x_col, ea, pad] fp16 + per-edge graph id ------
__global__ void build_e19_kernel(const float* __restrict__ x, const float* __restrict__ ea,
                                 const int* __restrict__ ei, const int* __restrict__ batch) {
    int e = blockIdx.x * 8 + (threadIdx.x >> 5);
    int lane = threadIdx.x & 31;
    int r = ei[e], c = ei[N_EDGES_C + e];
    float v = 0.f;
    if (lane < 9)        v = x[(size_t)r * 9 + lane];
    else if (lane < 18)  v = x[(size_t)c * 9 + (lane - 9)];
    else if (lane == 18) v = ea[e];
    g_e19[(size_t)e * 32 + lane] = __float2half(v);
    if (lane == 0) g_gedge[e] = batch[r];
}

// ------------------------- fp16 tensor-core GEMM ---------------------------------
// BMODE: 0 = column bias vector, 1 = per-row fp32 table, 2 = indexed table
#define BM 128
#define BN 256
#define BKK 32
#define GT 256
#define STG 3
#define A_ST (BM * 40)
#define B_ST (BKK * 264)
#define GEMM_SMEM (STG * (A_ST + B_ST) * 2)

template<bool RELU, int BMODE>
__global__ __launch_bounds__(GT, 1)
void gemm_kernel(const __half* __restrict__ A, int lda,
                 const __half* __restrict__ B, int ldb,
                 const float* __restrict__ bias,
                 const int* __restrict__ bidx,
                 __half* __restrict__ C, int ldc, int K) {
    extern __shared__ __half sm[];
    __half* Asm = sm;
    __half* Bsm = sm + STG * A_ST;

    const int tid  = threadIdx.x;
    const int lane = tid & 31, warp = tid >> 5;
    const int wm = warp & 1;
    const int wn = warp >> 1;
    const int bm = blockIdx.y, bn = blockIdx.x;

    const __half* Ag = A + (size_t)bm * BM * lda;
    const __half* Bg = B + (size_t)bn * BN;

    float acc[4][8][4];
    #pragma unroll
    for (int i = 0; i < 4; i++)
        #pragma unroll
        for (int j = 0; j < 8; j++)
            #pragma unroll
            for (int k = 0; k < 4; k++) acc[i][j][k] = 0.f;

    const int KT = K / BKK;

    auto load = [&](int kt, int st) {
        __half* as = Asm + st * A_ST;
        __half* bs = Bsm + st * B_ST;
        #pragma unroll
        for (int i = 0; i < 2; i++) {
            int ch = tid + i * GT;
            int r = ch >> 2, cc = (ch & 3) << 3;
            cp16(smem_u32(as + r * 40 + cc), Ag + (size_t)r * lda + kt * BKK + cc);
        }
        #pragma unroll
        for (int i = 0; i < 4; i++) {
            int ch = tid + i * GT;
            int r = ch >> 5, cc = (ch & 31) << 3;
            cp16(smem_u32(bs + r * 264 + cc), Bg + (size_t)(kt * BKK + r) * ldb + cc);
        }
        cp_commit();
    };

    load(0, 0);
    if (KT > 1) load(1, 1);
    else        cp_commit();   // empty group keeps wait_group(1) accounting valid

    for (int kt = 0; kt < KT; kt++) {
        cp_wait1();
        __syncthreads();
        const int st = kt % 3;
        if (kt + 2 < KT) load(kt + 2, (kt + 2) % 3);
        else             cp_commit();

        #pragma unroll
        for (int ks = 0; ks < 2; ks++) {
            uint32_t afr[4][4];
            {
                const __half* as = Asm + st * A_ST;
                int row = wm * 64 + (lane & 15);
                int col = ks * 16 + (lane >> 4) * 8;
                #pragma unroll
                for (int mi = 0; mi < 4; mi++)
                    ldm_x4(smem_u32(as + (row + mi * 16) * 40 + col),
                           afr[mi][0], afr[mi][1], afr[mi][2], afr[mi][3]);
            }
            uint32_t bfr[8][2];
            {
                const __half* bs = Bsm + st * B_ST;
                int row = ks * 16 + ((lane >> 3) & 1) * 8 + (lane & 7);
                #pragma unroll
                for (int p = 0; p < 4; p++) {
                    int col = wn * 64 + p * 16 + (lane >> 4) * 8;
                    uint32_t r0, r1, r2, r3;
                    ldm_x4t(smem_u32(bs + row * 264 + col), r0, r1, r2, r3);
                    bfr[2 * p][0] = r0;     bfr[2 * p][1] = r1;
                    bfr[2 * p + 1][0] = r2; bfr[2 * p + 1][1] = r3;
                }
            }
            #pragma unroll
            for (int mi = 0; mi < 4; mi++)
                #pragma unroll
                for (int nj = 0; nj < 8; nj++)
                    mma16816(acc[mi][nj], afr[mi], bfr[nj]);
        }
    }

    // epilogue
    int row0 = bm * BM + wm * 64;
    int col0 = bn * BN + wn * 64;
    #pragma unroll
    for (int mi = 0; mi < 4; mi++) {
        #pragma unroll
        for (int h = 0; h < 2; h++) {
            int r = row0 + mi * 16 + (lane >> 2) + h * 8;
            const float* tb = bias;
            if (BMODE == 1) tb = bias + (size_t)r * ldc;
            if (BMODE == 2) tb = bias + (size_t)bidx[r] * ldc;
            #pragma unroll
            for (int nj = 0; nj < 8; nj++) {
                int c = col0 + nj * 8 + (lane & 3) * 2;
                float b0 = tb[c], b1 = tb[c + 1];
                float f0 = acc[mi][nj][2 * h] + b0;
                float f1 = acc[mi][nj][2 * h + 1] + b1;
                if (RELU) { f0 = fmaxf(f0, 0.f); f1 = fmaxf(f1, 0.f); }
                *reinterpret_cast<__half2*>(C + (size_t)r * ldc + c) = __floats2half2_rn(f0, f1);
            }
        }
    }
}

// --------------- scatter-mean: CSR build + gather reduce -------------------------
__global__ void zero_cnt_kernel() {
    int i = blockIdx.x * blockDim.x + threadIdx.x;
    if (i < N_NODES_C) { g_cnt[i] = 0; g_cur[i] = 0; }
}
__global__ void count_kernel(const int* __restrict__ ei) {
    int e = blockIdx.x * blockDim.x + threadIdx.x;
    if (e < N_EDGES_C) atomicAdd(&g_cnt[ei[e]], 1);
}
__global__ void scan_kernel() {
    __shared__ int ws[32];
    int t = threadIdx.x;
    int base = t * 16;
    int v[16]; int s = 0;
    #pragma unroll
    for (int i = 0; i < 16; i++) { v[i] = s; s += g_cnt[base + i]; }
    int lane = t & 31, w = t >> 5;
    int x = s;
    #pragma unroll
    for (int o = 1; o < 32; o <<= 1) { int y = __shfl_up_sync(~0u, x, o); if (lane >= o) x += y; }
    if (lane == 31) ws[w] = x;
    __syncthreads();
    if (w == 0) {
        int y = ws[lane];
        #pragma unroll
        for (int o = 1; o < 32; o <<= 1) { int z = __shfl_up_sync(~0u, y, o); if (lane >= o) y += z; }
        ws[lane] = y;
    }
    __syncthreads();
    int pre = (x - s) + (w > 0 ? ws[w - 1] : 0);
    #pragma unroll
    for (int i = 0; i < 16; i++) g_off[base + i] = pre + v[i];
    if (t == 1023) g_off[N_NODES_C] = pre + s;
}
__global__ void fill_kernel(const int* __restrict__ ei) {
    int e = blockIdx.x * blockDim.x + threadIdx.x;
    if (e < N_EDGES_C) {
        int r = ei[e];
        int p = g_off[r] + atomicAdd(&g_cur[r], 1);
        g_elist[p] = e;
    }
}
// block per node: mean over its edges of h_n (g_bufD [E,512] fp16) -> oin
__global__ void node_reduce_kernel() {
    int n = blockIdx.x;
    int t = threadIdx.x;  // 128
    int deg = g_cnt[n], start = g_off[n];
    float a0 = 0.f, a1 = 0.f, a2 = 0.f, a3 = 0.f;
    for (int i = 0; i < deg; i++) {
        int e = g_elist[start + i];
        uint2 v = *reinterpret_cast<const uint2*>(g_bufD + (size_t)e * NODE_H_C + t * 4);
        __half2 h0 = *reinterpret_cast<__half2*>(&v.x);
        __half2 h1 = *reinterpret_cast<__half2*>(&v.y);
        float2 f0 = __half22float2(h0), f1 = __half22float2(h1);
        a0 += f0.x; a1 += f0.y; a2 += f1.x; a3 += f1.y;
    }
    float inv = 1.f / (float)(deg > 0 ? deg : 1);
    __half2 o0 = __floats2half2_rn(a0 * inv, a1 * inv);
    __half2 o1 = __floats2half2_rn(a2 * inv, a3 * inv);
    uint2 ov;
    ov.x = *reinterpret_cast<uint32_t*>(&o0);
    ov.y = *reinterpret_cast<uint32_t*>(&o1);
    *reinterpret_cast<uint2*>(g_oin + (size_t)n * NODE_H_C + t * 4) = ov;
}

// --------------- final dot: out[n] = h2[n,:] . n2_w1 + b --------------------------
__global__ void final_kernel(const float* __restrict__ w, const float* __restrict__ b,
                             float* __restrict__ out) {
    int n = blockIdx.x * 8 + (threadIdx.x >> 5);
    int lane = threadIdx.x & 31;
    const __half* h = g_h2 + (size_t)n * NODE_H_C;
    float s = 0.f;
    #pragma unroll
    for (int j = 0; j < 16; j++) {
        int c = lane + j * 32;
        s += __half2float(h[c]) * w[c];
    }
    #pragma unroll
    for (int o = 16; o > 0; o >>= 1) s += __shfl_xor_sync(~0u, s, o);
    if (lane == 0) out[n] = s + b[0];
}

// ------------------------- host launcher -----------------------------------------
extern "C" void kernel_launch(void* const* d_in, const int* in_sizes, int n_in,
                              void* d_out, int out_size) {
    (void)in_sizes; (void)n_in; (void)out_size;
    const float* x      = (const float*)d_in[0];
    const float* ea     = (const float*)d_in[1];
    const float* u      = (const float*)d_in[2];
    const int*   ei     = (const int*)d_in[3];
    const int*   batch  = (const int*)d_in[4];
    const float* w_dr   = (const float*)d_in[5];
    const float* b_dr   = (const float*)d_in[6];
    const float* e_w0   = (const float*)d_in[7];
    const float* e_b0   = (const float*)d_in[8];
    const float* e_w1   = (const float*)d_in[9];
    const float* e_b1   = (const float*)d_in[10];
    const float* e_w2   = (const float*)d_in[11];
    const float* e_b2   = (const float*)d_in[12];
    const float* e_w3   = (const float*)d_in[13];
    const float* e_b3   = (const float*)d_in[14];
    const float* e_wf   = (const float*)d_in[15];
    const float* e_bf   = (const float*)d_in[16];
    const float* n1_w0  = (const float*)d_in[17];
    const float* n1_b0  = (const float*)d_in[18];
    const float* n1_w1  = (const float*)d_in[19];
    const float* n1_b1  = (const float*)d_in[20];
    const float* n2_w0  = (const float*)d_in[21];
    const float* n2_b0  = (const float*)d_in[22];
    const float* n2_w1  = (const float*)d_in[23];
    const float* n2_b1  = (const float*)d_in[24];
    float* out = (float*)d_out;

    __half *w19h, *w1h, *w2h, *w3h, *wfh, *n1w0h, *n1w1h, *n2w0h, *cw;
    __half *bufA, *bufB, *bufC, *bufD, *oin, *h2, *e19;
    float  *addn, *pn1, *zerov, *uef;
    int    *gedge;
    cudaGetSymbolAddress((void**)&w19h,  g_w19h);
    cudaGetSymbolAddress((void**)&w1h,   g_w1h);
    cudaGetSymbolAddress((void**)&w2h,   g_w2h);
    cudaGetSymbolAddress((void**)&w3h,   g_w3h);
    cudaGetSymbolAddress((void**)&wfh,   g_wfh);
    cudaGetSymbolAddress((void**)&n1w0h, g_n1w0h);
    cudaGetSymbolAddress((void**)&n1w1h, g_n1w1h);
    cudaGetSymbolAddress((void**)&n2w0h, g_n2w0h);
    cudaGetSymbolAddress((void**)&cw,    g_cw);
    cudaGetSymbolAddress((void**)&bufA, g_bufA);
    cudaGetSymbolAddress((void**)&bufB, g_bufB);
    cudaGetSymbolAddress((void**)&bufC, g_bufC);
    cudaGetSymbolAddress((void**)&bufD, g_bufD);
    cudaGetSymbolAddress((void**)&oin,  g_oin);
    cudaGetSymbolAddress((void**)&h2,   g_h2);
    cudaGetSymbolAddress((void**)&e19,  g_e19);
    cudaGetSymbolAddress((void**)&addn, g_addn);
    cudaGetSymbolAddress((void**)&pn1,  g_pn1);
    cudaGetSymbolAddress((void**)&zerov, g_zero);
    cudaGetSymbolAddress((void**)&uef,  g_ue);
    cudaGetSymbolAddress((void**)&gedge, g_gedge);

    cudaFuncSetAttribute((const void*)gemm_kernel<true,  0>, cudaFuncAttributeMaxDynamicSharedMemorySize, GEMM_SMEM);
    cudaFuncSetAttribute((const void*)gemm_kernel<false, 0>, cudaFuncAttributeMaxDynamicSharedMemorySize, GEMM_SMEM);
    cudaFuncSetAttribute((const void*)gemm_kernel<true,  1>, cudaFuncAttributeMaxDynamicSharedMemorySize, GEMM_SMEM);
    cudaFuncSetAttribute((const void*)gemm_kernel<true,  2>, cudaFuncAttributeMaxDynamicSharedMemorySize, GEMM_SMEM);

    // streams + events — SAME footprint as the R13 clean pass (2 extra streams)
    static cudaStream_t s2 = nullptr, s3 = nullptr;
    static cudaEvent_t evFork = nullptr, evUE = nullptr, evE19 = nullptr,
                       evW123 = nullptr, evJoin = nullptr, evB = nullptr;
    if (s2 == nullptr) {
        cudaStreamCreateWithFlags(&s2, cudaStreamNonBlocking);
        cudaStreamCreateWithFlags(&s3, cudaStreamNonBlocking);
        cudaEventCreateWithFlags(&evFork, cudaEventDisableTiming);
        cudaEventCreateWithFlags(&evUE,   cudaEventDisableTiming);
        cudaEventCreateWithFlags(&evE19,  cudaEventDisableTiming);
        cudaEventCreateWithFlags(&evW123, cudaEventDisableTiming);
        cudaEventCreateWithFlags(&evJoin, cudaEventDisableTiming);
        cudaEventCreateWithFlags(&evB,    cudaEventDisableTiming);
    }

    const Seg Z{0, 0, 0};
    auto gsz = [](int n) { return (n + 255) / 256; };

    // ---- fork side work off the capture origin ----
    cudaEventRecord(evFork, 0);
    cudaStreamWaitEvent(s2, evFork, 0);
    cudaStreamWaitEvent(s3, evFork, 0);

    // ---- side stream s2: ue first (l0 dependency), then packs, tables, CSR ----
    dimred_kernel<<<dim3(16, 8), 256, 0, s2>>>(u, w_dr, b_dr);
    ue_kernel<<<dim3(16, 4), 256, 0, s2>>>(e_w0, e_b0);
    cudaEventRecord(evUE, s2);
    pack_weight<<<gsz(1024 * 1024), 256, 0, s2>>>(e_w1, w1h, 1024, 1024, Seg{0, 0, 1024}, Z, Z, Z);
    pack_weight<<<gsz(1024 * 1024), 256, 0, s2>>>(e_w2, w2h, 1024, 1024, Seg{0, 0, 1024}, Z, Z, Z);
    pack_weight<<<gsz(1024 * 1024), 256, 0, s2>>>(e_w3, w3h, 1024, 1024, Seg{0, 0, 1024}, Z, Z, Z);
    cudaEventRecord(evW123, s2);
    pack_weight<<<gsz(1024 * 512),  256, 0, s2>>>(e_wf, wfh, 512, 1024, Seg{0, 0, 1024}, Z, Z, Z);
    pack_weight<<<gsz(512 * 512),   256, 0, s2>>>(n1_w0, n1w0h, 512, 512, Seg{9, 0, 512}, Z, Z, Z);
    pack_weight<<<gsz(512 * 512),   256, 0, s2>>>(n1_w1, n1w1h, 512, 512, Seg{0, 0, 512}, Z, Z, Z);
    pack_weight<<<gsz(512 * 512),   256, 0, s2>>>(n2_w0, n2w0h, 512, 512, Seg{9, 0, 512}, Z, Z, Z);
    un_kernel<<<dim3(16, 2), 256, 0, s2>>>(n2_w0, n2_b0);
    addn_kernel<<<dim3(2, N_NODES_C), 256, 0, s2>>>(x, batch, n2_w0);
    bb_kernel<<<2, 256, 0, s2>>>(e_bf, n1_w0, n1_b0);
    pn1_kernel<<<dim3(2, N_NODES_C), 256, 0, s2>>>(x, n1_w0);
    gemm_kernel<false, 0><<<dim3(2, 8), GT, GEMM_SMEM, s2>>>(wfh, 512, n1w0h, 512, zerov, nullptr, cw, 512, 512);
    zero_cnt_kernel<<<N_NODES_C / 256, 256, 0, s2>>>();
    count_kernel<<<N_EDGES_C / 256, 256, 0, s2>>>(ei);
    scan_kernel<<<1, 1024, 0, s2>>>();
    fill_kernel<<<N_EDGES_C / 256, 256, 0, s2>>>(ei);
    cudaEventRecord(evJoin, s2);

    // ---- main: e19 build prologue ----
    pack_weight<<<gsz(32 * 1024), 256>>>(e_w0, w19h, 1024, 32, Seg{0, 0, 19}, Z, Z, Z);
    build_e19_kernel<<<N_EDGES_C / 8, 256>>>(x, ea, ei, batch);
    cudaEventRecord(evE19, 0);

    const int MT2 = E_HALF / BM;        // 512 M-tiles per chain
    const int MTN = N_NODES_C / BM;     // 128

    // per-chain GEMM sequence (c = 0 on stream 0, c = 1 on s3)
    auto run_chain = [&](cudaStream_t st, int c) {
        const size_t o32  = (size_t)c * E_HALF * 32;
        const size_t o1k  = (size_t)c * E_HALF * EDGE_H_C;
        const size_t o512 = (size_t)c * E_HALF * NODE_H_C;
        if (st != 0) cudaStreamWaitEvent(st, evE19, 0);
        cudaStreamWaitEvent(st, evUE, 0);
        gemm_kernel<true, 2><<<dim3(4, MT2), GT, GEMM_SMEM, st>>>(
            e19 + o32, 32, w19h, 1024, uef, gedge + c * E_HALF, bufA + o1k, 1024, 32);
        cudaStreamWaitEvent(st, evW123, 0);
        gemm_kernel<true, 0><<<dim3(4, MT2), GT, GEMM_SMEM, st>>>(
            bufA + o1k, 1024, w1h, 1024, e_b1, nullptr, bufB + o1k, 1024, 1024);
        gemm_kernel<true, 0><<<dim3(4, MT2), GT, GEMM_SMEM, st>>>(
            bufB + o1k, 1024, w2h, 1024, e_b2, nullptr, bufA + o1k, 1024, 1024);
        gemm_kernel<true, 0><<<dim3(4, MT2), GT, GEMM_SMEM, st>>>(
            bufA + o1k, 1024, w3h, 1024, e_b3, nullptr, bufB + o1k, 1024, 1024);
        cudaStreamWaitEvent(st, evJoin, 0);
        gemm_kernel<true, 2><<<dim3(2, MT2), GT, GEMM_SMEM, st>>>(
            bufB + o1k, 1024, cw, 512, pn1, ei + N_EDGES_C + c * E_HALF, bufC + o512, 512, 1024);
        gemm_kernel<true, 0><<<dim3(2, MT2), GT, GEMM_SMEM, st>>>(
            bufC + o512, 512, n1w1h, 512, n1_b1, nullptr, bufD + o512, 512, 512);
    };

    run_chain(0, 0);
    run_chain(s3, 1);
    cudaEventRecord(evB, s3);

    // ---- join both chains -> scatter-mean -> node MLP 2 -> final ----
    cudaStreamWaitEvent(0, evB, 0);
    node_reduce_kernel<<<N_NODES_C, 128>>>();
    gemm_kernel<true, 1><<<dim3(2, MTN), GT, GEMM_SMEM>>>(oin, 512, n2w0h, 512, addn, nullptr, h2, 512, 512);
    final_kernel<<<N_NODES_C / 8, 256>>>(n2_w1, n2_b1, out);
}

// round 16
// speedup vs baseline: 1.2292x; 1.0061x over previous
#include <cuda_runtime.h>
#include <cuda_fp16.h>
#include <cstdint>

#define DI __device__ __forceinline__

// ------------------------- problem sizes -------------------------
#define N_NODES_C 16384
#define N_EDGES_C 131072
#define N_GRAPHS_C 16
#define U_SZ_C 4096
#define U_RED_C 256
#define EDGE_H_C 1024
#define EDGE_OUT_C 512
#define NODE_H_C 512
#define E_HALF (N_EDGES_C / 2)

// ------------------------- device scratch -------------------------
__device__ __half g_bufA[(size_t)N_EDGES_C * EDGE_H_C];
__device__ __half g_bufB[(size_t)N_EDGES_C * EDGE_H_C];
__device__ __half g_bufC[(size_t)N_EDGES_C * NODE_H_C];   // CW-fused outputs (512-wide)
__device__ __half g_bufD[(size_t)N_EDGES_C * NODE_H_C];   // n1w1 outputs (512-wide)
__device__ __half g_oin [(size_t)N_NODES_C * NODE_H_C];
__device__ float  g_part[2 * N_NODES_C];                   // n2+final partial dots
__device__ float  g_ur  [N_GRAPHS_C * U_RED_C];

// layer-0 small-K input: [x_row(9), x_col(9), ea(1), pad->32] + per-edge graph id
__device__ __half g_e19 [(size_t)(N_EDGES_C + 256) * 32];
__device__ int    g_gedge[N_EDGES_C];

// factorization tables
__device__ float  g_ue  [N_GRAPHS_C * EDGE_H_C];          // u_r @ W_u + e_b0
__device__ float  g_un  [N_GRAPHS_C * NODE_H_C];          // u_r @ W_u2 + n2_b0
__device__ __half g_addnh[(size_t)N_NODES_C * NODE_H_C];  // fp16 row bias for n2 GEMM

// e_wf -> n1_w0 fusion tables
__device__ __half g_cw  [EDGE_H_C * NODE_H_C];            // e_wf @ n1_w0[9:521]
__device__ float  g_bb  [NODE_H_C];
__device__ __half g_pn1h[(size_t)N_NODES_C * NODE_H_C];   // fp16 bb + x[n] @ W_x (per node)
__device__ float  g_zero[NODE_H_C];

// weights packed [Kp, N] row-major fp16
__device__ __half g_w19h [32       * EDGE_H_C];
__device__ __half g_w1h  [EDGE_H_C * EDGE_H_C];
__device__ __half g_w2h  [EDGE_H_C * EDGE_H_C];
__device__ __half g_w3h  [EDGE_H_C * EDGE_H_C];
__device__ __half g_wfh  [EDGE_H_C * EDGE_OUT_C];
__device__ __half g_n1w0h[NODE_H_C * NODE_H_C];
__device__ __half g_n1w1h[NODE_H_C * NODE_H_C];
__device__ __half g_n2w0h[NODE_H_C * NODE_H_C];

__device__ int g_cnt[N_NODES_C];
__device__ int g_off[N_NODES_C + 1];
__device__ int g_cur[N_NODES_C];
__device__ int g_elist[N_EDGES_C];

// ------------------------- small helpers -------------------------
DI uint32_t smem_u32(const void* p) {
    return (uint32_t)__cvta_generic_to_shared(p);
}
DI void cp16(uint32_t dst, const void* src) {
    asm volatile("cp.async.cg.shared.global [%0], [%1], 16;\n" :: "r"(dst), "l"(src));
}
DI void cp_commit() { asm volatile("cp.async.commit_group;\n"); }
DI void cp_wait1()  { asm volatile("cp.async.wait_group 1;\n"); }

DI void ldm_x4(uint32_t addr, uint32_t& r0, uint32_t& r1, uint32_t& r2, uint32_t& r3) {
    asm volatile("ldmatrix.sync.aligned.m8n8.x4.shared.b16 {%0,%1,%2,%3}, [%4];\n"
                 : "=r"(r0), "=r"(r1), "=r"(r2), "=r"(r3) : "r"(addr));
}
DI void ldm_x4t(uint32_t addr, uint32_t& r0, uint32_t& r1, uint32_t& r2, uint32_t& r3) {
    asm volatile("ldmatrix.sync.aligned.m8n8.x4.trans.shared.b16 {%0,%1,%2,%3}, [%4];\n"
                 : "=r"(r0), "=r"(r1), "=r"(r2), "=r"(r3) : "r"(addr));
}
DI void mma16816(float* d, const uint32_t* a, const uint32_t* b) {
    asm volatile("mma.sync.aligned.m16n8k16.row.col.f32.f16.f16.f32 "
                 "{%0,%1,%2,%3}, {%4,%5,%6,%7}, {%8,%9}, {%0,%1,%2,%3};\n"
                 : "+f"(d[0]), "+f"(d[1]), "+f"(d[2]), "+f"(d[3])
                 : "r"(a[0]), "r"(a[1]), "r"(a[2]), "r"(a[3]),
                   "r"(b[0]), "r"(b[1]));
}

// --------------- weight pack: fp32 -> fp16, row permute + zero pad ---------------
struct Seg { int src0, dst0, n; };

__global__ void pack_weight(const float* __restrict__ src, __half* __restrict__ dst,
                            int N, int Kp, Seg a, Seg b, Seg c, Seg d) {
    int idx = blockIdx.x * blockDim.x + threadIdx.x;
    if (idx >= Kp * N) return;
    int r = idx / N, col = idx - r * N;
    float v = 0.f;
    if      (r >= a.dst0 && r < a.dst0 + a.n) v = src[(size_t)(a.src0 + r - a.dst0) * N + col];
    else if (r >= b.dst0 && r < b.dst0 + b.n) v = src[(size_t)(b.src0 + r - b.dst0) * N + col];
    else if (r >= c.dst0 && r < c.dst0 + c.n) v = src[(size_t)(c.src0 + r - c.dst0) * N + col];
    else if (r >= d.dst0 && r < d.dst0 + d.n) v = src[(size_t)(d.src0 + r - d.dst0) * N + col];
    dst[idx] = __float2half(v);
}

// --------------- dim reduction: u_r = u @ w_dr + b_dr (fp32, tiny) ---------------
__global__ void dimred_kernel(const float* __restrict__ u, const float* __restrict__ w,
                              const float* __restrict__ b) {
    __shared__ float red[8][32];
    int g = blockIdx.x, ct = blockIdx.y;
    int kg = threadIdx.x >> 5, cl = threadIdx.x & 31;
    int c = ct * 32 + cl;
    const float* up = u + (size_t)g * U_SZ_C + kg * 512;
    const float* wp = w + (size_t)(kg * 512) * U_RED_C + c;
    float s = 0.f;
    #pragma unroll 8
    for (int k = 0; k < 512; k++) s += up[k] * wp[(size_t)k * U_RED_C];
    red[kg][cl] = s;
    __syncthreads();
    if (kg == 0) {
        float t = b[c];
        #pragma unroll
        for (int i = 0; i < 8; i++) t += red[i][cl];
        g_ur[g * U_RED_C + c] = t;
    }
}

// --------------- bias-table precomputes -------------------------------------------
__global__ void ue_kernel(const float* __restrict__ e_w0, const float* __restrict__ e_b0) {
    int c = blockIdx.y * 256 + threadIdx.x;
    int g = blockIdx.x;
    float s = e_b0[c];
    #pragma unroll 4
    for (int j = 0; j < U_RED_C; j++)
        s += g_ur[g * U_RED_C + j] * e_w0[(size_t)(19 + j) * EDGE_H_C + c];
    g_ue[g * EDGE_H_C + c] = s;
}

__global__ void un_kernel(const float* __restrict__ n2_w0, const float* __restrict__ n2_b0) {
    int c = blockIdx.y * 256 + threadIdx.x;
    int g = blockIdx.x;
    float s = n2_b0[c];
    #pragma unroll 4
    for (int j = 0; j < U_RED_C; j++)
        s += g_ur[g * U_RED_C + j] * n2_w0[(size_t)(521 + j) * NODE_H_C + c];
    g_un[g * NODE_H_C + c] = s;
}

__global__ void addn_kernel(const float* __restrict__ x, const int* __restrict__ batch,
                            const float* __restrict__ n2_w0) {
    int c = blockIdx.x * 256 + threadIdx.x;
    int n = blockIdx.y;
    int g = batch[n];
    float s = g_un[g * NODE_H_C + c];
    #pragma unroll
    for (int j = 0; j < 9; j++)
        s += x[(size_t)n * 9 + j] * n2_w0[(size_t)j * NODE_H_C + c];
    g_addnh[(size_t)n * NODE_H_C + c] = __float2half(s);
}

__global__ void bb_kernel(const float* __restrict__ e_bf, const float* __restrict__ n1_w0,
                          const float* __restrict__ n1_b0) {
    int c = blockIdx.x * 256 + threadIdx.x;
    float s = n1_b0[c];
    #pragma unroll 4
    for (int j = 0; j < EDGE_OUT_C; j++)
        s += e_bf[j] * n1_w0[(size_t)(9 + j) * NODE_H_C + c];
    g_bb[c] = s;
}
__global__ void pn1_kernel(const float* __restrict__ x, const float* __restrict__ n1_w0) {
    int c = blockIdx.x * 256 + threadIdx.x;
    int n = blockIdx.y;
    float s = g_bb[c];
    #pragma unroll
    for (int j = 0; j < 9; j++)
        s += x[(size_t)n * 9 + j] * n1_w0[(size_t)j * NODE_H_C + c];
    g_pn1h[(size_t)n * NODE_H_C + c] = __float2half(s);
}

// --------------- build e19: [x_row, x_col, ea, pad] fp16 + per-edge graph id ------
__global__ void build_e19_kernel(const float* __restrict__ x, const float* __restrict__ ea,
                                 const int* __restrict__ ei, const int* __restrict__ batch) {
    int e = blockIdx.x * 8 + (threadIdx.x >> 5);
    int lane = threadIdx.x & 31;
    int r = ei[e], c = ei[N_EDGES_C + e];
    float v = 0.f;
    if (lane < 9)        v = x[(size_t)r * 9 + lane];
    else if (lane < 18)  v = x[(size_t)c * 9 + (lane - 9)];
    else if (lane == 18) v = ea[e];
    g_e19[(size_t)e * 32 + lane] = __float2half(v);
    if (lane == 0) g_gedge[e] = batch[r];
}

// ------------------------- fp16 tensor-core GEMM ---------------------------------
// BMODE: 0 = column fp32 bias vector
//        2 = indexed fp32 table  bias[bidx[r]*ldc + c]
//        3 = indexed fp16 table  hbias[bidx[r]*ldc + c]
// FINAL: fused final dot — out_part[bn*M + r] = sum_c relu(acc + hbias[r*ldc+c]) * fw[c]
#define BM 128
#define BN 256
#define BKK 32
#define GT 256
#define STG 3
#define A_ST (BM * 40)
#define B_ST (BKK * 264)
#define GEMM_SMEM (STG * (A_ST + B_ST) * 2)

template<bool RELU, int BMODE, bool FINAL>
__global__ __launch_bounds__(GT, 1)
void gemm_kernel(const __half* __restrict__ A, int lda,
                 const __half* __restrict__ B, int ldb,
                 const float* __restrict__ bias,
                 const __half* __restrict__ hbias,
                 const float* __restrict__ fw,
                 const int* __restrict__ bidx,
                 __half* __restrict__ C, float* __restrict__ part,
                 int ldc, int K) {
    extern __shared__ __half sm[];
    __half* Asm = sm;
    __half* Bsm = sm + STG * A_ST;

    const int tid  = threadIdx.x;
    const int lane = tid & 31, warp = tid >> 5;
    const int wm = warp & 1;
    const int wn = warp >> 1;
    const int bm = blockIdx.y, bn = blockIdx.x;

    const __half* Ag = A + (size_t)bm * BM * lda;
    const __half* Bg = B + (size_t)bn * BN;

    float acc[4][8][4];
    #pragma unroll
    for (int i = 0; i < 4; i++)
        #pragma unroll
        for (int j = 0; j < 8; j++)
            #pragma unroll
            for (int k = 0; k < 4; k++) acc[i][j][k] = 0.f;

    const int KT = K / BKK;

    auto load = [&](int kt, int st) {
        __half* as = Asm + st * A_ST;
        __half* bs = Bsm + st * B_ST;
        #pragma unroll
        for (int i = 0; i < 2; i++) {
            int ch = tid + i * GT;
            int r = ch >> 2, cc = (ch & 3) << 3;
            cp16(smem_u32(as + r * 40 + cc), Ag + (size_t)r * lda + kt * BKK + cc);
        }
        #pragma unroll
        for (int i = 0; i < 4; i++) {
            int ch = tid + i * GT;
            int r = ch >> 5, cc = (ch & 31) << 3;
            cp16(smem_u32(bs + r * 264 + cc), Bg + (size_t)(kt * BKK + r) * ldb + cc);
        }
        cp_commit();
    };

    load(0, 0);
    if (KT > 1) load(1, 1);
    else        cp_commit();   // empty group keeps wait_group(1) accounting valid

    for (int kt = 0; kt < KT; kt++) {
        cp_wait1();
        __syncthreads();
        const int st = kt % 3;
        if (kt + 2 < KT) load(kt + 2, (kt + 2) % 3);
        else             cp_commit();

        #pragma unroll
        for (int ks = 0; ks < 2; ks++) {
            uint32_t afr[4][4];
            {
                const __half* as = Asm + st * A_ST;
                int row = wm * 64 + (lane & 15);
                int col = ks * 16 + (lane >> 4) * 8;
                #pragma unroll
                for (int mi = 0; mi < 4; mi++)
                    ldm_x4(smem_u32(as + (row + mi * 16) * 40 + col),
                           afr[mi][0], afr[mi][1], afr[mi][2], afr[mi][3]);
            }
            uint32_t bfr[8][2];
            {
                const __half* bs = Bsm + st * B_ST;
                int row = ks * 16 + ((lane >> 3) & 1) * 8 + (lane & 7);
                #pragma unroll
                for (int p = 0; p < 4; p++) {
                    int col = wn * 64 + p * 16 + (lane >> 4) * 8;
                    uint32_t r0, r1, r2, r3;
                    ldm_x4t(smem_u32(bs + row * 264 + col), r0, r1, r2, r3);
                    bfr[2 * p][0] = r0;     bfr[2 * p][1] = r1;
                    bfr[2 * p + 1][0] = r2; bfr[2 * p + 1][1] = r3;
                }
            }
            #pragma unroll
            for (int mi = 0; mi < 4; mi++)
                #pragma unroll
                for (int nj = 0; nj < 8; nj++)
                    mma16816(acc[mi][nj], afr[mi], bfr[nj]);
        }
    }

    int row0 = bm * BM + wm * 64;
    int col0 = bn * BN + wn * 64;

    if (!FINAL) {
        // epilogue: bias + (relu) + fp16 store
        #pragma unroll
        for (int mi = 0; mi < 4; mi++) {
            #pragma unroll
            for (int h = 0; h < 2; h++) {
                int r = row0 + mi * 16 + (lane >> 2) + h * 8;
                const float* tbf = bias;
                const __half* tbh = hbias;
                if (BMODE == 2) tbf = bias + (size_t)bidx[r] * ldc;
                if (BMODE == 3) tbh = hbias + (size_t)bidx[r] * ldc;
                #pragma unroll
                for (int nj = 0; nj < 8; nj++) {
                    int c = col0 + nj * 8 + (lane & 3) * 2;
                    float b0, b1;
                    if (BMODE == 3) { b0 = __half2float(tbh[c]); b1 = __half2float(tbh[c + 1]); }
                    else            { b0 = tbf[c];               b1 = tbf[c + 1]; }
                    float f0 = acc[mi][nj][2 * h] + b0;
                    float f1 = acc[mi][nj][2 * h + 1] + b1;
                    if (RELU) { f0 = fmaxf(f0, 0.f); f1 = fmaxf(f1, 0.f); }
                    *reinterpret_cast<__half2*>(C + (size_t)r * ldc + c) = __floats2half2_rn(f0, f1);
                }
            }
        }
    } else {
        // fused final dot: per-row partial over this CTA's 256 columns
        float s[4][2];
        #pragma unroll
        for (int mi = 0; mi < 4; mi++)
            #pragma unroll
            for (int h = 0; h < 2; h++) s[mi][h] = 0.f;

        #pragma unroll
        for (int mi = 0; mi < 4; mi++) {
            #pragma unroll
            for (int h = 0; h < 2; h++) {
                int r = row0 + mi * 16 + (lane >> 2) + h * 8;
                const __half* tbh = hbias + (size_t)r * ldc;
                #pragma unroll
                for (int nj = 0; nj < 8; nj++) {
                    int c = col0 + nj * 8 + (lane & 3) * 2;
                    float b0 = __half2float(tbh[c]);
                    float b1 = __half2float(tbh[c + 1]);
                    float f0 = fmaxf(acc[mi][nj][2 * h] + b0, 0.f);
                    float f1 = fmaxf(acc[mi][nj][2 * h + 1] + b1, 0.f);
                    s[mi][h] += f0 * fw[c] + f1 * fw[c + 1];
                }
            }
        }
        // reduce over the 4 lanes sharing a row (lane&3)
        #pragma unroll
        for (int mi = 0; mi < 4; mi++)
            #pragma unroll
            for (int h = 0; h < 2; h++) {
                float v = s[mi][h];
                v += __shfl_xor_sync(~0u, v, 1);
                v += __shfl_xor_sync(~0u, v, 2);
                s[mi][h] = v;
            }
        __syncthreads();                    // cp.async drained; safe to reuse smem
        float* smf = reinterpret_cast<float*>(sm);   // [2 wm][4 wn][64 rows]
        if ((lane & 3) == 0) {
            #pragma unroll
            for (int mi = 0; mi < 4; mi++)
                #pragma unroll
                for (int h = 0; h < 2; h++)
                    smf[(wm * 4 + wn) * 64 + mi * 16 + h * 8 + (lane >> 2)] = s[mi][h];
        }
        __syncthreads();
        if (tid < 128) {
            int wmi = tid >> 6, r64 = tid & 63;
            float v = smf[(wmi * 4 + 0) * 64 + r64] + smf[(wmi * 4 + 1) * 64 + r64]
                    + smf[(wmi * 4 + 2) * 64 + r64] + smf[(wmi * 4 + 3) * 64 + r64];
            int r = bm * BM + wmi * 64 + r64;
            part[(size_t)bn * N_NODES_C + r] = v;
        }
    }
}

// --------------- scatter-mean: CSR build + gather reduce -------------------------
__global__ void zero_cnt_kernel() {
    int i = blockIdx.x * blockDim.x + threadIdx.x;
    if (i < N_NODES_C) { g_cnt[i] = 0; g_cur[i] = 0; }
}
__global__ void count_kernel(const int* __restrict__ ei) {
    int e = blockIdx.x * blockDim.x + threadIdx.x;
    if (e < N_EDGES_C) atomicAdd(&g_cnt[ei[e]], 1);
}
__global__ void scan_kernel() {
    __shared__ int ws[32];
    int t = threadIdx.x;
    int base = t * 16;
    int v[16]; int s = 0;
    #pragma unroll
    for (int i = 0; i < 16; i++) { v[i] = s; s += g_cnt[base + i]; }
    int lane = t & 31, w = t >> 5;
    int x = s;
    #pragma unroll
    for (int o = 1; o < 32; o <<= 1) { int y = __shfl_up_sync(~0u, x, o); if (lane >= o) x += y; }
    if (lane == 31) ws[w] = x;
    __syncthreads();
    if (w == 0) {
        int y = ws[lane];
        #pragma unroll
        for (int o = 1; o < 32; o <<= 1) { int z = __shfl_up_sync(~0u, y, o); if (lane >= o) y += z; }
        ws[lane] = y;
    }
    __syncthreads();
    int pre = (x - s) + (w > 0 ? ws[w - 1] : 0);
    #pragma unroll
    for (int i = 0; i < 16; i++) g_off[base + i] = pre + v[i];
    if (t == 1023) g_off[N_NODES_C] = pre + s;
}
__global__ void fill_kernel(const int* __restrict__ ei) {
    int e = blockIdx.x * blockDim.x + threadIdx.x;
    if (e < N_EDGES_C) {
        int r = ei[e];
        int p = g_off[r] + atomicAdd(&g_cur[r], 1);
        g_elist[p] = e;
    }
}
// block per node: mean over its edges of h_n (g_bufD [E,512] fp16) -> oin
__global__ void node_reduce_kernel() {
    int n = blockIdx.x;
    int t = threadIdx.x;  // 128
    int deg = g_cnt[n], start = g_off[n];
    float a0 = 0.f, a1 = 0.f, a2 = 0.f, a3 = 0.f;
    for (int i = 0; i < deg; i++) {
        int e = g_elist[start + i];
        uint2 v = *reinterpret_cast<const uint2*>(g_bufD + (size_t)e * NODE_H_C + t * 4);
        __half2 h0 = *reinterpret_cast<__half2*>(&v.x);
        __half2 h1 = *reinterpret_cast<__half2*>(&v.y);
        float2 f0 = __half22float2(h0), f1 = __half22float2(h1);
        a0 += f0.x; a1 += f0.y; a2 += f1.x; a3 += f1.y;
    }
    float inv = 1.f / (float)(deg > 0 ? deg : 1);
    __half2 o0 = __floats2half2_rn(a0 * inv, a1 * inv);
    __half2 o1 = __floats2half2_rn(a2 * inv, a3 * inv);
    uint2 ov;
    ov.x = *reinterpret_cast<uint32_t*>(&o0);
    ov.y = *reinterpret_cast<uint32_t*>(&o1);
    *reinterpret_cast<uint2*>(g_oin + (size_t)n * NODE_H_C + t * 4) = ov;
}

// --------------- sum partials + scalar bias: out[n] = p0 + p1 + b ------------------
__global__ void sum2_kernel(const float* __restrict__ b, float* __restrict__ out) {
    int n = blockIdx.x * blockDim.x + threadIdx.x;
    if (n < N_NODES_C)
        out[n] = g_part[n] + g_part[N_NODES_C + n] + b[0];
}

// ------------------------- host launcher -----------------------------------------
extern "C" void kernel_launch(void* const* d_in, const int* in_sizes, int n_in,
                              void* d_out, int out_size) {
    (void)in_sizes; (void)n_in; (void)out_size;
    const float* x      = (const float*)d_in[0];
    const float* ea     = (const float*)d_in[1];
    const float* u      = (const float*)d_in[2];
    const int*   ei     = (const int*)d_in[3];
    const int*   batch  = (const int*)d_in[4];
    const float* w_dr   = (const float*)d_in[5];
    const float* b_dr   = (const float*)d_in[6];
    const float* e_w0   = (const float*)d_in[7];
    const float* e_b0   = (const float*)d_in[8];
    const float* e_w1   = (const float*)d_in[9];
    const float* e_b1   = (const float*)d_in[10];
    const float* e_w2   = (const float*)d_in[11];
    const float* e_b2   = (const float*)d_in[12];
    const float* e_w3   = (const float*)d_in[13];
    const float* e_b3   = (const float*)d_in[14];
    const float* e_wf   = (const float*)d_in[15];
    const float* e_bf   = (const float*)d_in[16];
    const float* n1_w0  = (const float*)d_in[17];
    const float* n1_b0  = (const float*)d_in[18];
    const float* n1_w1  = (const float*)d_in[19];
    const float* n1_b1  = (const float*)d_in[20];
    const float* n2_w0  = (const float*)d_in[21];
    const float* n2_b0  = (const float*)d_in[22];
    const float* n2_w1  = (const float*)d_in[23];
    const float* n2_b1  = (const float*)d_in[24];
    float* out = (float*)d_out;

    __half *w19h, *w1h, *w2h, *w3h, *wfh, *n1w0h, *n1w1h, *n2w0h, *cw;
    __half *bufA, *bufB, *bufC, *bufD, *oin, *e19, *pn1h, *addnh;
    float  *zerov, *uef, *gpart;
    int    *gedge;
    cudaGetSymbolAddress((void**)&w19h,  g_w19h);
    cudaGetSymbolAddress((void**)&w1h,   g_w1h);
    cudaGetSymbolAddress((void**)&w2h,   g_w2h);
    cudaGetSymbolAddress((void**)&w3h,   g_w3h);
    cudaGetSymbolAddress((void**)&wfh,   g_wfh);
    cudaGetSymbolAddress((void**)&n1w0h, g_n1w0h);
    cudaGetSymbolAddress((void**)&n1w1h, g_n1w1h);
    cudaGetSymbolAddress((void**)&n2w0h, g_n2w0h);
    cudaGetSymbolAddress((void**)&cw,    g_cw);
    cudaGetSymbolAddress((void**)&bufA, g_bufA);
    cudaGetSymbolAddress((void**)&bufB, g_bufB);
    cudaGetSymbolAddress((void**)&bufC, g_bufC);
    cudaGetSymbolAddress((void**)&bufD, g_bufD);
    cudaGetSymbolAddress((void**)&oin,  g_oin);
    cudaGetSymbolAddress((void**)&e19,  g_e19);
    cudaGetSymbolAddress((void**)&pn1h, g_pn1h);
    cudaGetSymbolAddress((void**)&addnh, g_addnh);
    cudaGetSymbolAddress((void**)&zerov, g_zero);
    cudaGetSymbolAddress((void**)&uef,  g_ue);
    cudaGetSymbolAddress((void**)&gpart, g_part);
    cudaGetSymbolAddress((void**)&gedge, g_gedge);

    cudaFuncSetAttribute((const void*)gemm_kernel<true,  0, false>, cudaFuncAttributeMaxDynamicSharedMemorySize, GEMM_SMEM);
    cudaFuncSetAttribute((const void*)gemm_kernel<false, 0, false>, cudaFuncAttributeMaxDynamicSharedMemorySize, GEMM_SMEM);
    cudaFuncSetAttribute((const void*)gemm_kernel<true,  2, false>, cudaFuncAttributeMaxDynamicSharedMemorySize, GEMM_SMEM);
    cudaFuncSetAttribute((const void*)gemm_kernel<true,  3, false>, cudaFuncAttributeMaxDynamicSharedMemorySize, GEMM_SMEM);
    cudaFuncSetAttribute((const void*)gemm_kernel<true,  4, true >, cudaFuncAttributeMaxDynamicSharedMemorySize, GEMM_SMEM);

    // streams + events — SAME footprint as the R15 clean pass (2 extra streams)
    static cudaStream_t s2 = nullptr, s3 = nullptr;
    static cudaEvent_t evFork = nullptr, evUE = nullptr, evE19 = nullptr,
                       evW123 = nullptr, evJoin = nullptr, evB = nullptr;
    if (s2 == nullptr) {
        cudaStreamCreateWithFlags(&s2, cudaStreamNonBlocking);
        cudaStreamCreateWithFlags(&s3, cudaStreamNonBlocking);
        cudaEventCreateWithFlags(&evFork, cudaEventDisableTiming);
        cudaEventCreateWithFlags(&evUE,   cudaEventDisableTiming);
        cudaEventCreateWithFlags(&evE19,  cudaEventDisableTiming);
        cudaEventCreateWithFlags(&evW123, cudaEventDisableTiming);
        cudaEventCreateWithFlags(&evJoin, cudaEventDisableTiming);
        cudaEventCreateWithFlags(&evB,    cudaEventDisableTiming);
    }

    const Seg Z{0, 0, 0};
    auto gsz = [](int n) { return (n + 255) / 256; };

    // ---- fork side work off the capture origin ----
    cudaEventRecord(evFork, 0);
    cudaStreamWaitEvent(s2, evFork, 0);
    cudaStreamWaitEvent(s3, evFork, 0);

    // ---- side stream s2: ue first (l0 dependency), then packs, tables, CW, CSR ----
    dimred_kernel<<<dim3(16, 8), 256, 0, s2>>>(u, w_dr, b_dr);
    ue_kernel<<<dim3(16, 4), 256, 0, s2>>>(e_w0, e_b0);
    cudaEventRecord(evUE, s2);
    pack_weight<<<gsz(1024 * 1024), 256, 0, s2>>>(e_w1, w1h, 1024, 1024, Seg{0, 0, 1024}, Z, Z, Z);
    pack_weight<<<gsz(1024 * 1024), 256, 0, s2>>>(e_w2, w2h, 1024, 1024, Seg{0, 0, 1024}, Z, Z, Z);
    pack_weight<<<gsz(1024 * 1024), 256, 0, s2>>>(e_w3, w3h, 1024, 1024, Seg{0, 0, 1024}, Z, Z, Z);
    cudaEventRecord(evW123, s2);
    pack_weight<<<gsz(1024 * 512),  256, 0, s2>>>(e_wf, wfh, 512, 1024, Seg{0, 0, 1024}, Z, Z, Z);
    pack_weight<<<gsz(512 * 512),   256, 0, s2>>>(n1_w0, n1w0h, 512, 512, Seg{9, 0, 512}, Z, Z, Z);
    pack_weight<<<gsz(512 * 512),   256, 0, s2>>>(n1_w1, n1w1h, 512, 512, Seg{0, 0, 512}, Z, Z, Z);
    pack_weight<<<gsz(512 * 512),   256, 0, s2>>>(n2_w0, n2w0h, 512, 512, Seg{9, 0, 512}, Z, Z, Z);
    un_kernel<<<dim3(16, 2), 256, 0, s2>>>(n2_w0, n2_b0);
    addn_kernel<<<dim3(2, N_NODES_C), 256, 0, s2>>>(x, batch, n2_w0);
    bb_kernel<<<2, 256, 0, s2>>>(e_bf, n1_w0, n1_b0);
    pn1_kernel<<<dim3(2, N_NODES_C), 256, 0, s2>>>(x, n1_w0);
    gemm_kernel<false, 0, false><<<dim3(2, 8), GT, GEMM_SMEM, s2>>>(
        wfh, 512, n1w0h, 512, zerov, nullptr, nullptr, nullptr, cw, nullptr, 512, 512);
    cudaEventRecord(evJoin, s2);
    // CSR build (only node_reduce needs it; runs long before that joins)
    zero_cnt_kernel<<<N_NODES_C / 256, 256, 0, s2>>>();
    count_kernel<<<N_EDGES_C / 256, 256, 0, s2>>>(ei);
    scan_kernel<<<1, 1024, 0, s2>>>();
    fill_kernel<<<N_EDGES_C / 256, 256, 0, s2>>>(ei);
    cudaEventRecord(evB, s2);   // reused below as CSR-ready marker

    // ---- main: e19 build prologue ----
    pack_weight<<<gsz(32 * 1024), 256>>>(e_w0, w19h, 1024, 32, Seg{0, 0, 19}, Z, Z, Z);
    build_e19_kernel<<<N_EDGES_C / 8, 256>>>(x, ea, ei, batch);
    cudaEventRecord(evE19, 0);

    const int MT2 = E_HALF / BM;        // 512 M-tiles per chain
    const int MTN = N_NODES_C / BM;     // 128

    // per-chain GEMM sequence (c = 0 on stream 0, c = 1 on s3)
    auto run_chain = [&](cudaStream_t st, int c) {
        const size_t o32  = (size_t)c * E_HALF * 32;
        const size_t o1k  = (size_t)c * E_HALF * EDGE_H_C;
        const size_t o512 = (size_t)c * E_HALF * NODE_H_C;
        if (st != 0) cudaStreamWaitEvent(st, evE19, 0);
        cudaStreamWaitEvent(st, evUE, 0);
        gemm_kernel<true, 2, false><<<dim3(4, MT2), GT, GEMM_SMEM, st>>>(
            e19 + o32, 32, w19h, 1024, uef, nullptr, nullptr, gedge + c * E_HALF,
            bufA + o1k, nullptr, 1024, 32);
        cudaStreamWaitEvent(st, evW123, 0);
        gemm_kernel<true, 0, false><<<dim3(4, MT2), GT, GEMM_SMEM, st>>>(
            bufA + o1k, 1024, w1h, 1024, e_b1, nullptr, nullptr, nullptr,
            bufB + o1k, nullptr, 1024, 1024);
        gemm_kernel<true, 0, false><<<dim3(4, MT2), GT, GEMM_SMEM, st>>>(
            bufB + o1k, 1024, w2h, 1024, e_b2, nullptr, nullptr, nullptr,
            bufA + o1k, nullptr, 1024, 1024);
        gemm_kernel<true, 0, false><<<dim3(4, MT2), GT, GEMM_SMEM, st>>>(
            bufA + o1k, 1024, w3h, 1024, e_b3, nullptr, nullptr, nullptr,
            bufB + o1k, nullptr, 1024, 1024);
        cudaStreamWaitEvent(st, evJoin, 0);
        gemm_kernel<true, 3, false><<<dim3(2, MT2), GT, GEMM_SMEM, st>>>(
            bufB + o1k, 1024, cw, 512, nullptr, pn1h, nullptr, ei + N_EDGES_C + c * E_HALF,
            bufC + o512, nullptr, 512, 1024);
        gemm_kernel<true, 0, false><<<dim3(2, MT2), GT, GEMM_SMEM, st>>>(
            bufC + o512, 512, n1w1h, 512, n1_b1, nullptr, nullptr, nullptr,
            bufD + o512, nullptr, 512, 512);
    };

    static cudaEvent_t evC1 = nullptr;
    if (evC1 == nullptr) cudaEventCreateWithFlags(&evC1, cudaEventDisableTiming);

    run_chain(0, 0);
    run_chain(s3, 1);
    cudaEventRecord(evC1, s3);

    // ---- join both chains + CSR -> scatter-mean -> fused n2+final -> sum ----
    cudaStreamWaitEvent(0, evC1, 0);
    cudaStreamWaitEvent(0, evB, 0);
    node_reduce_kernel<<<N_NODES_C, 128>>>();
    gemm_kernel<true, 4, true><<<dim3(2, MTN), GT, GEMM_SMEM>>>(
        oin, 512, n2w0h, 512, nullptr, addnh, n2_w1, nullptr,
        nullptr, gpart, 512, 512);
    sum2_kernel<<<N_NODES_C / 256, 256>>>(n2_b1, out);
}